// round 2
// baseline (speedup 1.0000x reference)
#include <cuda_runtime.h>
#include <cuda_bf16.h>

// Problem constants (match reference)
#define NN 50000
#define DD 128
#define EE 800000
#define ET (EE + NN)     // edges + self loops
#define F1 256           // layer1 out features (4 heads x 64)
#define F2 32            // layer2 out features (1 head x 32)

// ---------------- scratch (device globals; no allocations) ----------------
__device__ float g_xl1[NN * F1];     // x @ W1
__device__ float g_agg1[NN * F1];    // layer1 aggregation
__device__ float g_ls1[NN * 4];
__device__ float g_ld1[NN * 4];
__device__ float g_max1[NN * 4];
__device__ float g_den1[NN * 4];
__device__ float g_w1[ET * 4];       // per-edge unnormalized softmax weights (L1)

__device__ float g_xl2[NN * F2];
__device__ float g_agg2[NN * F2];
__device__ float g_ls2[NN];
__device__ float g_ld2[NN];
__device__ float g_max2[NN];
__device__ float g_den2[NN];
__device__ float g_w2[ET];

// ---------------- helpers ----------------
__device__ __forceinline__ float lrelu(float e) { return fmaxf(e, 0.2f * e); }

__device__ __forceinline__ void atomicMaxF(float* addr, float v) {
    // ordered-int trick; never lets a negative overwrite a positive
    if (v >= 0.f) atomicMax((int*)addr, __float_as_int(v));
    else          atomicMin((unsigned int*)addr, __float_as_uint(v));
}

__device__ __forceinline__ void red_add_v4(float* p, float a, float b, float c, float d) {
    asm volatile("red.global.add.v4.f32 [%0], {%1, %2, %3, %4};"
                 :: "l"(p), "f"(a), "f"(b), "f"(c), "f"(d) : "memory");
}

__device__ __forceinline__ void fma4(float4& acc, float s, const float4& v) {
    acc.x += s * v.x; acc.y += s * v.y; acc.z += s * v.z; acc.w += s * v.w;
}

// ---------------- init: zeros + (-inf) fills ----------------
__global__ void k_init() {
    int i = blockIdx.x * blockDim.x + threadIdx.x;
    const float NEGINF = __int_as_float(0xff800000);
    if (i < NN * F1) g_agg1[i] = 0.f;
    if (i < NN * F2) g_agg2[i] = 0.f;
    if (i < NN * 4) { g_den1[i] = 0.f; g_max1[i] = NEGINF; }
    if (i < NN)     { g_den2[i] = 0.f; g_max2[i] = NEGINF; }
}

// ---------------- GEMM1: xl1 = x @ W1  (50000x128 @ 128x256) ----------------
// Block tile: 64 nodes x 256 ch, K-chunks of 32. Thread: 8 nodes x 8 channels
// (channels split as lane*4 and 128+lane*4 for conflict-free float4 smem access).
__global__ __launch_bounds__(256) void k_gemm1(const float* __restrict__ x,
                                               const float* __restrict__ W1) {
    __shared__ float xs[32 * 64];     // [k][node]
    __shared__ float ws[32 * 256];    // [k][c]
    int tid = threadIdx.x;
    int lane = tid & 31, wg = tid >> 5;
    int n0 = blockIdx.x * 64;
    int cA = lane * 4, cB = 128 + lane * 4;

    float4 accA[8], accB[8];
#pragma unroll
    for (int i = 0; i < 8; i++) { accA[i] = make_float4(0,0,0,0); accB[i] = make_float4(0,0,0,0); }

    for (int kk = 0; kk < 128; kk += 32) {
        __syncthreads();
        // load x tile transposed: 64 nodes x 32 k
#pragma unroll
        for (int j = 0; j < 2; j++) {
            int q = tid + j * 256;           // float4 index, 512 total
            int node = q >> 3, kq = q & 7;
            int gn = n0 + node;
            float4 v = make_float4(0,0,0,0);
            if (gn < NN) v = *(const float4*)(x + (size_t)gn * 128 + kk + kq * 4);
            xs[(kq*4 + 0) * 64 + node] = v.x;
            xs[(kq*4 + 1) * 64 + node] = v.y;
            xs[(kq*4 + 2) * 64 + node] = v.z;
            xs[(kq*4 + 3) * 64 + node] = v.w;
        }
        // load W1 chunk (rows kk..kk+31 contiguous)
        const float4* wsrc = (const float4*)(W1 + (size_t)kk * 256);
#pragma unroll
        for (int j = 0; j < 8; j++) {
            int q = tid + j * 256;           // 2048 float4 total
            ((float4*)ws)[q] = wsrc[q];
        }
        __syncthreads();

#pragma unroll
        for (int k = 0; k < 32; k++) {
            float4 x0 = *(float4*)&xs[k * 64 + wg * 8];
            float4 x1 = *(float4*)&xs[k * 64 + wg * 8 + 4];
            float4 wA = *(float4*)&ws[k * 256 + cA];
            float4 wB = *(float4*)&ws[k * 256 + cB];
            fma4(accA[0], x0.x, wA); fma4(accB[0], x0.x, wB);
            fma4(accA[1], x0.y, wA); fma4(accB[1], x0.y, wB);
            fma4(accA[2], x0.z, wA); fma4(accB[2], x0.z, wB);
            fma4(accA[3], x0.w, wA); fma4(accB[3], x0.w, wB);
            fma4(accA[4], x1.x, wA); fma4(accB[4], x1.x, wB);
            fma4(accA[5], x1.y, wA); fma4(accB[5], x1.y, wB);
            fma4(accA[6], x1.z, wA); fma4(accB[6], x1.z, wB);
            fma4(accA[7], x1.w, wA); fma4(accB[7], x1.w, wB);
        }
    }
#pragma unroll
    for (int i = 0; i < 8; i++) {
        int gn = n0 + wg * 8 + i;
        if (gn < NN) {
            *(float4*)(g_xl1 + (size_t)gn * 256 + cA) = accA[i];
            *(float4*)(g_xl1 + (size_t)gn * 256 + cB) = accB[i];
        }
    }
}

// ---------------- per-node attention logits, layer1 ----------------
__global__ void k_logits1(const float* __restrict__ as1, const float* __restrict__ ad1) {
    __shared__ float ss[256], sd[256];
    int tid = threadIdx.x;
    ss[tid] = as1[tid];
    sd[tid] = ad1[tid];
    __syncthreads();
    int i = blockIdx.x * 256 + tid;   // (node, head)
    if (i >= NN * 4) return;
    int n = i >> 2, h = i & 3;
    const float4* xr = (const float4*)(g_xl1 + (size_t)n * 256 + h * 64);
    const float4* av = (const float4*)(ss + h * 64);
    const float4* dv = (const float4*)(sd + h * 64);
    float s = 0.f, d = 0.f;
#pragma unroll
    for (int j = 0; j < 16; j++) {
        float4 xv = xr[j], a = av[j], b = dv[j];
        s += xv.x*a.x + xv.y*a.y + xv.z*a.z + xv.w*a.w;
        d += xv.x*b.x + xv.y*b.y + xv.z*b.z + xv.w*b.w;
    }
    g_ls1[i] = s;
    g_ld1[i] = d;
}

// ---------------- edge passes, layer1 ----------------
__global__ void k_max1(const int* __restrict__ ei) {
    int i = blockIdx.x * blockDim.x + threadIdx.x;
    if (i >= ET) return;
    int s, d;
    if (i < EE) { s = ei[i]; d = ei[EE + i]; } else { s = d = i - EE; }
    float4 a = *(const float4*)(g_ls1 + (size_t)s * 4);
    float4 b = *(const float4*)(g_ld1 + (size_t)d * 4);
    atomicMaxF(&g_max1[d*4+0], lrelu(a.x + b.x));
    atomicMaxF(&g_max1[d*4+1], lrelu(a.y + b.y));
    atomicMaxF(&g_max1[d*4+2], lrelu(a.z + b.z));
    atomicMaxF(&g_max1[d*4+3], lrelu(a.w + b.w));
}

__global__ void k_w1(const int* __restrict__ ei) {
    int i = blockIdx.x * blockDim.x + threadIdx.x;
    if (i >= ET) return;
    int s, d;
    if (i < EE) { s = ei[i]; d = ei[EE + i]; } else { s = d = i - EE; }
    float4 a = *(const float4*)(g_ls1 + (size_t)s * 4);
    float4 b = *(const float4*)(g_ld1 + (size_t)d * 4);
    float4 m = *(const float4*)(g_max1 + (size_t)d * 4);
    float4 w;
    w.x = __expf(lrelu(a.x + b.x) - m.x);
    w.y = __expf(lrelu(a.y + b.y) - m.y);
    w.z = __expf(lrelu(a.z + b.z) - m.z);
    w.w = __expf(lrelu(a.w + b.w) - m.w);
    *(float4*)(g_w1 + (size_t)i * 4) = w;
    atomicAdd(&g_den1[d*4+0], w.x);
    atomicAdd(&g_den1[d*4+1], w.y);
    atomicAdd(&g_den1[d*4+2], w.z);
    atomicAdd(&g_den1[d*4+3], w.w);
}

// one warp per edge; lane handles 8 channels (one head's 8-slice)
__global__ __launch_bounds__(256) void k_agg1(const int* __restrict__ ei) {
    int gt = blockIdx.x * 256 + threadIdx.x;
    int e = gt >> 5, lane = gt & 31;
    if (e >= ET) return;
    int s, d;
    if (e < EE) { s = __ldg(ei + e); d = __ldg(ei + EE + e); } else { s = d = e - EE; }
    float4 w  = *(const float4*)(g_w1  + (size_t)e * 4);
    float4 dn = *(const float4*)(g_den1 + (size_t)d * 4);
    int hh = lane >> 3;
    float wv = (hh == 0) ? w.x  : (hh == 1) ? w.y  : (hh == 2) ? w.z  : w.w;
    float dv = (hh == 0) ? dn.x : (hh == 1) ? dn.y : (hh == 2) ? dn.z : dn.w;
    float a = wv / dv;
    const float4* xp = (const float4*)(g_xl1 + (size_t)s * 256 + lane * 8);
    float4 v0 = xp[0], v1 = xp[1];
    float* op = g_agg1 + (size_t)d * 256 + lane * 8;
    red_add_v4(op,     v0.x * a, v0.y * a, v0.z * a, v0.w * a);
    red_add_v4(op + 4, v1.x * a, v1.y * a, v1.z * a, v1.w * a);
}

// ---------------- GEMM2 (+ fused bias1/relu on input, fused logits2) ----------------
// xl2 = relu(agg1 + b1) @ W2  (50000x256 @ 256x32); also ls2/ld2 dot products.
__global__ __launch_bounds__(256) void k_gemm2(const float* __restrict__ W2,
                                               const float* __restrict__ b1,
                                               const float* __restrict__ as2,
                                               const float* __restrict__ ad2) {
    __shared__ float hs[64 * 64];     // [node][k] chunk
    __shared__ float ws[64 * 32];     // [k][c] chunk
    __shared__ float sb1[256];
    __shared__ float sa[32], sdd[32];
    int tid = threadIdx.x;
    sb1[tid] = b1[tid];
    if (tid < 32) { sa[tid] = as2[tid]; sdd[tid] = ad2[tid]; }
    int n0 = blockIdx.x * 64;
    int c = tid & 31, nl = tid >> 5;
    float acc[8] = {0,0,0,0,0,0,0,0};

    for (int kk = 0; kk < 256; kk += 64) {
        __syncthreads();
        const float4* wsrc = (const float4*)(W2 + (size_t)kk * 32);
#pragma unroll
        for (int j = 0; j < 2; j++) ((float4*)ws)[tid + j * 256] = wsrc[tid + j * 256];
#pragma unroll
        for (int j = 0; j < 4; j++) {
            int q = tid + j * 256;            // float4 idx, 1024 total
            int flat = q * 4;
            int node = flat >> 6, kl = flat & 63;
            int gn = n0 + node;
            float4 v = make_float4(0,0,0,0);
            if (gn < NN) v = *(const float4*)(g_agg1 + (size_t)gn * 256 + kk + kl);
            float4 bb = *(const float4*)(sb1 + kk + kl);
            v.x = fmaxf(v.x + bb.x, 0.f);
            v.y = fmaxf(v.y + bb.y, 0.f);
            v.z = fmaxf(v.z + bb.z, 0.f);
            v.w = fmaxf(v.w + bb.w, 0.f);
            *(float4*)&hs[flat] = v;
        }
        __syncthreads();
#pragma unroll
        for (int k = 0; k < 64; k += 4) {
            float w0 = ws[(k+0)*32 + c];
            float w1 = ws[(k+1)*32 + c];
            float w2 = ws[(k+2)*32 + c];
            float w3 = ws[(k+3)*32 + c];
#pragma unroll
            for (int i = 0; i < 8; i++) {
                float4 h4 = *(float4*)&hs[(nl*8 + i) * 64 + k];
                acc[i] += h4.x*w0 + h4.y*w1 + h4.z*w2 + h4.w*w3;
            }
        }
    }
#pragma unroll
    for (int i = 0; i < 8; i++) {
        int gn = n0 + nl * 8 + i;
        float ps = acc[i] * sa[c];
        float pd = acc[i] * sdd[c];
#pragma unroll
        for (int o = 16; o > 0; o >>= 1) {
            ps += __shfl_xor_sync(0xffffffffu, ps, o);
            pd += __shfl_xor_sync(0xffffffffu, pd, o);
        }
        if (gn < NN) {
            g_xl2[(size_t)gn * 32 + c] = acc[i];
            if (c == 0) { g_ls2[gn] = ps; g_ld2[gn] = pd; }
        }
    }
}

// ---------------- edge passes, layer2 (1 head) ----------------
__global__ void k_max2(const int* __restrict__ ei) {
    int i = blockIdx.x * blockDim.x + threadIdx.x;
    if (i >= ET) return;
    int s, d;
    if (i < EE) { s = ei[i]; d = ei[EE + i]; } else { s = d = i - EE; }
    atomicMaxF(&g_max2[d], lrelu(g_ls2[s] + g_ld2[d]));
}

__global__ void k_w2(const int* __restrict__ ei) {
    int i = blockIdx.x * blockDim.x + threadIdx.x;
    if (i >= ET) return;
    int s, d;
    if (i < EE) { s = ei[i]; d = ei[EE + i]; } else { s = d = i - EE; }
    float w = __expf(lrelu(g_ls2[s] + g_ld2[d]) - g_max2[d]);
    g_w2[i] = w;
    atomicAdd(&g_den2[d], w);
}

// 8 threads per edge; each handles 4 channels
__global__ void k_agg2(const int* __restrict__ ei) {
    int gt = blockIdx.x * blockDim.x + threadIdx.x;
    int e = gt >> 3, j = gt & 7;
    if (e >= ET) return;
    int s, d;
    if (e < EE) { s = __ldg(ei + e); d = __ldg(ei + EE + e); } else { s = d = e - EE; }
    float a = g_w2[e] / g_den2[d];
    float4 v = *(const float4*)(g_xl2 + (size_t)s * 32 + j * 4);
    red_add_v4(g_agg2 + (size_t)d * 32 + j * 4, v.x * a, v.y * a, v.z * a, v.w * a);
}

// ---------------- final: out = relu(agg2 + b2) @ fc_W + fc_b ----------------
__global__ __launch_bounds__(128) void k_final(const float* __restrict__ fcW,
                                               const float* __restrict__ fcb,
                                               const float* __restrict__ b2,
                                               float* __restrict__ out) {
    __shared__ float fw[32 * 128];
    __shared__ float hs[32 * 32];
    __shared__ float sb2[32];
    int tid = threadIdx.x;
    int n0 = blockIdx.x * 32;
    if (tid < 32) sb2[tid] = b2[tid];
    __syncthreads();
#pragma unroll
    for (int j = 0; j < 8; j++) ((float4*)fw)[tid + j * 128] = ((const float4*)fcW)[tid + j * 128];
#pragma unroll
    for (int j = 0; j < 2; j++) {
        int q = tid + j * 128;            // float4 idx, 256 total
        int flat = q * 4;
        int node = flat >> 5, kl = flat & 31;
        int gn = n0 + node;
        float4 v = make_float4(0,0,0,0);
        if (gn < NN) v = *(const float4*)(g_agg2 + (size_t)gn * 32 + kl);
        float4 bb = *(const float4*)(sb2 + kl);
        v.x = fmaxf(v.x + bb.x, 0.f);
        v.y = fmaxf(v.y + bb.y, 0.f);
        v.z = fmaxf(v.z + bb.z, 0.f);
        v.w = fmaxf(v.w + bb.w, 0.f);
        *(float4*)&hs[flat] = v;
    }
    __syncthreads();
    float acc[32];
#pragma unroll
    for (int n = 0; n < 32; n++) acc[n] = 0.f;
#pragma unroll
    for (int k = 0; k < 32; k += 4) {
        float w0 = fw[(k+0)*128 + tid];
        float w1 = fw[(k+1)*128 + tid];
        float w2 = fw[(k+2)*128 + tid];
        float w3 = fw[(k+3)*128 + tid];
#pragma unroll
        for (int n = 0; n < 32; n++) {
            float4 h4 = *(float4*)&hs[n * 32 + k];
            acc[n] += h4.x*w0 + h4.y*w1 + h4.z*w2 + h4.w*w3;
        }
    }
    float bb = fcb[tid];
#pragma unroll
    for (int n = 0; n < 32; n++) {
        int gn = n0 + n;
        if (gn < NN) out[(size_t)gn * 128 + tid] = acc[n] + bb;
    }
}

// ---------------- launch ----------------
extern "C" void kernel_launch(void* const* d_in, const int* in_sizes, int n_in,
                              void* d_out, int out_size) {
    const float* x   = (const float*)d_in[0];
    const int*   ei  = (const int*)d_in[1];
    const float* W1  = (const float*)d_in[2];
    const float* as1 = (const float*)d_in[3];
    const float* ad1 = (const float*)d_in[4];
    const float* b1  = (const float*)d_in[5];
    const float* W2  = (const float*)d_in[6];
    const float* as2 = (const float*)d_in[7];
    const float* ad2 = (const float*)d_in[8];
    const float* b2  = (const float*)d_in[9];
    const float* fcW = (const float*)d_in[10];
    const float* fcb = (const float*)d_in[11];
    float* out = (float*)d_out;

    k_init<<<(NN * F1 + 255) / 256, 256>>>();
    k_gemm1<<<(NN + 63) / 64, 256>>>(x, W1);
    k_logits1<<<(NN * 4 + 255) / 256, 256>>>(as1, ad1);
    k_max1<<<(ET + 255) / 256, 256>>>(ei);
    k_w1<<<(ET + 255) / 256, 256>>>(ei);
    k_agg1<<<(ET * 32 + 255) / 256, 256>>>(ei);
    k_gemm2<<<(NN + 63) / 64, 256>>>(W2, b1, as2, ad2);
    k_max2<<<(ET + 255) / 256, 256>>>(ei);
    k_w2<<<(ET + 255) / 256, 256>>>(ei);
    k_agg2<<<(ET * 8 + 255) / 256, 256>>>(ei);
    k_final<<<(NN + 31) / 32, 128>>>(fcW, fcb, b2, out);
}

// round 3
// speedup vs baseline: 1.7122x; 1.7122x over previous
#include <cuda_runtime.h>
#include <cuda_bf16.h>

// Problem constants
#define NN 50000
#define DD 128
#define EE 800000
#define ET (EE + NN)     // edges + self loops
#define F1 256
#define F2 32
#define NB ((NN + 255) / 256)   // 196 scan blocks

// ---------------- scratch (device globals; no allocations) ----------------
__device__ float g_xl1[NN * F1];     // x @ W1
__device__ float g_h1[NN * F1];      // relu(agg1 + b1)
__device__ float g_ls1[NN * 4];
__device__ float g_ld1[NN * 4];
__device__ float g_w1[ET * 4];       // per-edge softmax weights (sorted order)

__device__ float g_xl2[NN * F2];
__device__ float g_h2[NN * F2];      // relu(agg2 + b2)
__device__ float g_ls2[NN];
__device__ float g_ld2[NN];

// CSR structures
__device__ int g_cnt[NN];
__device__ int g_off[NN];
__device__ int g_cur[NN];
__device__ int g_part[NN];
__device__ int g_bsum[NB];
__device__ int g_boff[NB];
__device__ int g_src[ET];            // src node per sorted edge

// ---------------- helpers ----------------
__device__ __forceinline__ float lrelu(float e) { return fmaxf(e, 0.2f * e); }

__device__ __forceinline__ unsigned long long pk2(float a, float b) {
    unsigned long long r;
    asm("mov.b64 %0, {%1, %2};" : "=l"(r) : "f"(a), "f"(b));
    return r;
}
__device__ __forceinline__ void unpk2(unsigned long long v, float& a, float& b) {
    asm("mov.b64 {%0, %1}, %2;" : "=f"(a), "=f"(b) : "l"(v));
}
__device__ __forceinline__ void fma2(unsigned long long& acc, unsigned long long a, unsigned long long b) {
    asm("fma.rn.f32x2 %0, %1, %2, %0;" : "+l"(acc) : "l"(a), "l"(b));
}

// ---------------- CSR build ----------------
__global__ void k_zero() {
    int i = blockIdx.x * blockDim.x + threadIdx.x;
    if (i < NN) g_cnt[i] = 0;
}

__global__ void k_hist(const int* __restrict__ ei) {
    int i = blockIdx.x * blockDim.x + threadIdx.x;
    if (i >= ET) return;
    int d = (i < EE) ? ei[EE + i] : (i - EE);
    atomicAdd(&g_cnt[d], 1);
}

__global__ void k_scan_blk() {
    __shared__ int wsum[8];
    int tid = threadIdx.x;
    int t = blockIdx.x * 256 + tid;
    int v = (t < NN) ? g_cnt[t] : 0;
    int lane = tid & 31, wid = tid >> 5;
    int incl = v;
#pragma unroll
    for (int o = 1; o < 32; o <<= 1) {
        int n = __shfl_up_sync(0xffffffffu, incl, o);
        if (lane >= o) incl += n;
    }
    if (lane == 31) wsum[wid] = incl;
    __syncthreads();
    if (wid == 0) {
        int s = (lane < 8) ? wsum[lane] : 0;
#pragma unroll
        for (int o = 1; o < 8; o <<= 1) {
            int n = __shfl_up_sync(0xffffffffu, s, o);
            if (lane >= o) s += n;
        }
        if (lane < 8) wsum[lane] = s;
    }
    __syncthreads();
    int base = (wid > 0) ? wsum[wid - 1] : 0;
    if (t < NN) g_part[t] = base + incl - v;
    if (tid == 255) g_bsum[blockIdx.x] = wsum[7];
}

__global__ void k_scan_top() {
    __shared__ int wsum[8];
    int tid = threadIdx.x;
    int v = (tid < NB) ? g_bsum[tid] : 0;
    int lane = tid & 31, wid = tid >> 5;
    int incl = v;
#pragma unroll
    for (int o = 1; o < 32; o <<= 1) {
        int n = __shfl_up_sync(0xffffffffu, incl, o);
        if (lane >= o) incl += n;
    }
    if (lane == 31) wsum[wid] = incl;
    __syncthreads();
    if (wid == 0) {
        int s = (lane < 8) ? wsum[lane] : 0;
#pragma unroll
        for (int o = 1; o < 8; o <<= 1) {
            int n = __shfl_up_sync(0xffffffffu, s, o);
            if (lane >= o) s += n;
        }
        if (lane < 8) wsum[lane] = s;
    }
    __syncthreads();
    int base = (wid > 0) ? wsum[wid - 1] : 0;
    if (tid < NB) g_boff[tid] = base + incl - v;
}

__global__ void k_scan_add() {
    int t = blockIdx.x * blockDim.x + threadIdx.x;
    if (t < NN) {
        int off = g_part[t] + g_boff[t >> 8];
        g_off[t] = off;
        g_cur[t] = off;
    }
}

// scatter: place edge src + softmax weight at sorted position (w = exp(lrelu(.)), no max shift)
__global__ void k_scatter(const int* __restrict__ ei) {
    int i = blockIdx.x * blockDim.x + threadIdx.x;
    if (i >= ET) return;
    int s, d;
    if (i < EE) { s = ei[i]; d = ei[EE + i]; } else { s = d = i - EE; }
    int pos = atomicAdd(&g_cur[d], 1);
    g_src[pos] = s;
    float4 a = *(const float4*)(g_ls1 + (size_t)s * 4);
    float4 b = *(const float4*)(g_ld1 + (size_t)d * 4);
    float4 w;
    w.x = __expf(lrelu(a.x + b.x));
    w.y = __expf(lrelu(a.y + b.y));
    w.z = __expf(lrelu(a.z + b.z));
    w.w = __expf(lrelu(a.w + b.w));
    *(float4*)(g_w1 + (size_t)pos * 4) = w;
}

// ---------------- GEMM1: xl1 = x @ W1  (f32x2 packed FMA) ----------------
__global__ __launch_bounds__(256) void k_gemm1(const float* __restrict__ x,
                                               const float* __restrict__ W1) {
    __shared__ float xs[32 * 64];     // [k][node]
    __shared__ float ws[32 * 256];    // [k][c]
    int tid = threadIdx.x;
    int lane = tid & 31, wg = tid >> 5;
    int n0 = blockIdx.x * 64;
    int cA = lane * 4, cB = 128 + lane * 4;

    unsigned long long accA0[8], accA1[8], accB0[8], accB1[8];
#pragma unroll
    for (int i = 0; i < 8; i++) { accA0[i] = 0ull; accA1[i] = 0ull; accB0[i] = 0ull; accB1[i] = 0ull; }

    for (int kk = 0; kk < 128; kk += 32) {
        __syncthreads();
#pragma unroll
        for (int j = 0; j < 2; j++) {
            int q = tid + j * 256;
            int node = q >> 3, kq = q & 7;
            int gn = n0 + node;
            float4 v = make_float4(0,0,0,0);
            if (gn < NN) v = *(const float4*)(x + (size_t)gn * 128 + kk + kq * 4);
            xs[(kq*4 + 0) * 64 + node] = v.x;
            xs[(kq*4 + 1) * 64 + node] = v.y;
            xs[(kq*4 + 2) * 64 + node] = v.z;
            xs[(kq*4 + 3) * 64 + node] = v.w;
        }
        const float4* wsrc = (const float4*)(W1 + (size_t)kk * 256);
#pragma unroll
        for (int j = 0; j < 8; j++) {
            int q = tid + j * 256;
            ((float4*)ws)[q] = wsrc[q];
        }
        __syncthreads();

#pragma unroll 4
        for (int k = 0; k < 32; k++) {
            float4 x0 = *(float4*)&xs[k * 64 + wg * 8];
            float4 x1 = *(float4*)&xs[k * 64 + wg * 8 + 4];
            float4 wA = *(float4*)&ws[k * 256 + cA];
            float4 wB = *(float4*)&ws[k * 256 + cB];
            unsigned long long wa0 = pk2(wA.x, wA.y), wa1 = pk2(wA.z, wA.w);
            unsigned long long wb0 = pk2(wB.x, wB.y), wb1 = pk2(wB.z, wB.w);
            float xv[8] = {x0.x, x0.y, x0.z, x0.w, x1.x, x1.y, x1.z, x1.w};
#pragma unroll
            for (int i = 0; i < 8; i++) {
                unsigned long long xx = pk2(xv[i], xv[i]);
                fma2(accA0[i], xx, wa0); fma2(accA1[i], xx, wa1);
                fma2(accB0[i], xx, wb0); fma2(accB1[i], xx, wb1);
            }
        }
    }
#pragma unroll
    for (int i = 0; i < 8; i++) {
        int gn = n0 + wg * 8 + i;
        if (gn < NN) {
            float4 rA, rB;
            unpk2(accA0[i], rA.x, rA.y); unpk2(accA1[i], rA.z, rA.w);
            unpk2(accB0[i], rB.x, rB.y); unpk2(accB1[i], rB.z, rB.w);
            *(float4*)(g_xl1 + (size_t)gn * 256 + cA) = rA;
            *(float4*)(g_xl1 + (size_t)gn * 256 + cB) = rB;
        }
    }
}

// ---------------- per-node attention logits, layer1 ----------------
__global__ void k_logits1(const float* __restrict__ as1, const float* __restrict__ ad1) {
    __shared__ float ss[256], sd[256];
    int tid = threadIdx.x;
    ss[tid] = as1[tid];
    sd[tid] = ad1[tid];
    __syncthreads();
    int i = blockIdx.x * 256 + tid;   // (node, head)
    if (i >= NN * 4) return;
    int n = i >> 2, h = i & 3;
    const float4* xr = (const float4*)(g_xl1 + (size_t)n * 256 + h * 64);
    const float4* av = (const float4*)(ss + h * 64);
    const float4* dv = (const float4*)(sd + h * 64);
    float s = 0.f, d = 0.f;
#pragma unroll
    for (int j = 0; j < 16; j++) {
        float4 xv = xr[j], a = av[j], b = dv[j];
        s += xv.x*a.x + xv.y*a.y + xv.z*a.z + xv.w*a.w;
        d += xv.x*b.x + xv.y*b.y + xv.z*b.z + xv.w*b.w;
    }
    g_ls1[i] = s;
    g_ld1[i] = d;
}

// ---------------- aggregation layer1 (CSR; warp per dst; fused bias+relu) ----
__global__ __launch_bounds__(256) void k_agg1(const float* __restrict__ b1) {
    int wid = threadIdx.x >> 5, lane = threadIdx.x & 31;
    int dst = blockIdx.x * 8 + wid;
    if (dst >= NN) return;
    int beg = g_off[dst], num = g_cnt[dst];
    int hh = lane >> 3;
    float acc0 = 0.f, acc1 = 0.f, acc2 = 0.f, acc3 = 0.f;
    float acc4 = 0.f, acc5 = 0.f, acc6 = 0.f, acc7 = 0.f;
    float den = 0.f;
    for (int j = beg; j < beg + num; j++) {
        int s = __ldg(&g_src[j]);
        float4 w4 = *(const float4*)(g_w1 + (size_t)j * 4);
        float wv = (hh == 0) ? w4.x : (hh == 1) ? w4.y : (hh == 2) ? w4.z : w4.w;
        den += wv;
        const float4* xp = (const float4*)(g_xl1 + (size_t)s * 256 + lane * 8);
        float4 v0 = __ldg(xp);
        float4 v1 = __ldg(xp + 1);
        acc0 += wv * v0.x; acc1 += wv * v0.y; acc2 += wv * v0.z; acc3 += wv * v0.w;
        acc4 += wv * v1.x; acc5 += wv * v1.y; acc6 += wv * v1.z; acc7 += wv * v1.w;
    }
    float inv = 1.f / den;
    float4 bb0 = *(const float4*)(b1 + lane * 8);
    float4 bb1 = *(const float4*)(b1 + lane * 8 + 4);
    float4 o0, o1;
    o0.x = fmaxf(acc0 * inv + bb0.x, 0.f);
    o0.y = fmaxf(acc1 * inv + bb0.y, 0.f);
    o0.z = fmaxf(acc2 * inv + bb0.z, 0.f);
    o0.w = fmaxf(acc3 * inv + bb0.w, 0.f);
    o1.x = fmaxf(acc4 * inv + bb1.x, 0.f);
    o1.y = fmaxf(acc5 * inv + bb1.y, 0.f);
    o1.z = fmaxf(acc6 * inv + bb1.z, 0.f);
    o1.w = fmaxf(acc7 * inv + bb1.w, 0.f);
    float* op = g_h1 + (size_t)dst * 256 + lane * 8;
    *(float4*)op = o0;
    *(float4*)(op + 4) = o1;
}

// ---------------- GEMM2 (+ fused logits2) ----------------
// xl2 = h1 @ W2  (50000x256 @ 256x32); h1 already bias+relu'd.
__global__ __launch_bounds__(256) void k_gemm2(const float* __restrict__ W2,
                                               const float* __restrict__ as2,
                                               const float* __restrict__ ad2) {
    __shared__ float hs[64 * 64];
    __shared__ float ws[64 * 32];
    __shared__ float sa[32], sdd[32];
    int tid = threadIdx.x;
    if (tid < 32) { sa[tid] = as2[tid]; sdd[tid] = ad2[tid]; }
    int n0 = blockIdx.x * 64;
    int c = tid & 31, nl = tid >> 5;
    float acc[8] = {0,0,0,0,0,0,0,0};

    for (int kk = 0; kk < 256; kk += 64) {
        __syncthreads();
        const float4* wsrc = (const float4*)(W2 + (size_t)kk * 32);
#pragma unroll
        for (int j = 0; j < 2; j++) ((float4*)ws)[tid + j * 256] = wsrc[tid + j * 256];
#pragma unroll
        for (int j = 0; j < 4; j++) {
            int q = tid + j * 256;
            int flat = q * 4;
            int node = flat >> 6, kl = flat & 63;
            int gn = n0 + node;
            float4 v = make_float4(0,0,0,0);
            if (gn < NN) v = *(const float4*)(g_h1 + (size_t)gn * 256 + kk + kl);
            *(float4*)&hs[flat] = v;
        }
        __syncthreads();
#pragma unroll
        for (int k = 0; k < 64; k += 4) {
            float w0 = ws[(k+0)*32 + c];
            float w1 = ws[(k+1)*32 + c];
            float w2 = ws[(k+2)*32 + c];
            float w3 = ws[(k+3)*32 + c];
#pragma unroll
            for (int i = 0; i < 8; i++) {
                float4 h4 = *(float4*)&hs[(nl*8 + i) * 64 + k];
                acc[i] += h4.x*w0 + h4.y*w1 + h4.z*w2 + h4.w*w3;
            }
        }
    }
#pragma unroll
    for (int i = 0; i < 8; i++) {
        int gn = n0 + nl * 8 + i;
        float ps = acc[i] * sa[c];
        float pd = acc[i] * sdd[c];
#pragma unroll
        for (int o = 16; o > 0; o >>= 1) {
            ps += __shfl_xor_sync(0xffffffffu, ps, o);
            pd += __shfl_xor_sync(0xffffffffu, pd, o);
        }
        if (gn < NN) {
            g_xl2[(size_t)gn * 32 + c] = acc[i];
            if (c == 0) { g_ls2[gn] = ps; g_ld2[gn] = pd; }
        }
    }
}

// ---------------- aggregation layer2 (CSR; fused softmax+bias+relu) --------
__global__ __launch_bounds__(256) void k_agg2(const float* __restrict__ b2) {
    int wid = threadIdx.x >> 5, lane = threadIdx.x & 31;
    int dst = blockIdx.x * 8 + wid;
    if (dst >= NN) return;
    int beg = g_off[dst], num = g_cnt[dst];
    float ld2d = g_ld2[dst];
    float acc = 0.f, den = 0.f;
    for (int j = beg; j < beg + num; j++) {
        int s = __ldg(&g_src[j]);
        float w = __expf(lrelu(__ldg(&g_ls2[s]) + ld2d));
        den += w;
        acc += w * __ldg(&g_xl2[(size_t)s * 32 + lane]);
    }
    float h = fmaxf(acc / den + b2[lane], 0.f);
    g_h2[(size_t)dst * 32 + lane] = h;
}

// ---------------- final: out = h2 @ fc_W + fc_b ----------------
__global__ __launch_bounds__(128) void k_final(const float* __restrict__ fcW,
                                               const float* __restrict__ fcb,
                                               float* __restrict__ out) {
    __shared__ float fw[32 * 128];
    __shared__ float hs[32 * 32];
    int tid = threadIdx.x;
    int n0 = blockIdx.x * 32;
#pragma unroll
    for (int j = 0; j < 8; j++) ((float4*)fw)[tid + j * 128] = ((const float4*)fcW)[tid + j * 128];
#pragma unroll
    for (int j = 0; j < 2; j++) {
        int q = tid + j * 128;
        int flat = q * 4;
        int node = flat >> 5, kl = flat & 31;
        int gn = n0 + node;
        float4 v = make_float4(0,0,0,0);
        if (gn < NN) v = *(const float4*)(g_h2 + (size_t)gn * 32 + kl);
        *(float4*)&hs[flat] = v;
    }
    __syncthreads();
    float acc[32];
#pragma unroll
    for (int n = 0; n < 32; n++) acc[n] = 0.f;
#pragma unroll
    for (int k = 0; k < 32; k += 4) {
        float w0 = fw[(k+0)*128 + tid];
        float w1 = fw[(k+1)*128 + tid];
        float w2 = fw[(k+2)*128 + tid];
        float w3 = fw[(k+3)*128 + tid];
#pragma unroll
        for (int n = 0; n < 32; n++) {
            float4 h4 = *(float4*)&hs[n * 32 + k];
            acc[n] += h4.x*w0 + h4.y*w1 + h4.z*w2 + h4.w*w3;
        }
    }
    float bb = fcb[tid];
#pragma unroll
    for (int n = 0; n < 32; n++) {
        int gn = n0 + n;
        if (gn < NN) out[(size_t)gn * 128 + tid] = acc[n] + bb;
    }
}

// ---------------- launch ----------------
extern "C" void kernel_launch(void* const* d_in, const int* in_sizes, int n_in,
                              void* d_out, int out_size) {
    const float* x   = (const float*)d_in[0];
    const int*   ei  = (const int*)d_in[1];
    const float* W1  = (const float*)d_in[2];
    const float* as1 = (const float*)d_in[3];
    const float* ad1 = (const float*)d_in[4];
    const float* b1  = (const float*)d_in[5];
    const float* W2  = (const float*)d_in[6];
    const float* as2 = (const float*)d_in[7];
    const float* ad2 = (const float*)d_in[8];
    const float* b2  = (const float*)d_in[9];
    const float* fcW = (const float*)d_in[10];
    const float* fcb = (const float*)d_in[11];
    float* out = (float*)d_out;

    k_zero<<<NB, 256>>>();
    k_hist<<<(ET + 255) / 256, 256>>>(ei);
    k_scan_blk<<<NB, 256>>>();
    k_scan_top<<<1, 256>>>();
    k_scan_add<<<NB, 256>>>();
    k_gemm1<<<(NN + 63) / 64, 256>>>(x, W1);
    k_logits1<<<(NN * 4 + 255) / 256, 256>>>(as1, ad1);
    k_scatter<<<(ET + 255) / 256, 256>>>(ei);
    k_agg1<<<(NN + 7) / 8, 256>>>(b1);
    k_gemm2<<<(NN + 63) / 64, 256>>>(W2, as2, ad2);
    k_agg2<<<(NN + 7) / 8, 256>>>(b2);
    k_final<<<(NN + 31) / 32, 128>>>(fcW, fcb, out);
}

// round 4
// speedup vs baseline: 1.8365x; 1.0726x over previous
#include <cuda_runtime.h>
#include <cuda_fp16.h>

// Problem constants
#define NN 50000
#define DD 128
#define EE 800000
#define ET (EE + NN)     // edges + self loops
#define F1 256
#define F2 32
#define NB ((NN + 255) / 256)   // 196 scan blocks

// ---------------- scratch (device globals; no allocations) ----------------
__device__ float  g_xl1[NN * F1];    // x @ W1 (fp32 master, for logits)
__device__ __half g_xl1h[NN * F1];   // fp16 copy for aggregation gather
__device__ __half g_h1h[NN * F1];    // relu(agg1 + b1), fp16 for gemm2
__device__ float  g_ls1[NN * 4];
__device__ float  g_ld1[NN * 4];
__device__ float  g_w1[ET * 4];      // per-edge softmax weights (sorted order)

__device__ __half g_xl2h[NN * F2];   // fp16 copy for agg2 gather
__device__ float  g_h2[NN * F2];     // relu(agg2 + b2) fp32 (feeds final)
__device__ float  g_ls2[NN];
__device__ float  g_ld2[NN];

// CSR structures
__device__ int g_cnt[NN];
__device__ int g_off[NN];
__device__ int g_cur[NN];
__device__ int g_part[NN];
__device__ int g_bsum[NB];
__device__ int g_boff[NB];
__device__ int g_src[ET];            // src node per sorted edge

// ---------------- helpers ----------------
__device__ __forceinline__ float lrelu(float e) { return fmaxf(e, 0.2f * e); }

__device__ __forceinline__ unsigned long long pk2(float a, float b) {
    unsigned long long r;
    asm("mov.b64 %0, {%1, %2};" : "=l"(r) : "f"(a), "f"(b));
    return r;
}
__device__ __forceinline__ void unpk2(unsigned long long v, float& a, float& b) {
    asm("mov.b64 {%0, %1}, %2;" : "=f"(a), "=f"(b) : "l"(v));
}
__device__ __forceinline__ void fma2(unsigned long long& acc, unsigned long long a, unsigned long long b) {
    asm("fma.rn.f32x2 %0, %1, %2, %0;" : "+l"(acc) : "l"(a), "l"(b));
}

// ---------------- CSR build ----------------
__global__ void k_zero() {
    int i = blockIdx.x * blockDim.x + threadIdx.x;
    if (i < NN) g_cnt[i] = 0;
}

__global__ void k_hist(const int* __restrict__ ei) {
    int i = blockIdx.x * blockDim.x + threadIdx.x;
    if (i >= ET) return;
    int d = (i < EE) ? ei[EE + i] : (i - EE);
    atomicAdd(&g_cnt[d], 1);
}

__global__ void k_scan_blk() {
    __shared__ int wsum[8];
    int tid = threadIdx.x;
    int t = blockIdx.x * 256 + tid;
    int v = (t < NN) ? g_cnt[t] : 0;
    int lane = tid & 31, wid = tid >> 5;
    int incl = v;
#pragma unroll
    for (int o = 1; o < 32; o <<= 1) {
        int n = __shfl_up_sync(0xffffffffu, incl, o);
        if (lane >= o) incl += n;
    }
    if (lane == 31) wsum[wid] = incl;
    __syncthreads();
    if (wid == 0) {
        int s = (lane < 8) ? wsum[lane] : 0;
#pragma unroll
        for (int o = 1; o < 8; o <<= 1) {
            int n = __shfl_up_sync(0xffffffffu, s, o);
            if (lane >= o) s += n;
        }
        if (lane < 8) wsum[lane] = s;
    }
    __syncthreads();
    int base = (wid > 0) ? wsum[wid - 1] : 0;
    if (t < NN) g_part[t] = base + incl - v;
    if (tid == 255) g_bsum[blockIdx.x] = wsum[7];
}

__global__ void k_scan_top() {
    __shared__ int wsum[8];
    int tid = threadIdx.x;
    int v = (tid < NB) ? g_bsum[tid] : 0;
    int lane = tid & 31, wid = tid >> 5;
    int incl = v;
#pragma unroll
    for (int o = 1; o < 32; o <<= 1) {
        int n = __shfl_up_sync(0xffffffffu, incl, o);
        if (lane >= o) incl += n;
    }
    if (lane == 31) wsum[wid] = incl;
    __syncthreads();
    if (wid == 0) {
        int s = (lane < 8) ? wsum[lane] : 0;
#pragma unroll
        for (int o = 1; o < 8; o <<= 1) {
            int n = __shfl_up_sync(0xffffffffu, s, o);
            if (lane >= o) s += n;
        }
        if (lane < 8) wsum[lane] = s;
    }
    __syncthreads();
    int base = (wid > 0) ? wsum[wid - 1] : 0;
    if (tid < NB) g_boff[tid] = base + incl - v;
}

__global__ void k_scan_add() {
    int t = blockIdx.x * blockDim.x + threadIdx.x;
    if (t < NN) {
        int off = g_part[t] + g_boff[t >> 8];
        g_off[t] = off;
        g_cur[t] = off;
    }
}

// scatter: place edge src + softmax weight at sorted position
__global__ void k_scatter(const int* __restrict__ ei) {
    int i = blockIdx.x * blockDim.x + threadIdx.x;
    if (i >= ET) return;
    int s, d;
    if (i < EE) { s = ei[i]; d = ei[EE + i]; } else { s = d = i - EE; }
    int pos = atomicAdd(&g_cur[d], 1);
    g_src[pos] = s;
    float4 a = *(const float4*)(g_ls1 + (size_t)s * 4);
    float4 b = *(const float4*)(g_ld1 + (size_t)d * 4);
    float4 w;
    w.x = __expf(lrelu(a.x + b.x));
    w.y = __expf(lrelu(a.y + b.y));
    w.z = __expf(lrelu(a.z + b.z));
    w.w = __expf(lrelu(a.w + b.w));
    *(float4*)(g_w1 + (size_t)pos * 4) = w;
}

// ---------------- GEMM1: xl1 = x @ W1 (f32x2), dual fp32 + fp16 store -------
__global__ __launch_bounds__(256) void k_gemm1(const float* __restrict__ x,
                                               const float* __restrict__ W1) {
    __shared__ float xs[32 * 64];     // [k][node]
    __shared__ float ws[32 * 256];    // [k][c]
    int tid = threadIdx.x;
    int lane = tid & 31, wg = tid >> 5;
    int n0 = blockIdx.x * 64;
    int cA = lane * 4, cB = 128 + lane * 4;

    unsigned long long accA0[8], accA1[8], accB0[8], accB1[8];
#pragma unroll
    for (int i = 0; i < 8; i++) { accA0[i] = 0ull; accA1[i] = 0ull; accB0[i] = 0ull; accB1[i] = 0ull; }

    for (int kk = 0; kk < 128; kk += 32) {
        __syncthreads();
#pragma unroll
        for (int j = 0; j < 2; j++) {
            int q = tid + j * 256;
            int node = q >> 3, kq = q & 7;
            int gn = n0 + node;
            float4 v = make_float4(0,0,0,0);
            if (gn < NN) v = *(const float4*)(x + (size_t)gn * 128 + kk + kq * 4);
            xs[(kq*4 + 0) * 64 + node] = v.x;
            xs[(kq*4 + 1) * 64 + node] = v.y;
            xs[(kq*4 + 2) * 64 + node] = v.z;
            xs[(kq*4 + 3) * 64 + node] = v.w;
        }
        const float4* wsrc = (const float4*)(W1 + (size_t)kk * 256);
#pragma unroll
        for (int j = 0; j < 8; j++) {
            int q = tid + j * 256;
            ((float4*)ws)[q] = wsrc[q];
        }
        __syncthreads();

#pragma unroll 4
        for (int k = 0; k < 32; k++) {
            float4 x0 = *(float4*)&xs[k * 64 + wg * 8];
            float4 x1 = *(float4*)&xs[k * 64 + wg * 8 + 4];
            float4 wA = *(float4*)&ws[k * 256 + cA];
            float4 wB = *(float4*)&ws[k * 256 + cB];
            unsigned long long wa0 = pk2(wA.x, wA.y), wa1 = pk2(wA.z, wA.w);
            unsigned long long wb0 = pk2(wB.x, wB.y), wb1 = pk2(wB.z, wB.w);
            float xv[8] = {x0.x, x0.y, x0.z, x0.w, x1.x, x1.y, x1.z, x1.w};
#pragma unroll
            for (int i = 0; i < 8; i++) {
                unsigned long long xx = pk2(xv[i], xv[i]);
                fma2(accA0[i], xx, wa0); fma2(accA1[i], xx, wa1);
                fma2(accB0[i], xx, wb0); fma2(accB1[i], xx, wb1);
            }
        }
    }
#pragma unroll
    for (int i = 0; i < 8; i++) {
        int gn = n0 + wg * 8 + i;
        if (gn < NN) {
            float4 rA, rB;
            unpk2(accA0[i], rA.x, rA.y); unpk2(accA1[i], rA.z, rA.w);
            unpk2(accB0[i], rB.x, rB.y); unpk2(accB1[i], rB.z, rB.w);
            *(float4*)(g_xl1 + (size_t)gn * 256 + cA) = rA;
            *(float4*)(g_xl1 + (size_t)gn * 256 + cB) = rB;
            __half2 hA0 = __floats2half2_rn(rA.x, rA.y);
            __half2 hA1 = __floats2half2_rn(rA.z, rA.w);
            __half2 hB0 = __floats2half2_rn(rB.x, rB.y);
            __half2 hB1 = __floats2half2_rn(rB.z, rB.w);
            *(__half2*)(g_xl1h + (size_t)gn * 256 + cA)     = hA0;
            *(__half2*)(g_xl1h + (size_t)gn * 256 + cA + 2) = hA1;
            *(__half2*)(g_xl1h + (size_t)gn * 256 + cB)     = hB0;
            *(__half2*)(g_xl1h + (size_t)gn * 256 + cB + 2) = hB1;
        }
    }
}

// ---------------- per-node attention logits, layer1 (fp32 xl1) -------------
__global__ void k_logits1(const float* __restrict__ as1, const float* __restrict__ ad1) {
    __shared__ float ss[256], sd[256];
    int tid = threadIdx.x;
    ss[tid] = as1[tid];
    sd[tid] = ad1[tid];
    __syncthreads();
    int i = blockIdx.x * 256 + tid;   // (node, head)
    if (i >= NN * 4) return;
    int n = i >> 2, h = i & 3;
    const float4* xr = (const float4*)(g_xl1 + (size_t)n * 256 + h * 64);
    const float4* av = (const float4*)(ss + h * 64);
    const float4* dv = (const float4*)(sd + h * 64);
    float s = 0.f, d = 0.f;
#pragma unroll
    for (int j = 0; j < 16; j++) {
        float4 xv = xr[j], a = av[j], b = dv[j];
        s += xv.x*a.x + xv.y*a.y + xv.z*a.z + xv.w*a.w;
        d += xv.x*b.x + xv.y*b.y + xv.z*b.z + xv.w*b.w;
    }
    g_ls1[i] = s;
    g_ld1[i] = d;
}

// ---------------- aggregation layer1 (CSR; warp/dst; fp16 gather) ----------
__global__ __launch_bounds__(256) void k_agg1(const float* __restrict__ b1) {
    int wid = threadIdx.x >> 5, lane = threadIdx.x & 31;
    int dst = blockIdx.x * 8 + wid;
    if (dst >= NN) return;
    int beg = g_off[dst], num = g_cnt[dst];
    int hh = lane >> 3;
    float2 a0 = make_float2(0,0), a1 = make_float2(0,0);
    float2 a2 = make_float2(0,0), a3 = make_float2(0,0);
    float den = 0.f;
    for (int j = beg; j < beg + num; j++) {
        int s = __ldg(&g_src[j]);
        float4 w4 = *(const float4*)(g_w1 + (size_t)j * 4);
        float wv = (hh == 0) ? w4.x : (hh == 1) ? w4.y : (hh == 2) ? w4.z : w4.w;
        den += wv;
        uint4 hv = __ldg((const uint4*)(g_xl1h + (size_t)s * 256 + lane * 8));
        float2 v0 = __half22float2(*(__half2*)&hv.x);
        float2 v1 = __half22float2(*(__half2*)&hv.y);
        float2 v2 = __half22float2(*(__half2*)&hv.z);
        float2 v3 = __half22float2(*(__half2*)&hv.w);
        a0.x += wv * v0.x; a0.y += wv * v0.y;
        a1.x += wv * v1.x; a1.y += wv * v1.y;
        a2.x += wv * v2.x; a2.y += wv * v2.y;
        a3.x += wv * v3.x; a3.y += wv * v3.y;
    }
    float inv = 1.f / den;
    float4 bb0 = *(const float4*)(b1 + lane * 8);
    float4 bb1 = *(const float4*)(b1 + lane * 8 + 4);
    float o0 = fmaxf(a0.x * inv + bb0.x, 0.f);
    float o1 = fmaxf(a0.y * inv + bb0.y, 0.f);
    float o2 = fmaxf(a1.x * inv + bb0.z, 0.f);
    float o3 = fmaxf(a1.y * inv + bb0.w, 0.f);
    float o4 = fmaxf(a2.x * inv + bb1.x, 0.f);
    float o5 = fmaxf(a2.y * inv + bb1.y, 0.f);
    float o6 = fmaxf(a3.x * inv + bb1.z, 0.f);
    float o7 = fmaxf(a3.y * inv + bb1.w, 0.f);
    uint4 st;
    *(__half2*)&st.x = __floats2half2_rn(o0, o1);
    *(__half2*)&st.y = __floats2half2_rn(o2, o3);
    *(__half2*)&st.z = __floats2half2_rn(o4, o5);
    *(__half2*)&st.w = __floats2half2_rn(o6, o7);
    *(uint4*)(g_h1h + (size_t)dst * 256 + lane * 8) = st;
}

// ---------------- GEMM2 (+ fused logits2); fp16 input ----------------------
__global__ __launch_bounds__(256) void k_gemm2(const float* __restrict__ W2,
                                               const float* __restrict__ as2,
                                               const float* __restrict__ ad2) {
    __shared__ float hs[64 * 64];
    __shared__ float ws[64 * 32];
    __shared__ float sa[32], sdd[32];
    int tid = threadIdx.x;
    if (tid < 32) { sa[tid] = as2[tid]; sdd[tid] = ad2[tid]; }
    int n0 = blockIdx.x * 64;
    int c = tid & 31, nl = tid >> 5;
    float acc[8] = {0,0,0,0,0,0,0,0};

    for (int kk = 0; kk < 256; kk += 64) {
        __syncthreads();
        const float4* wsrc = (const float4*)(W2 + (size_t)kk * 32);
#pragma unroll
        for (int j = 0; j < 2; j++) ((float4*)ws)[tid + j * 256] = wsrc[tid + j * 256];
#pragma unroll
        for (int j = 0; j < 2; j++) {
            int q = tid + j * 256;            // 512 x 8-half loads
            int flat = q * 8;
            int node = flat >> 6, kl = flat & 63;
            int gn = n0 + node;
            uint4 hv = make_uint4(0,0,0,0);
            if (gn < NN) hv = *(const uint4*)(g_h1h + (size_t)gn * 256 + kk + kl);
            float2 v0 = __half22float2(*(__half2*)&hv.x);
            float2 v1 = __half22float2(*(__half2*)&hv.y);
            float2 v2 = __half22float2(*(__half2*)&hv.z);
            float2 v3 = __half22float2(*(__half2*)&hv.w);
            float* hp = &hs[flat];
            hp[0] = v0.x; hp[1] = v0.y; hp[2] = v1.x; hp[3] = v1.y;
            hp[4] = v2.x; hp[5] = v2.y; hp[6] = v3.x; hp[7] = v3.y;
        }
        __syncthreads();
#pragma unroll
        for (int k = 0; k < 64; k += 4) {
            float w0 = ws[(k+0)*32 + c];
            float w1 = ws[(k+1)*32 + c];
            float w2 = ws[(k+2)*32 + c];
            float w3 = ws[(k+3)*32 + c];
#pragma unroll
            for (int i = 0; i < 8; i++) {
                float4 h4 = *(float4*)&hs[(nl*8 + i) * 64 + k];
                acc[i] += h4.x*w0 + h4.y*w1 + h4.z*w2 + h4.w*w3;
            }
        }
    }
#pragma unroll
    for (int i = 0; i < 8; i++) {
        int gn = n0 + nl * 8 + i;
        float ps = acc[i] * sa[c];
        float pd = acc[i] * sdd[c];
#pragma unroll
        for (int o = 16; o > 0; o >>= 1) {
            ps += __shfl_xor_sync(0xffffffffu, ps, o);
            pd += __shfl_xor_sync(0xffffffffu, pd, o);
        }
        if (gn < NN) {
            g_xl2h[(size_t)gn * 32 + c] = __float2half_rn(acc[i]);
            if (c == 0) { g_ls2[gn] = ps; g_ld2[gn] = pd; }
        }
    }
}

// ---------------- aggregation layer2 (CSR; fp16 gather) --------------------
__global__ __launch_bounds__(256) void k_agg2(const float* __restrict__ b2) {
    int wid = threadIdx.x >> 5, lane = threadIdx.x & 31;
    int dst = blockIdx.x * 8 + wid;
    if (dst >= NN) return;
    int beg = g_off[dst], num = g_cnt[dst];
    float ld2d = g_ld2[dst];
    float acc = 0.f, den = 0.f;
    for (int j = beg; j < beg + num; j++) {
        int s = __ldg(&g_src[j]);
        float w = __expf(lrelu(__ldg(&g_ls2[s]) + ld2d));
        den += w;
        acc += w * __half2float(__ldg(&g_xl2h[(size_t)s * 32 + lane]));
    }
    float h = fmaxf(acc / den + b2[lane], 0.f);
    g_h2[(size_t)dst * 32 + lane] = h;
}

// ---------------- final: out = h2 @ fc_W + fc_b ----------------
__global__ __launch_bounds__(128) void k_final(const float* __restrict__ fcW,
                                               const float* __restrict__ fcb,
                                               float* __restrict__ out) {
    __shared__ float fw[32 * 128];
    __shared__ float hs[32 * 32];
    int tid = threadIdx.x;
    int n0 = blockIdx.x * 32;
#pragma unroll
    for (int j = 0; j < 8; j++) ((float4*)fw)[tid + j * 128] = ((const float4*)fcW)[tid + j * 128];
#pragma unroll
    for (int j = 0; j < 2; j++) {
        int q = tid + j * 128;
        int flat = q * 4;
        int node = flat >> 5, kl = flat & 31;
        int gn = n0 + node;
        float4 v = make_float4(0,0,0,0);
        if (gn < NN) v = *(const float4*)(g_h2 + (size_t)gn * 32 + kl);
        *(float4*)&hs[flat] = v;
    }
    __syncthreads();
    float acc[32];
#pragma unroll
    for (int n = 0; n < 32; n++) acc[n] = 0.f;
#pragma unroll
    for (int k = 0; k < 32; k += 4) {
        float w0 = fw[(k+0)*128 + tid];
        float w1 = fw[(k+1)*128 + tid];
        float w2 = fw[(k+2)*128 + tid];
        float w3 = fw[(k+3)*128 + tid];
#pragma unroll
        for (int n = 0; n < 32; n++) {
            float4 h4 = *(float4*)&hs[n * 32 + k];
            acc[n] += h4.x*w0 + h4.y*w1 + h4.z*w2 + h4.w*w3;
        }
    }
    float bb = fcb[tid];
#pragma unroll
    for (int n = 0; n < 32; n++) {
        int gn = n0 + n;
        if (gn < NN) out[(size_t)gn * 128 + tid] = acc[n] + bb;
    }
}

// ---------------- launch ----------------
extern "C" void kernel_launch(void* const* d_in, const int* in_sizes, int n_in,
                              void* d_out, int out_size) {
    const float* x   = (const float*)d_in[0];
    const int*   ei  = (const int*)d_in[1];
    const float* W1  = (const float*)d_in[2];
    const float* as1 = (const float*)d_in[3];
    const float* ad1 = (const float*)d_in[4];
    const float* b1  = (const float*)d_in[5];
    const float* W2  = (const float*)d_in[6];
    const float* as2 = (const float*)d_in[7];
    const float* ad2 = (const float*)d_in[8];
    const float* b2  = (const float*)d_in[9];
    const float* fcW = (const float*)d_in[10];
    const float* fcb = (const float*)d_in[11];
    float* out = (float*)d_out;

    k_zero<<<NB, 256>>>();
    k_hist<<<(ET + 255) / 256, 256>>>(ei);
    k_scan_blk<<<NB, 256>>>();
    k_scan_top<<<1, 256>>>();
    k_scan_add<<<NB, 256>>>();
    k_gemm1<<<(NN + 63) / 64, 256>>>(x, W1);
    k_logits1<<<(NN * 4 + 255) / 256, 256>>>(as1, ad1);
    k_scatter<<<(ET + 255) / 256, 256>>>(ei);
    k_agg1<<<(NN + 7) / 8, 256>>>(b1);
    k_gemm2<<<(NN + 63) / 64, 256>>>(W2, as2, ad2);
    k_agg2<<<(NN + 7) / 8, 256>>>(b2);
    k_final<<<(NN + 31) / 32, 128>>>(fcW, fcb, out);
}

// round 5
// speedup vs baseline: 2.2803x; 1.2416x over previous
#include <cuda_runtime.h>
#include <cuda_fp16.h>

// Problem constants
#define NN 50000
#define DD 128
#define EE 800000
#define ET (EE + NN)     // edges + self loops
#define F1 256
#define F2 32
#define NB ((NN + 255) / 256)   // 196 scan blocks

// ---------------- scratch (device globals; no allocations) ----------------
__device__ __half g_xl1h[NN * F1];   // fp16 xl1 for aggregation gather
__device__ __half g_h1h[NN * F1];    // relu(agg1 + b1), fp16 for gemm2
__device__ float  g_ls1[NN * 4];
__device__ float  g_ld1[NN * 4];
__device__ float  g_w1[ET * 4];      // per-edge softmax weights (sorted order)

__device__ __half g_xl2h[NN * F2];   // fp16 copy for agg2 gather
__device__ float  g_h2[NN * F2];     // relu(agg2 + b2) fp32 (feeds final)
__device__ float  g_ls2[NN];
__device__ float  g_ld2[NN];

// CSR structures
__device__ int g_cnt[NN];
__device__ int g_off[NN];
__device__ int g_cur[NN];
__device__ int g_part[NN];
__device__ int g_bsum[NB];
__device__ int g_boff[NB];
__device__ int g_src[ET];            // src node per sorted edge

// ---------------- helpers ----------------
__device__ __forceinline__ float lrelu(float e) { return fmaxf(e, 0.2f * e); }

__device__ __forceinline__ unsigned f2tf32(float f) {
    unsigned u;
    asm("cvt.rna.tf32.f32 %0, %1;" : "=r"(u) : "f"(f));
    return u;
}
__device__ __forceinline__ void mma_tf32(float& c0, float& c1, float& c2, float& c3,
                                         unsigned a0, unsigned a1, unsigned a2, unsigned a3,
                                         unsigned b0, unsigned b1) {
    asm volatile("mma.sync.aligned.m16n8k8.row.col.f32.tf32.tf32.f32 "
                 "{%0,%1,%2,%3}, {%4,%5,%6,%7}, {%8,%9}, {%0,%1,%2,%3};"
                 : "+f"(c0), "+f"(c1), "+f"(c2), "+f"(c3)
                 : "r"(a0), "r"(a1), "r"(a2), "r"(a3), "r"(b0), "r"(b1));
}

// ---------------- CSR build ----------------
__global__ void k_zero() {
    int i = blockIdx.x * blockDim.x + threadIdx.x;
    if (i < NN) g_cnt[i] = 0;
}

__global__ void k_hist(const int* __restrict__ ei) {
    int i = blockIdx.x * blockDim.x + threadIdx.x;
    if (i >= ET) return;
    int d = (i < EE) ? ei[EE + i] : (i - EE);
    atomicAdd(&g_cnt[d], 1);
}

__global__ void k_scan_blk() {
    __shared__ int wsum[8];
    int tid = threadIdx.x;
    int t = blockIdx.x * 256 + tid;
    int v = (t < NN) ? g_cnt[t] : 0;
    int lane = tid & 31, wid = tid >> 5;
    int incl = v;
#pragma unroll
    for (int o = 1; o < 32; o <<= 1) {
        int n = __shfl_up_sync(0xffffffffu, incl, o);
        if (lane >= o) incl += n;
    }
    if (lane == 31) wsum[wid] = incl;
    __syncthreads();
    if (wid == 0) {
        int s = (lane < 8) ? wsum[lane] : 0;
#pragma unroll
        for (int o = 1; o < 8; o <<= 1) {
            int n = __shfl_up_sync(0xffffffffu, s, o);
            if (lane >= o) s += n;
        }
        if (lane < 8) wsum[lane] = s;
    }
    __syncthreads();
    int base = (wid > 0) ? wsum[wid - 1] : 0;
    if (t < NN) g_part[t] = base + incl - v;
    if (tid == 255) g_bsum[blockIdx.x] = wsum[7];
}

__global__ void k_scan_top() {
    __shared__ int wsum[8];
    int tid = threadIdx.x;
    int v = (tid < NB) ? g_bsum[tid] : 0;
    int lane = tid & 31, wid = tid >> 5;
    int incl = v;
#pragma unroll
    for (int o = 1; o < 32; o <<= 1) {
        int n = __shfl_up_sync(0xffffffffu, incl, o);
        if (lane >= o) incl += n;
    }
    if (lane == 31) wsum[wid] = incl;
    __syncthreads();
    if (wid == 0) {
        int s = (lane < 8) ? wsum[lane] : 0;
#pragma unroll
        for (int o = 1; o < 8; o <<= 1) {
            int n = __shfl_up_sync(0xffffffffu, s, o);
            if (lane >= o) s += n;
        }
        if (lane < 8) wsum[lane] = s;
    }
    __syncthreads();
    int base = (wid > 0) ? wsum[wid - 1] : 0;
    if (tid < NB) g_boff[tid] = base + incl - v;
}

__global__ void k_scan_add() {
    int t = blockIdx.x * blockDim.x + threadIdx.x;
    if (t < NN) {
        int off = g_part[t] + g_boff[t >> 8];
        g_off[t] = off;
        g_cur[t] = off;
    }
}

// scatter: place edge src + softmax weight at sorted position
__global__ void k_scatter(const int* __restrict__ ei) {
    int i = blockIdx.x * blockDim.x + threadIdx.x;
    if (i >= ET) return;
    int s, d;
    if (i < EE) { s = ei[i]; d = ei[EE + i]; } else { s = d = i - EE; }
    int pos = atomicAdd(&g_cur[d], 1);
    g_src[pos] = s;
    float4 a = *(const float4*)(g_ls1 + (size_t)s * 4);
    float4 b = *(const float4*)(g_ld1 + (size_t)d * 4);
    float4 w;
    w.x = __expf(lrelu(a.x + b.x));
    w.y = __expf(lrelu(a.y + b.y));
    w.z = __expf(lrelu(a.z + b.z));
    w.w = __expf(lrelu(a.w + b.w));
    *(float4*)(g_w1 + (size_t)pos * 4) = w;
}

// ---------------- GEMM1 (tf32 tensor-core) + fused logits1 ------------------
// grid: (782, 4). Block tile: 64 nodes x 64 cols (= head blockIdx.y), K=128
// in two 64-chunks. 128 threads = 4 warps; warp w -> rows [w*16, w*16+16).
// Epilogue: stage C tile as fp16 in smem, write g_xl1h coalesced, and compute
// this head's ls1/ld1 logits exactly (block covers the full 64-ch head).
__global__ __launch_bounds__(128) void k_gemm1(const float* __restrict__ x,
                                               const float* __restrict__ W1,
                                               const float* __restrict__ as1,
                                               const float* __restrict__ ad1) {
    __shared__ unsigned As[64 * 68];   // [m][k], tf32 bits, pad 68
    __shared__ unsigned Bs[64 * 68];   // [k][n], tf32 bits, pad 68
    __shared__ __half   Cs[64 * 72];   // [m][n] fp16 staging, pad 72
    __shared__ float    sA[64], sD[64];

    int tid = threadIdx.x;
    int lane = tid & 31, w = tid >> 5;
    int n0 = blockIdx.x * 64;          // node base
    int hb = blockIdx.y;               // head index / col base = hb*64
    if (tid < 64) {
        sA[tid] = as1[hb * 64 + tid];
        sD[tid] = ad1[hb * 64 + tid];
    }

    float c[8][4];
#pragma unroll
    for (int j = 0; j < 8; j++)
#pragma unroll
        for (int q = 0; q < 4; q++) c[j][q] = 0.f;

    int m0 = w * 16;
    int r4 = lane >> 2, c4 = lane & 3;

    for (int kk = 0; kk < 128; kk += 64) {
        __syncthreads();
        // load A: x[n0..n0+63][kk..kk+63] -> As[m][k]
#pragma unroll
        for (int i = 0; i < 8; i++) {
            int q = tid + i * 128;             // 1024 float4
            int row = q >> 4, cq = (q & 15) * 4;
            int gn = n0 + row;
            float4 v = make_float4(0,0,0,0);
            if (gn < NN) v = *(const float4*)(x + (size_t)gn * 128 + kk + cq);
            unsigned* ap = &As[row * 68 + cq];
            ap[0] = f2tf32(v.x); ap[1] = f2tf32(v.y);
            ap[2] = f2tf32(v.z); ap[3] = f2tf32(v.w);
        }
        // load B: W1[kk..kk+63][hb*64..+63] -> Bs[k][n]
#pragma unroll
        for (int i = 0; i < 8; i++) {
            int q = tid + i * 128;
            int row = q >> 4, cq = (q & 15) * 4;
            float4 v = *(const float4*)(W1 + (size_t)(kk + row) * 256 + hb * 64 + cq);
            unsigned* bp = &Bs[row * 68 + cq];
            bp[0] = f2tf32(v.x); bp[1] = f2tf32(v.y);
            bp[2] = f2tf32(v.z); bp[3] = f2tf32(v.w);
        }
        __syncthreads();

#pragma unroll
        for (int ks = 0; ks < 8; ks++) {
            int k0 = ks * 8;
            unsigned a0 = As[(m0 + r4) * 68 + k0 + c4];
            unsigned a1 = As[(m0 + r4 + 8) * 68 + k0 + c4];
            unsigned a2 = As[(m0 + r4) * 68 + k0 + c4 + 4];
            unsigned a3 = As[(m0 + r4 + 8) * 68 + k0 + c4 + 4];
#pragma unroll
            for (int j = 0; j < 8; j++) {
                unsigned b0 = Bs[(k0 + c4) * 68 + j * 8 + r4];
                unsigned b1 = Bs[(k0 + c4 + 4) * 68 + j * 8 + r4];
                mma_tf32(c[j][0], c[j][1], c[j][2], c[j][3], a0, a1, a2, a3, b0, b1);
            }
        }
    }

    // stage C as fp16 in smem
    __syncthreads();
#pragma unroll
    for (int j = 0; j < 8; j++) {
        int col = j * 8 + 2 * c4;
        *(__half2*)&Cs[(m0 + r4) * 72 + col]     = __floats2half2_rn(c[j][0], c[j][1]);
        *(__half2*)&Cs[(m0 + r4 + 8) * 72 + col] = __floats2half2_rn(c[j][2], c[j][3]);
    }
    __syncthreads();

    // coalesced write of fp16 tile
#pragma unroll
    for (int i = 0; i < 4; i++) {
        int q = tid + i * 128;          // 512 uint4 (8 halves each)
        int row = q >> 3, cq = (q & 7) * 8;
        int gn = n0 + row;
        if (gn < NN)
            *(uint4*)(g_xl1h + (size_t)gn * 256 + hb * 64 + cq) =
                *(uint4*)&Cs[row * 72 + cq];
    }

    // fused logits: thread pair per row (t even: cols 0..31, t odd: 32..63)
    {
        int row = tid >> 1;
        int cbase = (tid & 1) * 32;
        float s = 0.f, d = 0.f;
#pragma unroll
        for (int cc = 0; cc < 32; cc++) {
            float v = __half2float(Cs[row * 72 + cbase + cc]);
            s += v * sA[cbase + cc];
            d += v * sD[cbase + cc];
        }
        s += __shfl_xor_sync(0xffffffffu, s, 1);
        d += __shfl_xor_sync(0xffffffffu, d, 1);
        int gn = n0 + row;
        if ((tid & 1) == 0 && gn < NN) {
            g_ls1[gn * 4 + hb] = s;
            g_ld1[gn * 4 + hb] = d;
        }
    }
}

// ---------------- aggregation layer1 (CSR; warp/dst; fp16 gather) ----------
__global__ __launch_bounds__(256) void k_agg1(const float* __restrict__ b1) {
    int wid = threadIdx.x >> 5, lane = threadIdx.x & 31;
    int dst = blockIdx.x * 8 + wid;
    if (dst >= NN) return;
    int beg = g_off[dst], num = g_cnt[dst];
    int hh = lane >> 3;
    float2 a0 = make_float2(0,0), a1 = make_float2(0,0);
    float2 a2 = make_float2(0,0), a3 = make_float2(0,0);
    float den = 0.f;
    for (int j = beg; j < beg + num; j++) {
        int s = __ldg(&g_src[j]);
        float4 w4 = *(const float4*)(g_w1 + (size_t)j * 4);
        float wv = (hh == 0) ? w4.x : (hh == 1) ? w4.y : (hh == 2) ? w4.z : w4.w;
        den += wv;
        uint4 hv = __ldg((const uint4*)(g_xl1h + (size_t)s * 256 + lane * 8));
        float2 v0 = __half22float2(*(__half2*)&hv.x);
        float2 v1 = __half22float2(*(__half2*)&hv.y);
        float2 v2 = __half22float2(*(__half2*)&hv.z);
        float2 v3 = __half22float2(*(__half2*)&hv.w);
        a0.x += wv * v0.x; a0.y += wv * v0.y;
        a1.x += wv * v1.x; a1.y += wv * v1.y;
        a2.x += wv * v2.x; a2.y += wv * v2.y;
        a3.x += wv * v3.x; a3.y += wv * v3.y;
    }
    float inv = 1.f / den;
    float4 bb0 = *(const float4*)(b1 + lane * 8);
    float4 bb1 = *(const float4*)(b1 + lane * 8 + 4);
    float o0 = fmaxf(a0.x * inv + bb0.x, 0.f);
    float o1 = fmaxf(a0.y * inv + bb0.y, 0.f);
    float o2 = fmaxf(a1.x * inv + bb0.z, 0.f);
    float o3 = fmaxf(a1.y * inv + bb0.w, 0.f);
    float o4 = fmaxf(a2.x * inv + bb1.x, 0.f);
    float o5 = fmaxf(a2.y * inv + bb1.y, 0.f);
    float o6 = fmaxf(a3.x * inv + bb1.z, 0.f);
    float o7 = fmaxf(a3.y * inv + bb1.w, 0.f);
    uint4 st;
    *(__half2*)&st.x = __floats2half2_rn(o0, o1);
    *(__half2*)&st.y = __floats2half2_rn(o2, o3);
    *(__half2*)&st.z = __floats2half2_rn(o4, o5);
    *(__half2*)&st.w = __floats2half2_rn(o6, o7);
    *(uint4*)(g_h1h + (size_t)dst * 256 + lane * 8) = st;
}

// ---------------- GEMM2 (+ fused logits2); fp16 input ----------------------
__global__ __launch_bounds__(256) void k_gemm2(const float* __restrict__ W2,
                                               const float* __restrict__ as2,
                                               const float* __restrict__ ad2) {
    __shared__ float hs[64 * 64];
    __shared__ float ws[64 * 32];
    __shared__ float sa[32], sdd[32];
    int tid = threadIdx.x;
    if (tid < 32) { sa[tid] = as2[tid]; sdd[tid] = ad2[tid]; }
    int n0 = blockIdx.x * 64;
    int c = tid & 31, nl = tid >> 5;
    float acc[8] = {0,0,0,0,0,0,0,0};

    for (int kk = 0; kk < 256; kk += 64) {
        __syncthreads();
        const float4* wsrc = (const float4*)(W2 + (size_t)kk * 32);
#pragma unroll
        for (int j = 0; j < 2; j++) ((float4*)ws)[tid + j * 256] = wsrc[tid + j * 256];
#pragma unroll
        for (int j = 0; j < 2; j++) {
            int q = tid + j * 256;
            int flat = q * 8;
            int node = flat >> 6, kl = flat & 63;
            int gn = n0 + node;
            uint4 hv = make_uint4(0,0,0,0);
            if (gn < NN) hv = *(const uint4*)(g_h1h + (size_t)gn * 256 + kk + kl);
            float2 v0 = __half22float2(*(__half2*)&hv.x);
            float2 v1 = __half22float2(*(__half2*)&hv.y);
            float2 v2 = __half22float2(*(__half2*)&hv.z);
            float2 v3 = __half22float2(*(__half2*)&hv.w);
            float* hp = &hs[flat];
            hp[0] = v0.x; hp[1] = v0.y; hp[2] = v1.x; hp[3] = v1.y;
            hp[4] = v2.x; hp[5] = v2.y; hp[6] = v3.x; hp[7] = v3.y;
        }
        __syncthreads();
#pragma unroll
        for (int k = 0; k < 64; k += 4) {
            float w0 = ws[(k+0)*32 + c];
            float w1 = ws[(k+1)*32 + c];
            float w2 = ws[(k+2)*32 + c];
            float w3 = ws[(k+3)*32 + c];
#pragma unroll
            for (int i = 0; i < 8; i++) {
                float4 h4 = *(float4*)&hs[(nl*8 + i) * 64 + k];
                acc[i] += h4.x*w0 + h4.y*w1 + h4.z*w2 + h4.w*w3;
            }
        }
    }
#pragma unroll
    for (int i = 0; i < 8; i++) {
        int gn = n0 + nl * 8 + i;
        float ps = acc[i] * sa[c];
        float pd = acc[i] * sdd[c];
#pragma unroll
        for (int o = 16; o > 0; o >>= 1) {
            ps += __shfl_xor_sync(0xffffffffu, ps, o);
            pd += __shfl_xor_sync(0xffffffffu, pd, o);
        }
        if (gn < NN) {
            g_xl2h[(size_t)gn * 32 + c] = __float2half_rn(acc[i]);
            if (c == 0) { g_ls2[gn] = ps; g_ld2[gn] = pd; }
        }
    }
}

// ---------------- aggregation layer2 (CSR; fp16 gather) --------------------
__global__ __launch_bounds__(256) void k_agg2(const float* __restrict__ b2) {
    int wid = threadIdx.x >> 5, lane = threadIdx.x & 31;
    int dst = blockIdx.x * 8 + wid;
    if (dst >= NN) return;
    int beg = g_off[dst], num = g_cnt[dst];
    float ld2d = g_ld2[dst];
    float acc = 0.f, den = 0.f;
    for (int j = beg; j < beg + num; j++) {
        int s = __ldg(&g_src[j]);
        float w = __expf(lrelu(__ldg(&g_ls2[s]) + ld2d));
        den += w;
        acc += w * __half2float(__ldg(&g_xl2h[(size_t)s * 32 + lane]));
    }
    float h = fmaxf(acc / den + b2[lane], 0.f);
    g_h2[(size_t)dst * 32 + lane] = h;
}

// ---------------- final: out = h2 @ fc_W + fc_b ----------------
__global__ __launch_bounds__(128) void k_final(const float* __restrict__ fcW,
                                               const float* __restrict__ fcb,
                                               float* __restrict__ out) {
    __shared__ float fw[32 * 128];
    __shared__ float hs[32 * 32];
    int tid = threadIdx.x;
    int n0 = blockIdx.x * 32;
#pragma unroll
    for (int j = 0; j < 8; j++) ((float4*)fw)[tid + j * 128] = ((const float4*)fcW)[tid + j * 128];
#pragma unroll
    for (int j = 0; j < 2; j++) {
        int q = tid + j * 128;
        int flat = q * 4;
        int node = flat >> 5, kl = flat & 31;
        int gn = n0 + node;
        float4 v = make_float4(0,0,0,0);
        if (gn < NN) v = *(const float4*)(g_h2 + (size_t)gn * 32 + kl);
        *(float4*)&hs[flat] = v;
    }
    __syncthreads();
    float acc[32];
#pragma unroll
    for (int n = 0; n < 32; n++) acc[n] = 0.f;
#pragma unroll
    for (int k = 0; k < 32; k += 4) {
        float w0 = fw[(k+0)*128 + tid];
        float w1 = fw[(k+1)*128 + tid];
        float w2 = fw[(k+2)*128 + tid];
        float w3 = fw[(k+3)*128 + tid];
#pragma unroll
        for (int n = 0; n < 32; n++) {
            float4 h4 = *(float4*)&hs[n * 32 + k];
            acc[n] += h4.x*w0 + h4.y*w1 + h4.z*w2 + h4.w*w3;
        }
    }
    float bb = fcb[tid];
#pragma unroll
    for (int n = 0; n < 32; n++) {
        int gn = n0 + n;
        if (gn < NN) out[(size_t)gn * 128 + tid] = acc[n] + bb;
    }
}

// ---------------- launch ----------------
extern "C" void kernel_launch(void* const* d_in, const int* in_sizes, int n_in,
                              void* d_out, int out_size) {
    const float* x   = (const float*)d_in[0];
    const int*   ei  = (const int*)d_in[1];
    const float* W1  = (const float*)d_in[2];
    const float* as1 = (const float*)d_in[3];
    const float* ad1 = (const float*)d_in[4];
    const float* b1  = (const float*)d_in[5];
    const float* W2  = (const float*)d_in[6];
    const float* as2 = (const float*)d_in[7];
    const float* ad2 = (const float*)d_in[8];
    const float* b2  = (const float*)d_in[9];
    const float* fcW = (const float*)d_in[10];
    const float* fcb = (const float*)d_in[11];
    float* out = (float*)d_out;

    k_zero<<<NB, 256>>>();
    k_hist<<<(ET + 255) / 256, 256>>>(ei);
    k_scan_blk<<<NB, 256>>>();
    k_scan_top<<<1, 256>>>();
    k_scan_add<<<NB, 256>>>();
    dim3 g1((NN + 63) / 64, 4);
    k_gemm1<<<g1, 128>>>(x, W1, as1, ad1);
    k_scatter<<<(ET + 255) / 256, 256>>>(ei);
    k_agg1<<<(NN + 7) / 8, 256>>>(b1);
    k_gemm2<<<(NN + 63) / 64, 256>>>(W2, as2, ad2);
    k_agg2<<<(NN + 7) / 8, 256>>>(b2);
    k_final<<<(NN + 31) / 32, 128>>>(fcW, fcb, out);
}

// round 6
// speedup vs baseline: 2.5160x; 1.1034x over previous
#include <cuda_runtime.h>
#include <cuda_fp16.h>

// Problem constants
#define NN 50000
#define DD 128
#define EE 800000
#define ET (EE + NN)     // edges + self loops
#define F1 256
#define F2 32
#define NB ((NN + 255) / 256)   // 196 scan blocks

// ---------------- scratch (device globals; no allocations) ----------------
__device__ __half g_xl1h[NN * F1];   // fp16 xl1 for aggregation gather
__device__ __half g_h1h[NN * F1];    // relu(agg1 + b1), fp16 for gemm2
__device__ float  g_ls1[NN * 4];
__device__ float  g_ld1[NN * 4];

__device__ __half g_xl2h[NN * F2];   // fp16 copy for agg2 gather
__device__ float  g_h2[NN * F2];     // relu(agg2 + b2) fp32 (feeds final)
__device__ float  g_ls2[NN];
__device__ float  g_ld2[NN];

// CSR structures (g_cnt self-restores to 0 every call: zeroed in k_scan_blk)
__device__ int g_cnt[NN];
__device__ int g_off[NN + 1];
__device__ int g_cur[NN];
__device__ int g_part[NN];
__device__ int g_bsum[NB];
__device__ int g_boff[NB];
__device__ int g_src[ET];            // src node per sorted edge

// ---------------- helpers ----------------
__device__ __forceinline__ float lrelu(float e) { return fmaxf(e, 0.2f * e); }

__device__ __forceinline__ unsigned f2tf32(float f) {
    unsigned u;
    asm("cvt.rna.tf32.f32 %0, %1;" : "=r"(u) : "f"(f));
    return u;
}
__device__ __forceinline__ void mma_tf32(float& c0, float& c1, float& c2, float& c3,
                                         unsigned a0, unsigned a1, unsigned a2, unsigned a3,
                                         unsigned b0, unsigned b1) {
    asm volatile("mma.sync.aligned.m16n8k8.row.col.f32.tf32.tf32.f32 "
                 "{%0,%1,%2,%3}, {%4,%5,%6,%7}, {%8,%9}, {%0,%1,%2,%3};"
                 : "+f"(c0), "+f"(c1), "+f"(c2), "+f"(c3)
                 : "r"(a0), "r"(a1), "r"(a2), "r"(a3), "r"(b0), "r"(b1));
}

// ---------------- CSR build ----------------
__global__ void k_hist(const int* __restrict__ ei) {
    int i = blockIdx.x * blockDim.x + threadIdx.x;
    if (i >= ET) return;
    int d = (i < EE) ? ei[EE + i] : (i - EE);
    atomicAdd(&g_cnt[d], 1);
}

__global__ void k_scan_blk() {
    __shared__ int wsum[8];
    int tid = threadIdx.x;
    int t = blockIdx.x * 256 + tid;
    int v = 0;
    if (t < NN) { v = g_cnt[t]; g_cnt[t] = 0; }   // read + self-restore
    int lane = tid & 31, wid = tid >> 5;
    int incl = v;
#pragma unroll
    for (int o = 1; o < 32; o <<= 1) {
        int n = __shfl_up_sync(0xffffffffu, incl, o);
        if (lane >= o) incl += n;
    }
    if (lane == 31) wsum[wid] = incl;
    __syncthreads();
    if (wid == 0) {
        int s = (lane < 8) ? wsum[lane] : 0;
#pragma unroll
        for (int o = 1; o < 8; o <<= 1) {
            int n = __shfl_up_sync(0xffffffffu, s, o);
            if (lane >= o) s += n;
        }
        if (lane < 8) wsum[lane] = s;
    }
    __syncthreads();
    int base = (wid > 0) ? wsum[wid - 1] : 0;
    if (t < NN) g_part[t] = base + incl - v;
    if (tid == 255) g_bsum[blockIdx.x] = wsum[7];
}

__global__ void k_scan_top() {
    __shared__ int wsum[8];
    int tid = threadIdx.x;
    int v = (tid < NB) ? g_bsum[tid] : 0;
    int lane = tid & 31, wid = tid >> 5;
    int incl = v;
#pragma unroll
    for (int o = 1; o < 32; o <<= 1) {
        int n = __shfl_up_sync(0xffffffffu, incl, o);
        if (lane >= o) incl += n;
    }
    if (lane == 31) wsum[wid] = incl;
    __syncthreads();
    if (wid == 0) {
        int s = (lane < 8) ? wsum[lane] : 0;
#pragma unroll
        for (int o = 1; o < 8; o <<= 1) {
            int n = __shfl_up_sync(0xffffffffu, s, o);
            if (lane >= o) s += n;
        }
        if (lane < 8) wsum[lane] = s;
    }
    __syncthreads();
    int base = (wid > 0) ? wsum[wid - 1] : 0;
    if (tid < NB) g_boff[tid] = base + incl - v;
}

__global__ void k_scan_add() {
    int t = blockIdx.x * blockDim.x + threadIdx.x;
    if (t < NN) {
        int off = g_part[t] + g_boff[t >> 8];
        g_off[t] = off;
        g_cur[t] = off;
    }
    if (t == 0) g_off[NN] = ET;
}

// scatter: place edge src at sorted position (weights recomputed in agg1)
__global__ void k_scatter(const int* __restrict__ ei) {
    int i = blockIdx.x * blockDim.x + threadIdx.x;
    if (i >= ET) return;
    int s, d;
    if (i < EE) { s = ei[i]; d = ei[EE + i]; } else { s = d = i - EE; }
    int pos = atomicAdd(&g_cur[d], 1);
    g_src[pos] = s;
}

// ---------------- GEMM1 (tf32 tensor-core) + fused logits1 ------------------
__global__ __launch_bounds__(128) void k_gemm1(const float* __restrict__ x,
                                               const float* __restrict__ W1,
                                               const float* __restrict__ as1,
                                               const float* __restrict__ ad1) {
    __shared__ unsigned As[64 * 68];   // [m][k], tf32 bits, pad 68
    __shared__ unsigned Bs[64 * 68];   // [k][n], tf32 bits, pad 68
    __shared__ __half   Cs[64 * 72];   // [m][n] fp16 staging, pad 72
    __shared__ float    sA[64], sD[64];

    int tid = threadIdx.x;
    int lane = tid & 31, w = tid >> 5;
    int n0 = blockIdx.x * 64;          // node base
    int hb = blockIdx.y;               // head index / col base = hb*64
    if (tid < 64) {
        sA[tid] = as1[hb * 64 + tid];
        sD[tid] = ad1[hb * 64 + tid];
    }

    float c[8][4];
#pragma unroll
    for (int j = 0; j < 8; j++)
#pragma unroll
        for (int q = 0; q < 4; q++) c[j][q] = 0.f;

    int m0 = w * 16;
    int r4 = lane >> 2, c4 = lane & 3;

    for (int kk = 0; kk < 128; kk += 64) {
        __syncthreads();
#pragma unroll
        for (int i = 0; i < 8; i++) {
            int q = tid + i * 128;
            int row = q >> 4, cq = (q & 15) * 4;
            int gn = n0 + row;
            float4 v = make_float4(0,0,0,0);
            if (gn < NN) v = *(const float4*)(x + (size_t)gn * 128 + kk + cq);
            unsigned* ap = &As[row * 68 + cq];
            ap[0] = f2tf32(v.x); ap[1] = f2tf32(v.y);
            ap[2] = f2tf32(v.z); ap[3] = f2tf32(v.w);
        }
#pragma unroll
        for (int i = 0; i < 8; i++) {
            int q = tid + i * 128;
            int row = q >> 4, cq = (q & 15) * 4;
            float4 v = *(const float4*)(W1 + (size_t)(kk + row) * 256 + hb * 64 + cq);
            unsigned* bp = &Bs[row * 68 + cq];
            bp[0] = f2tf32(v.x); bp[1] = f2tf32(v.y);
            bp[2] = f2tf32(v.z); bp[3] = f2tf32(v.w);
        }
        __syncthreads();

#pragma unroll
        for (int ks = 0; ks < 8; ks++) {
            int k0 = ks * 8;
            unsigned a0 = As[(m0 + r4) * 68 + k0 + c4];
            unsigned a1 = As[(m0 + r4 + 8) * 68 + k0 + c4];
            unsigned a2 = As[(m0 + r4) * 68 + k0 + c4 + 4];
            unsigned a3 = As[(m0 + r4 + 8) * 68 + k0 + c4 + 4];
#pragma unroll
            for (int j = 0; j < 8; j++) {
                unsigned b0 = Bs[(k0 + c4) * 68 + j * 8 + r4];
                unsigned b1 = Bs[(k0 + c4 + 4) * 68 + j * 8 + r4];
                mma_tf32(c[j][0], c[j][1], c[j][2], c[j][3], a0, a1, a2, a3, b0, b1);
            }
        }
    }

    __syncthreads();
#pragma unroll
    for (int j = 0; j < 8; j++) {
        int col = j * 8 + 2 * c4;
        *(__half2*)&Cs[(m0 + r4) * 72 + col]     = __floats2half2_rn(c[j][0], c[j][1]);
        *(__half2*)&Cs[(m0 + r4 + 8) * 72 + col] = __floats2half2_rn(c[j][2], c[j][3]);
    }
    __syncthreads();

#pragma unroll
    for (int i = 0; i < 4; i++) {
        int q = tid + i * 128;
        int row = q >> 3, cq = (q & 7) * 8;
        int gn = n0 + row;
        if (gn < NN)
            *(uint4*)(g_xl1h + (size_t)gn * 256 + hb * 64 + cq) =
                *(uint4*)&Cs[row * 72 + cq];
    }

    {
        int row = tid >> 1;
        int cbase = (tid & 1) * 32;
        float s = 0.f, d = 0.f;
#pragma unroll
        for (int cc = 0; cc < 32; cc++) {
            float v = __half2float(Cs[row * 72 + cbase + cc]);
            s += v * sA[cbase + cc];
            d += v * sD[cbase + cc];
        }
        s += __shfl_xor_sync(0xffffffffu, s, 1);
        d += __shfl_xor_sync(0xffffffffu, d, 1);
        int gn = n0 + row;
        if ((tid & 1) == 0 && gn < NN) {
            g_ls1[gn * 4 + hb] = s;
            g_ld1[gn * 4 + hb] = d;
        }
    }
}

// ------- aggregation layer1 (CSR; warp/dst; fp16 gather; recomputed w) ------
__global__ __launch_bounds__(256) void k_agg1(const float* __restrict__ b1) {
    int wid = threadIdx.x >> 5, lane = threadIdx.x & 31;
    int dst = blockIdx.x * 8 + wid;
    if (dst >= NN) return;
    int beg = g_off[dst], end = g_off[dst + 1];
    int hh = lane >> 3;
    float ldv = g_ld1[dst * 4 + hh];
    float2 a0 = make_float2(0,0), a1 = make_float2(0,0);
    float2 a2 = make_float2(0,0), a3 = make_float2(0,0);
    float den = 0.f;
    int j = beg;
    for (; j + 2 <= end; j += 2) {
        int s0 = __ldg(&g_src[j]);
        int s1 = __ldg(&g_src[j + 1]);
        float w0 = __expf(lrelu(__ldg(&g_ls1[s0 * 4 + hh]) + ldv));
        float w1 = __expf(lrelu(__ldg(&g_ls1[s1 * 4 + hh]) + ldv));
        uint4 hv0 = __ldg((const uint4*)(g_xl1h + (size_t)s0 * 256 + lane * 8));
        uint4 hv1 = __ldg((const uint4*)(g_xl1h + (size_t)s1 * 256 + lane * 8));
        den += w0 + w1;
        float2 v;
        v = __half22float2(*(__half2*)&hv0.x); a0.x += w0 * v.x; a0.y += w0 * v.y;
        v = __half22float2(*(__half2*)&hv0.y); a1.x += w0 * v.x; a1.y += w0 * v.y;
        v = __half22float2(*(__half2*)&hv0.z); a2.x += w0 * v.x; a2.y += w0 * v.y;
        v = __half22float2(*(__half2*)&hv0.w); a3.x += w0 * v.x; a3.y += w0 * v.y;
        v = __half22float2(*(__half2*)&hv1.x); a0.x += w1 * v.x; a0.y += w1 * v.y;
        v = __half22float2(*(__half2*)&hv1.y); a1.x += w1 * v.x; a1.y += w1 * v.y;
        v = __half22float2(*(__half2*)&hv1.z); a2.x += w1 * v.x; a2.y += w1 * v.y;
        v = __half22float2(*(__half2*)&hv1.w); a3.x += w1 * v.x; a3.y += w1 * v.y;
    }
    if (j < end) {
        int s0 = __ldg(&g_src[j]);
        float w0 = __expf(lrelu(__ldg(&g_ls1[s0 * 4 + hh]) + ldv));
        uint4 hv0 = __ldg((const uint4*)(g_xl1h + (size_t)s0 * 256 + lane * 8));
        den += w0;
        float2 v;
        v = __half22float2(*(__half2*)&hv0.x); a0.x += w0 * v.x; a0.y += w0 * v.y;
        v = __half22float2(*(__half2*)&hv0.y); a1.x += w0 * v.x; a1.y += w0 * v.y;
        v = __half22float2(*(__half2*)&hv0.z); a2.x += w0 * v.x; a2.y += w0 * v.y;
        v = __half22float2(*(__half2*)&hv0.w); a3.x += w0 * v.x; a3.y += w0 * v.y;
    }
    float inv = 1.f / den;
    float4 bb0 = *(const float4*)(b1 + lane * 8);
    float4 bb1 = *(const float4*)(b1 + lane * 8 + 4);
    float o0 = fmaxf(a0.x * inv + bb0.x, 0.f);
    float o1 = fmaxf(a0.y * inv + bb0.y, 0.f);
    float o2 = fmaxf(a1.x * inv + bb0.z, 0.f);
    float o3 = fmaxf(a1.y * inv + bb0.w, 0.f);
    float o4 = fmaxf(a2.x * inv + bb1.x, 0.f);
    float o5 = fmaxf(a2.y * inv + bb1.y, 0.f);
    float o6 = fmaxf(a3.x * inv + bb1.z, 0.f);
    float o7 = fmaxf(a3.y * inv + bb1.w, 0.f);
    uint4 st;
    *(__half2*)&st.x = __floats2half2_rn(o0, o1);
    *(__half2*)&st.y = __floats2half2_rn(o2, o3);
    *(__half2*)&st.z = __floats2half2_rn(o4, o5);
    *(__half2*)&st.w = __floats2half2_rn(o6, o7);
    *(uint4*)(g_h1h + (size_t)dst * 256 + lane * 8) = st;
}

// ---------------- GEMM2 (+ fused logits2); fp16 input ----------------------
__global__ __launch_bounds__(256) void k_gemm2(const float* __restrict__ W2,
                                               const float* __restrict__ as2,
                                               const float* __restrict__ ad2) {
    __shared__ float hs[64 * 64];
    __shared__ float ws[64 * 32];
    __shared__ float sa[32], sdd[32];
    int tid = threadIdx.x;
    if (tid < 32) { sa[tid] = as2[tid]; sdd[tid] = ad2[tid]; }
    int n0 = blockIdx.x * 64;
    int c = tid & 31, nl = tid >> 5;
    float acc[8] = {0,0,0,0,0,0,0,0};

    for (int kk = 0; kk < 256; kk += 64) {
        __syncthreads();
        const float4* wsrc = (const float4*)(W2 + (size_t)kk * 32);
#pragma unroll
        for (int j = 0; j < 2; j++) ((float4*)ws)[tid + j * 256] = wsrc[tid + j * 256];
#pragma unroll
        for (int j = 0; j < 2; j++) {
            int q = tid + j * 256;
            int flat = q * 8;
            int node = flat >> 6, kl = flat & 63;
            int gn = n0 + node;
            uint4 hv = make_uint4(0,0,0,0);
            if (gn < NN) hv = *(const uint4*)(g_h1h + (size_t)gn * 256 + kk + kl);
            float2 v0 = __half22float2(*(__half2*)&hv.x);
            float2 v1 = __half22float2(*(__half2*)&hv.y);
            float2 v2 = __half22float2(*(__half2*)&hv.z);
            float2 v3 = __half22float2(*(__half2*)&hv.w);
            float* hp = &hs[flat];
            hp[0] = v0.x; hp[1] = v0.y; hp[2] = v1.x; hp[3] = v1.y;
            hp[4] = v2.x; hp[5] = v2.y; hp[6] = v3.x; hp[7] = v3.y;
        }
        __syncthreads();
#pragma unroll
        for (int k = 0; k < 64; k += 4) {
            float w0 = ws[(k+0)*32 + c];
            float w1 = ws[(k+1)*32 + c];
            float w2 = ws[(k+2)*32 + c];
            float w3 = ws[(k+3)*32 + c];
#pragma unroll
            for (int i = 0; i < 8; i++) {
                float4 h4 = *(float4*)&hs[(nl*8 + i) * 64 + k];
                acc[i] += h4.x*w0 + h4.y*w1 + h4.z*w2 + h4.w*w3;
            }
        }
    }
#pragma unroll
    for (int i = 0; i < 8; i++) {
        int gn = n0 + nl * 8 + i;
        float ps = acc[i] * sa[c];
        float pd = acc[i] * sdd[c];
#pragma unroll
        for (int o = 16; o > 0; o >>= 1) {
            ps += __shfl_xor_sync(0xffffffffu, ps, o);
            pd += __shfl_xor_sync(0xffffffffu, pd, o);
        }
        if (gn < NN) {
            g_xl2h[(size_t)gn * 32 + c] = __float2half_rn(acc[i]);
            if (c == 0) { g_ls2[gn] = ps; g_ld2[gn] = pd; }
        }
    }
}

// ---------------- aggregation layer2 (CSR; fp16 gather; unroll 2) ----------
__global__ __launch_bounds__(256) void k_agg2(const float* __restrict__ b2) {
    int wid = threadIdx.x >> 5, lane = threadIdx.x & 31;
    int dst = blockIdx.x * 8 + wid;
    if (dst >= NN) return;
    int beg = g_off[dst], end = g_off[dst + 1];
    float ld2d = g_ld2[dst];
    float acc = 0.f, den = 0.f;
    int j = beg;
    for (; j + 2 <= end; j += 2) {
        int s0 = __ldg(&g_src[j]);
        int s1 = __ldg(&g_src[j + 1]);
        float w0 = __expf(lrelu(__ldg(&g_ls2[s0]) + ld2d));
        float w1 = __expf(lrelu(__ldg(&g_ls2[s1]) + ld2d));
        float v0 = __half2float(__ldg(&g_xl2h[(size_t)s0 * 32 + lane]));
        float v1 = __half2float(__ldg(&g_xl2h[(size_t)s1 * 32 + lane]));
        den += w0 + w1;
        acc += w0 * v0 + w1 * v1;
    }
    if (j < end) {
        int s0 = __ldg(&g_src[j]);
        float w0 = __expf(lrelu(__ldg(&g_ls2[s0]) + ld2d));
        den += w0;
        acc += w0 * __half2float(__ldg(&g_xl2h[(size_t)s0 * 32 + lane]));
    }
    float h = fmaxf(acc / den + b2[lane], 0.f);
    g_h2[(size_t)dst * 32 + lane] = h;
}

// ---------------- final: out = h2 @ fc_W + fc_b ----------------
__global__ __launch_bounds__(128) void k_final(const float* __restrict__ fcW,
                                               const float* __restrict__ fcb,
                                               float* __restrict__ out) {
    __shared__ float fw[32 * 128];
    __shared__ float hs[32 * 32];
    int tid = threadIdx.x;
    int n0 = blockIdx.x * 32;
#pragma unroll
    for (int j = 0; j < 8; j++) ((float4*)fw)[tid + j * 128] = ((const float4*)fcW)[tid + j * 128];
#pragma unroll
    for (int j = 0; j < 2; j++) {
        int q = tid + j * 128;
        int flat = q * 4;
        int node = flat >> 5, kl = flat & 31;
        int gn = n0 + node;
        float4 v = make_float4(0,0,0,0);
        if (gn < NN) v = *(const float4*)(g_h2 + (size_t)gn * 32 + kl);
        *(float4*)&hs[flat] = v;
    }
    __syncthreads();
    float acc[32];
#pragma unroll
    for (int n = 0; n < 32; n++) acc[n] = 0.f;
#pragma unroll
    for (int k = 0; k < 32; k += 4) {
        float w0 = fw[(k+0)*128 + tid];
        float w1 = fw[(k+1)*128 + tid];
        float w2 = fw[(k+2)*128 + tid];
        float w3 = fw[(k+3)*128 + tid];
#pragma unroll
        for (int n = 0; n < 32; n++) {
            float4 h4 = *(float4*)&hs[n * 32 + k];
            acc[n] += h4.x*w0 + h4.y*w1 + h4.z*w2 + h4.w*w3;
        }
    }
    float bb = fcb[tid];
#pragma unroll
    for (int n = 0; n < 32; n++) {
        int gn = n0 + n;
        if (gn < NN) out[(size_t)gn * 128 + tid] = acc[n] + bb;
    }
}

// ---------------- launch ----------------
extern "C" void kernel_launch(void* const* d_in, const int* in_sizes, int n_in,
                              void* d_out, int out_size) {
    const float* x   = (const float*)d_in[0];
    const int*   ei  = (const int*)d_in[1];
    const float* W1  = (const float*)d_in[2];
    const float* as1 = (const float*)d_in[3];
    const float* ad1 = (const float*)d_in[4];
    const float* b1  = (const float*)d_in[5];
    const float* W2  = (const float*)d_in[6];
    const float* as2 = (const float*)d_in[7];
    const float* ad2 = (const float*)d_in[8];
    const float* b2  = (const float*)d_in[9];
    const float* fcW = (const float*)d_in[10];
    const float* fcb = (const float*)d_in[11];
    float* out = (float*)d_out;

    k_hist<<<(ET + 255) / 256, 256>>>(ei);
    k_scan_blk<<<NB, 256>>>();
    k_scan_top<<<1, 256>>>();
    k_scan_add<<<NB, 256>>>();
    k_scatter<<<(ET + 255) / 256, 256>>>(ei);
    dim3 g1((NN + 63) / 64, 4);
    k_gemm1<<<g1, 128>>>(x, W1, as1, ad1);
    k_agg1<<<(NN + 7) / 8, 256>>>(b1);
    k_gemm2<<<(NN + 63) / 64, 256>>>(W2, as2, ad2);
    k_agg2<<<(NN + 7) / 8, 256>>>(b2);
    k_final<<<(NN + 31) / 32, 128>>>(fcW, fcb, out);
}

// round 7
// speedup vs baseline: 2.5393x; 1.0093x over previous
#include <cuda_runtime.h>
#include <cuda_fp16.h>

// Problem constants
#define NN 50000
#define DD 128
#define EE 800000
#define ET (EE + NN)     // edges + self loops
#define F1 256
#define F2 32
#define NB ((NN + 255) / 256)   // 196 scan blocks

// ---------------- scratch (device globals; no allocations) ----------------
__device__ __half g_xl1h[NN * F1];   // fp16 xl1 for aggregation gather
__device__ __half g_h1h[NN * F1];    // relu(agg1 + b1), fp16 for gemm2
__device__ float  g_ls1[NN * 4];
__device__ float  g_ld1[NN * 4];

__device__ __half g_xl2h[NN * F2];   // fp16 xl2 for agg2 gather
__device__ __half g_h2h[NN * F2];    // relu(agg2 + b2) fp16 (feeds final mma)
__device__ float  g_ls2[NN];
__device__ float  g_ld2[NN];

// CSR structures (g_cnt self-restores to 0 every call: zeroed in k_scan_blk)
__device__ int g_cnt[NN];
__device__ int g_off[NN + 1];
__device__ int g_cur[NN];
__device__ int g_part[NN];
__device__ int g_bsum[NB];
__device__ int g_src[ET];            // src node per sorted edge

// ---------------- helpers ----------------
__device__ __forceinline__ float lrelu(float e) { return fmaxf(e, 0.2f * e); }

__device__ __forceinline__ unsigned f2tf32(float f) {
    unsigned u;
    asm("cvt.rna.tf32.f32 %0, %1;" : "=r"(u) : "f"(f));
    return u;
}
__device__ __forceinline__ void mma_tf32(float& c0, float& c1, float& c2, float& c3,
                                         unsigned a0, unsigned a1, unsigned a2, unsigned a3,
                                         unsigned b0, unsigned b1) {
    asm volatile("mma.sync.aligned.m16n8k8.row.col.f32.tf32.tf32.f32 "
                 "{%0,%1,%2,%3}, {%4,%5,%6,%7}, {%8,%9}, {%0,%1,%2,%3};"
                 : "+f"(c0), "+f"(c1), "+f"(c2), "+f"(c3)
                 : "r"(a0), "r"(a1), "r"(a2), "r"(a3), "r"(b0), "r"(b1));
}
__device__ __forceinline__ void mma_f16(float& c0, float& c1, float& c2, float& c3,
                                        unsigned a0, unsigned a1, unsigned a2, unsigned a3,
                                        unsigned b0, unsigned b1) {
    asm volatile("mma.sync.aligned.m16n8k16.row.col.f32.f16.f16.f32 "
                 "{%0,%1,%2,%3}, {%4,%5,%6,%7}, {%8,%9}, {%0,%1,%2,%3};"
                 : "+f"(c0), "+f"(c1), "+f"(c2), "+f"(c3)
                 : "r"(a0), "r"(a1), "r"(a2), "r"(a3), "r"(b0), "r"(b1));
}

// ---------------- CSR build ----------------
// Self-loops contribute exactly +1 per node, folded into k_scan_blk.
__global__ void k_hist(const int* __restrict__ ei) {
    int i = blockIdx.x * blockDim.x + threadIdx.x;
    if (i * 4 >= EE) return;
    int4 d4 = *(const int4*)(ei + EE + i * 4);
    atomicAdd(&g_cnt[d4.x], 1);
    atomicAdd(&g_cnt[d4.y], 1);
    atomicAdd(&g_cnt[d4.z], 1);
    atomicAdd(&g_cnt[d4.w], 1);
}

__global__ void k_scan_blk() {
    __shared__ int wsum[8];
    int tid = threadIdx.x;
    int t = blockIdx.x * 256 + tid;
    int v = 0;
    if (t < NN) { v = g_cnt[t] + 1; g_cnt[t] = 0; }   // +1 = self loop; restore 0
    int lane = tid & 31, wid = tid >> 5;
    int incl = v;
#pragma unroll
    for (int o = 1; o < 32; o <<= 1) {
        int n = __shfl_up_sync(0xffffffffu, incl, o);
        if (lane >= o) incl += n;
    }
    if (lane == 31) wsum[wid] = incl;
    __syncthreads();
    if (wid == 0) {
        int s = (lane < 8) ? wsum[lane] : 0;
#pragma unroll
        for (int o = 1; o < 8; o <<= 1) {
            int n = __shfl_up_sync(0xffffffffu, s, o);
            if (lane >= o) s += n;
        }
        if (lane < 8) wsum[lane] = s;
    }
    __syncthreads();
    int base = (wid > 0) ? wsum[wid - 1] : 0;
    if (t < NN) g_part[t] = base + incl - v;
    if (tid == 255) g_bsum[blockIdx.x] = wsum[7];
}

// merged top-level scan: each block reduces g_bsum[0..blockIdx.x-1]
__global__ void k_scan_add() {
    __shared__ int wsum[8];
    __shared__ int sbase;
    int tid = threadIdx.x;
    int lane = tid & 31, wid = tid >> 5;
    int vb = (tid < blockIdx.x) ? g_bsum[tid] : 0;   // blockIdx.x <= 195 < 256
#pragma unroll
    for (int o = 16; o > 0; o >>= 1) vb += __shfl_xor_sync(0xffffffffu, vb, o);
    if (lane == 0) wsum[wid] = vb;
    __syncthreads();
    if (wid == 0) {
        int s = (lane < 8) ? wsum[lane] : 0;
#pragma unroll
        for (int o = 4; o > 0; o >>= 1) s += __shfl_xor_sync(0xffffffffu, s, o);
        if (lane == 0) sbase = s;
    }
    __syncthreads();
    int t = blockIdx.x * 256 + tid;
    if (t < NN) {
        int off = g_part[t] + sbase;
        g_off[t] = off;
        g_cur[t] = off;
    }
    if (blockIdx.x == 0 && tid == 0) g_off[NN] = ET;
}

// scatter: place edge src at sorted position (weights recomputed in agg1)
__global__ void k_scatter(const int* __restrict__ ei) {
    int i = blockIdx.x * blockDim.x + threadIdx.x;
    if (i >= ET) return;
    int s, d;
    if (i < EE) { s = ei[i]; d = ei[EE + i]; } else { s = d = i - EE; }
    int pos = atomicAdd(&g_cur[d], 1);
    g_src[pos] = s;
}

// ---------------- GEMM1 (tf32 tensor-core) + fused logits1 ------------------
__global__ __launch_bounds__(128) void k_gemm1(const float* __restrict__ x,
                                               const float* __restrict__ W1,
                                               const float* __restrict__ as1,
                                               const float* __restrict__ ad1) {
    __shared__ unsigned As[64 * 68];
    __shared__ unsigned Bs[64 * 68];
    __shared__ __half   Cs[64 * 72];
    __shared__ float    sA[64], sD[64];

    int tid = threadIdx.x;
    int lane = tid & 31, w = tid >> 5;
    int n0 = blockIdx.x * 64;
    int hb = blockIdx.y;
    if (tid < 64) {
        sA[tid] = as1[hb * 64 + tid];
        sD[tid] = ad1[hb * 64 + tid];
    }

    float c[8][4];
#pragma unroll
    for (int j = 0; j < 8; j++)
#pragma unroll
        for (int q = 0; q < 4; q++) c[j][q] = 0.f;

    int m0 = w * 16;
    int r4 = lane >> 2, c4 = lane & 3;

    for (int kk = 0; kk < 128; kk += 64) {
        __syncthreads();
#pragma unroll
        for (int i = 0; i < 8; i++) {
            int q = tid + i * 128;
            int row = q >> 4, cq = (q & 15) * 4;
            int gn = n0 + row;
            float4 v = make_float4(0,0,0,0);
            if (gn < NN) v = *(const float4*)(x + (size_t)gn * 128 + kk + cq);
            unsigned* ap = &As[row * 68 + cq];
            ap[0] = f2tf32(v.x); ap[1] = f2tf32(v.y);
            ap[2] = f2tf32(v.z); ap[3] = f2tf32(v.w);
        }
#pragma unroll
        for (int i = 0; i < 8; i++) {
            int q = tid + i * 128;
            int row = q >> 4, cq = (q & 15) * 4;
            float4 v = *(const float4*)(W1 + (size_t)(kk + row) * 256 + hb * 64 + cq);
            unsigned* bp = &Bs[row * 68 + cq];
            bp[0] = f2tf32(v.x); bp[1] = f2tf32(v.y);
            bp[2] = f2tf32(v.z); bp[3] = f2tf32(v.w);
        }
        __syncthreads();

#pragma unroll
        for (int ks = 0; ks < 8; ks++) {
            int k0 = ks * 8;
            unsigned a0 = As[(m0 + r4) * 68 + k0 + c4];
            unsigned a1 = As[(m0 + r4 + 8) * 68 + k0 + c4];
            unsigned a2 = As[(m0 + r4) * 68 + k0 + c4 + 4];
            unsigned a3 = As[(m0 + r4 + 8) * 68 + k0 + c4 + 4];
#pragma unroll
            for (int j = 0; j < 8; j++) {
                unsigned b0 = Bs[(k0 + c4) * 68 + j * 8 + r4];
                unsigned b1 = Bs[(k0 + c4 + 4) * 68 + j * 8 + r4];
                mma_tf32(c[j][0], c[j][1], c[j][2], c[j][3], a0, a1, a2, a3, b0, b1);
            }
        }
    }

    __syncthreads();
#pragma unroll
    for (int j = 0; j < 8; j++) {
        int col = j * 8 + 2 * c4;
        *(__half2*)&Cs[(m0 + r4) * 72 + col]     = __floats2half2_rn(c[j][0], c[j][1]);
        *(__half2*)&Cs[(m0 + r4 + 8) * 72 + col] = __floats2half2_rn(c[j][2], c[j][3]);
    }
    __syncthreads();

#pragma unroll
    for (int i = 0; i < 4; i++) {
        int q = tid + i * 128;
        int row = q >> 3, cq = (q & 7) * 8;
        int gn = n0 + row;
        if (gn < NN)
            *(uint4*)(g_xl1h + (size_t)gn * 256 + hb * 64 + cq) =
                *(uint4*)&Cs[row * 72 + cq];
    }

    {
        int row = tid >> 1;
        int cbase = (tid & 1) * 32;
        float s = 0.f, d = 0.f;
#pragma unroll
        for (int cc = 0; cc < 32; cc++) {
            float v = __half2float(Cs[row * 72 + cbase + cc]);
            s += v * sA[cbase + cc];
            d += v * sD[cbase + cc];
        }
        s += __shfl_xor_sync(0xffffffffu, s, 1);
        d += __shfl_xor_sync(0xffffffffu, d, 1);
        int gn = n0 + row;
        if ((tid & 1) == 0 && gn < NN) {
            g_ls1[gn * 4 + hb] = s;
            g_ld1[gn * 4 + hb] = d;
        }
    }
}

// ------- aggregation layer1 (CSR; warp/dst; fp16 gather; unroll 4) ----------
__global__ __launch_bounds__(256) void k_agg1(const float* __restrict__ b1) {
    int wid = threadIdx.x >> 5, lane = threadIdx.x & 31;
    int dst = blockIdx.x * 8 + wid;
    if (dst >= NN) return;
    int beg = g_off[dst], end = g_off[dst + 1];
    int hh = lane >> 3;
    float ldv = g_ld1[dst * 4 + hh];
    float2 a0 = make_float2(0,0), a1 = make_float2(0,0);
    float2 a2 = make_float2(0,0), a3 = make_float2(0,0);
    float den = 0.f;
    int j = beg;
    for (; j + 4 <= end; j += 4) {
        int s[4];
#pragma unroll
        for (int u = 0; u < 4; u++) s[u] = __ldg(&g_src[j + u]);
        float wv[4];
#pragma unroll
        for (int u = 0; u < 4; u++) wv[u] = __expf(lrelu(__ldg(&g_ls1[s[u] * 4 + hh]) + ldv));
        uint4 hv[4];
#pragma unroll
        for (int u = 0; u < 4; u++) hv[u] = __ldg((const uint4*)(g_xl1h + (size_t)s[u] * 256 + lane * 8));
#pragma unroll
        for (int u = 0; u < 4; u++) {
            float wu = wv[u];
            den += wu;
            float2 v;
            v = __half22float2(*(__half2*)&hv[u].x); a0.x += wu * v.x; a0.y += wu * v.y;
            v = __half22float2(*(__half2*)&hv[u].y); a1.x += wu * v.x; a1.y += wu * v.y;
            v = __half22float2(*(__half2*)&hv[u].z); a2.x += wu * v.x; a2.y += wu * v.y;
            v = __half22float2(*(__half2*)&hv[u].w); a3.x += wu * v.x; a3.y += wu * v.y;
        }
    }
    for (; j < end; j++) {
        int s0 = __ldg(&g_src[j]);
        float w0 = __expf(lrelu(__ldg(&g_ls1[s0 * 4 + hh]) + ldv));
        uint4 hv0 = __ldg((const uint4*)(g_xl1h + (size_t)s0 * 256 + lane * 8));
        den += w0;
        float2 v;
        v = __half22float2(*(__half2*)&hv0.x); a0.x += w0 * v.x; a0.y += w0 * v.y;
        v = __half22float2(*(__half2*)&hv0.y); a1.x += w0 * v.x; a1.y += w0 * v.y;
        v = __half22float2(*(__half2*)&hv0.z); a2.x += w0 * v.x; a2.y += w0 * v.y;
        v = __half22float2(*(__half2*)&hv0.w); a3.x += w0 * v.x; a3.y += w0 * v.y;
    }
    float inv = 1.f / den;
    float4 bb0 = *(const float4*)(b1 + lane * 8);
    float4 bb1 = *(const float4*)(b1 + lane * 8 + 4);
    float o0 = fmaxf(a0.x * inv + bb0.x, 0.f);
    float o1 = fmaxf(a0.y * inv + bb0.y, 0.f);
    float o2 = fmaxf(a1.x * inv + bb0.z, 0.f);
    float o3 = fmaxf(a1.y * inv + bb0.w, 0.f);
    float o4 = fmaxf(a2.x * inv + bb1.x, 0.f);
    float o5 = fmaxf(a2.y * inv + bb1.y, 0.f);
    float o6 = fmaxf(a3.x * inv + bb1.z, 0.f);
    float o7 = fmaxf(a3.y * inv + bb1.w, 0.f);
    uint4 st;
    *(__half2*)&st.x = __floats2half2_rn(o0, o1);
    *(__half2*)&st.y = __floats2half2_rn(o2, o3);
    *(__half2*)&st.z = __floats2half2_rn(o4, o5);
    *(__half2*)&st.w = __floats2half2_rn(o6, o7);
    *(uint4*)(g_h1h + (size_t)dst * 256 + lane * 8) = st;
}

// ---------------- GEMM2 (fp16 mma) + fused logits2 --------------------------
// 64 nodes x 32 cols per block; K=256 in two 128-chunks. 128 thr / 4 warps.
__global__ __launch_bounds__(128) void k_gemm2(const float* __restrict__ W2,
                                               const float* __restrict__ as2,
                                               const float* __restrict__ ad2) {
    __shared__ __half As[64 * 136];   // [row][k-chunk 128], pad 136
    __shared__ __half Bs[32 * 264];   // [n][k 256], pad 264
    __shared__ __half Cs[64 * 40];    // [row][n 32], pad 40
    __shared__ float  sa[32], sd[32];
    int tid = threadIdx.x;
    int lane = tid & 31, w = tid >> 5;
    int n0 = blockIdx.x * 64;
    if (tid < 32) { sa[tid] = as2[tid]; sd[tid] = ad2[tid]; }
    // load W2 transposed -> Bs[n][k] fp16
#pragma unroll
    for (int i = 0; i < 64; i++) {
        int idx = tid + i * 128;          // 8192 elements
        int k = idx >> 5, n = idx & 31;
        Bs[n * 264 + k] = __float2half_rn(W2[idx]);
    }
    float c[4][4];
#pragma unroll
    for (int j = 0; j < 4; j++)
#pragma unroll
        for (int q = 0; q < 4; q++) c[j][q] = 0.f;
    int r4 = lane >> 2, c4 = lane & 3, m0 = w * 16;

    for (int ch = 0; ch < 2; ch++) {
        __syncthreads();
#pragma unroll
        for (int i = 0; i < 8; i++) {
            int q = tid + i * 128;             // 1024 uint4
            int row = q >> 4, cq = (q & 15) * 8;
            int gn = n0 + row;
            uint4 v = make_uint4(0,0,0,0);
            if (gn < NN) v = *(const uint4*)(g_h1h + (size_t)gn * 256 + ch * 128 + cq);
            *(uint4*)&As[row * 136 + cq] = v;
        }
        __syncthreads();
#pragma unroll
        for (int ks = 0; ks < 8; ks++) {
            int kb = ks * 16;
            unsigned a0 = *(unsigned*)&As[(m0 + r4) * 136 + kb + 2 * c4];
            unsigned a1 = *(unsigned*)&As[(m0 + r4 + 8) * 136 + kb + 2 * c4];
            unsigned a2 = *(unsigned*)&As[(m0 + r4) * 136 + kb + 2 * c4 + 8];
            unsigned a3 = *(unsigned*)&As[(m0 + r4 + 8) * 136 + kb + 2 * c4 + 8];
            int kg = ch * 128 + kb + 2 * c4;
#pragma unroll
            for (int j = 0; j < 4; j++) {
                int n = j * 8 + r4;
                unsigned b0 = *(unsigned*)&Bs[n * 264 + kg];
                unsigned b1 = *(unsigned*)&Bs[n * 264 + kg + 8];
                mma_f16(c[j][0], c[j][1], c[j][2], c[j][3], a0, a1, a2, a3, b0, b1);
            }
        }
    }
    __syncthreads();
#pragma unroll
    for (int j = 0; j < 4; j++) {
        int col = j * 8 + 2 * c4;
        *(__half2*)&Cs[(m0 + r4) * 40 + col]     = __floats2half2_rn(c[j][0], c[j][1]);
        *(__half2*)&Cs[(m0 + r4 + 8) * 40 + col] = __floats2half2_rn(c[j][2], c[j][3]);
    }
    __syncthreads();
    // write xl2h
#pragma unroll
    for (int i = 0; i < 2; i++) {
        int q = tid + i * 128;                 // 256 uint4
        int row = q >> 2, cq = (q & 3) * 8;
        int gn = n0 + row;
        if (gn < NN)
            *(uint4*)(g_xl2h + (size_t)gn * 32 + cq) = *(uint4*)&Cs[row * 40 + cq];
    }
    // logits2
    if (tid < 64) {
        int gn = n0 + tid;
        if (gn < NN) {
            float s = 0.f, d = 0.f;
#pragma unroll
            for (int cc = 0; cc < 32; cc++) {
                float v = __half2float(Cs[tid * 40 + cc]);
                s += v * sa[cc];
                d += v * sd[cc];
            }
            g_ls2[gn] = s;
            g_ld2[gn] = d;
        }
    }
}

// ---------------- aggregation layer2 (CSR; fp16 gather; unroll 4) ----------
__global__ __launch_bounds__(256) void k_agg2(const float* __restrict__ b2) {
    int wid = threadIdx.x >> 5, lane = threadIdx.x & 31;
    int dst = blockIdx.x * 8 + wid;
    if (dst >= NN) return;
    int beg = g_off[dst], end = g_off[dst + 1];
    float ld2d = g_ld2[dst];
    float acc = 0.f, den = 0.f;
    int j = beg;
    for (; j + 4 <= end; j += 4) {
        int s[4];
#pragma unroll
        for (int u = 0; u < 4; u++) s[u] = __ldg(&g_src[j + u]);
        float wv[4], vv[4];
#pragma unroll
        for (int u = 0; u < 4; u++) wv[u] = __expf(lrelu(__ldg(&g_ls2[s[u]]) + ld2d));
#pragma unroll
        for (int u = 0; u < 4; u++) vv[u] = __half2float(__ldg(&g_xl2h[(size_t)s[u] * 32 + lane]));
#pragma unroll
        for (int u = 0; u < 4; u++) { den += wv[u]; acc += wv[u] * vv[u]; }
    }
    for (; j < end; j++) {
        int s0 = __ldg(&g_src[j]);
        float w0 = __expf(lrelu(__ldg(&g_ls2[s0]) + ld2d));
        den += w0;
        acc += w0 * __half2float(__ldg(&g_xl2h[(size_t)s0 * 32 + lane]));
    }
    float h = fmaxf(acc / den + b2[lane], 0.f);
    g_h2h[(size_t)dst * 32 + lane] = __float2half_rn(h);
}

// ---------------- final (fp16 mma): out = h2 @ fc_W + fc_b ------------------
// 64 nodes x 128 cols per block; K=32 (2 k16 steps). 128 thr / 4 warps.
__global__ __launch_bounds__(128) void k_final(const float* __restrict__ fcW,
                                               const float* __restrict__ fcb,
                                               float* __restrict__ out) {
    __shared__ __half As[64 * 40];    // [row][k 32], pad 40
    __shared__ __half Bs[128 * 40];   // [n][k 32], pad 40
    __shared__ float  sb[128];
    int tid = threadIdx.x;
    int lane = tid & 31, w = tid >> 5;
    int n0 = blockIdx.x * 64;
    sb[tid] = fcb[tid];
    // fcW [32][128] -> Bs[n][k] fp16
#pragma unroll
    for (int i = 0; i < 32; i++) {
        int idx = tid + i * 128;           // 4096 elements
        int k = idx >> 7, n = idx & 127;
        Bs[n * 40 + k] = __float2half_rn(fcW[idx]);
    }
    // h2h tile -> As
#pragma unroll
    for (int i = 0; i < 2; i++) {
        int q = tid + i * 128;             // 256 uint4
        int row = q >> 2, cq = (q & 3) * 8;
        int gn = n0 + row;
        uint4 v = make_uint4(0,0,0,0);
        if (gn < NN) v = *(const uint4*)(g_h2h + (size_t)gn * 32 + cq);
        *(uint4*)&As[row * 40 + cq] = v;
    }
    __syncthreads();

    float c[16][4];
#pragma unroll
    for (int j = 0; j < 16; j++)
#pragma unroll
        for (int q = 0; q < 4; q++) c[j][q] = 0.f;
    int r4 = lane >> 2, c4 = lane & 3, m0 = w * 16;

#pragma unroll
    for (int ks = 0; ks < 2; ks++) {
        int kb = ks * 16;
        unsigned a0 = *(unsigned*)&As[(m0 + r4) * 40 + kb + 2 * c4];
        unsigned a1 = *(unsigned*)&As[(m0 + r4 + 8) * 40 + kb + 2 * c4];
        unsigned a2 = *(unsigned*)&As[(m0 + r4) * 40 + kb + 2 * c4 + 8];
        unsigned a3 = *(unsigned*)&As[(m0 + r4 + 8) * 40 + kb + 2 * c4 + 8];
#pragma unroll
        for (int j = 0; j < 16; j++) {
            int n = j * 8 + r4;
            unsigned b0 = *(unsigned*)&Bs[n * 40 + kb + 2 * c4];
            unsigned b1 = *(unsigned*)&Bs[n * 40 + kb + 2 * c4 + 8];
            mma_f16(c[j][0], c[j][1], c[j][2], c[j][3], a0, a1, a2, a3, b0, b1);
        }
    }
    int row0 = n0 + m0 + r4, row1 = row0 + 8;
#pragma unroll
    for (int j = 0; j < 16; j++) {
        int col = j * 8 + 2 * c4;
        float bx = sb[col], by = sb[col + 1];
        if (row0 < NN) {
            float2 v0 = make_float2(c[j][0] + bx, c[j][1] + by);
            *(float2*)(out + (size_t)row0 * 128 + col) = v0;
        }
        if (row1 < NN) {
            float2 v1 = make_float2(c[j][2] + bx, c[j][3] + by);
            *(float2*)(out + (size_t)row1 * 128 + col) = v1;
        }
    }
}

// ---------------- launch ----------------
extern "C" void kernel_launch(void* const* d_in, const int* in_sizes, int n_in,
                              void* d_out, int out_size) {
    const float* x   = (const float*)d_in[0];
    const int*   ei  = (const int*)d_in[1];
    const float* W1  = (const float*)d_in[2];
    const float* as1 = (const float*)d_in[3];
    const float* ad1 = (const float*)d_in[4];
    const float* b1  = (const float*)d_in[5];
    const float* W2  = (const float*)d_in[6];
    const float* as2 = (const float*)d_in[7];
    const float* ad2 = (const float*)d_in[8];
    const float* b2  = (const float*)d_in[9];
    const float* fcW = (const float*)d_in[10];
    const float* fcb = (const float*)d_in[11];
    float* out = (float*)d_out;

    k_hist<<<(EE / 4 + 255) / 256, 256>>>(ei);
    k_scan_blk<<<NB, 256>>>();
    k_scan_add<<<NB, 256>>>();
    k_scatter<<<(ET + 255) / 256, 256>>>(ei);
    dim3 g1((NN + 63) / 64, 4);
    k_gemm1<<<g1, 128>>>(x, W1, as1, ad1);
    k_agg1<<<(NN + 7) / 8, 256>>>(b1);
    k_gemm2<<<(NN + 63) / 64, 128>>>(W2, as2, ad2);
    k_agg2<<<(NN + 7) / 8, 256>>>(b2);
    k_final<<<(NN + 63) / 64, 128>>>(fcW, fcb, out);
}

// round 8
// speedup vs baseline: 3.1741x; 1.2500x over previous
#include <cuda_runtime.h>
#include <cuda_fp16.h>

// Problem constants
#define NN 50000
#define DD 128
#define EE 800000
#define ET (EE + NN)     // edges + self loops
#define F1 256
#define F2 32
#define NB ((NN + 255) / 256)   // 196 scan blocks

// ---------------- scratch (device globals; no allocations) ----------------
__device__ __half g_xl1h[NN * F1];   // fp16 xl1 for aggregation gather
__device__ __half g_h1h[NN * F1];    // relu(agg1 + b1), fp16 for gemm2
__device__ float  g_ls1[NN * 4];
__device__ float  g_ld1[NN * 4];

__device__ __half g_xl2h[NN * F2];   // fp16 xl2 for agg2 gather
__device__ __half g_h2h[NN * F2];    // relu(agg2 + b2) fp16 (feeds final mma)
__device__ float  g_ls2[NN];
__device__ float  g_ld2[NN];

// CSR structures (g_cnt self-restores to 0 every call: zeroed in k_scan_blk)
__device__ int g_cnt[NN];
__device__ int g_off[NN + 1];
__device__ int g_cur[NN];
__device__ int g_part[NN];
__device__ int g_bsum[NB];
__device__ int g_src[ET];            // src node per sorted edge

// ---------------- side stream for DAG capture (created once at load) -------
struct SideStream {
    cudaStream_t s = nullptr;
    cudaEvent_t fork = nullptr, join = nullptr;
    bool ok = false;
    SideStream() {
        if (cudaStreamCreateWithFlags(&s, cudaStreamNonBlocking) == cudaSuccess &&
            cudaEventCreateWithFlags(&fork, cudaEventDisableTiming) == cudaSuccess &&
            cudaEventCreateWithFlags(&join, cudaEventDisableTiming) == cudaSuccess)
            ok = true;
    }
};
static SideStream g_ss;

// ---------------- helpers ----------------
__device__ __forceinline__ float lrelu(float e) { return fmaxf(e, 0.2f * e); }

__device__ __forceinline__ unsigned f2tf32(float f) {
    unsigned u;
    asm("cvt.rna.tf32.f32 %0, %1;" : "=r"(u) : "f"(f));
    return u;
}
__device__ __forceinline__ void mma_tf32(float& c0, float& c1, float& c2, float& c3,
                                         unsigned a0, unsigned a1, unsigned a2, unsigned a3,
                                         unsigned b0, unsigned b1) {
    asm volatile("mma.sync.aligned.m16n8k8.row.col.f32.tf32.tf32.f32 "
                 "{%0,%1,%2,%3}, {%4,%5,%6,%7}, {%8,%9}, {%0,%1,%2,%3};"
                 : "+f"(c0), "+f"(c1), "+f"(c2), "+f"(c3)
                 : "r"(a0), "r"(a1), "r"(a2), "r"(a3), "r"(b0), "r"(b1));
}
__device__ __forceinline__ void mma_f16(float& c0, float& c1, float& c2, float& c3,
                                        unsigned a0, unsigned a1, unsigned a2, unsigned a3,
                                        unsigned b0, unsigned b1) {
    asm volatile("mma.sync.aligned.m16n8k16.row.col.f32.f16.f16.f32 "
                 "{%0,%1,%2,%3}, {%4,%5,%6,%7}, {%8,%9}, {%0,%1,%2,%3};"
                 : "+f"(c0), "+f"(c1), "+f"(c2), "+f"(c3)
                 : "r"(a0), "r"(a1), "r"(a2), "r"(a3), "r"(b0), "r"(b1));
}

// ---------------- CSR build ----------------
__global__ void k_hist(const int* __restrict__ ei) {
    int i = blockIdx.x * blockDim.x + threadIdx.x;
    if (i * 4 >= EE) return;
    int4 d4 = *(const int4*)(ei + EE + i * 4);
    atomicAdd(&g_cnt[d4.x], 1);
    atomicAdd(&g_cnt[d4.y], 1);
    atomicAdd(&g_cnt[d4.z], 1);
    atomicAdd(&g_cnt[d4.w], 1);
}

__global__ void k_scan_blk() {
    __shared__ int wsum[8];
    int tid = threadIdx.x;
    int t = blockIdx.x * 256 + tid;
    int v = 0;
    if (t < NN) { v = g_cnt[t] + 1; g_cnt[t] = 0; }   // +1 = self loop; restore 0
    int lane = tid & 31, wid = tid >> 5;
    int incl = v;
#pragma unroll
    for (int o = 1; o < 32; o <<= 1) {
        int n = __shfl_up_sync(0xffffffffu, incl, o);
        if (lane >= o) incl += n;
    }
    if (lane == 31) wsum[wid] = incl;
    __syncthreads();
    if (wid == 0) {
        int s = (lane < 8) ? wsum[lane] : 0;
#pragma unroll
        for (int o = 1; o < 8; o <<= 1) {
            int n = __shfl_up_sync(0xffffffffu, s, o);
            if (lane >= o) s += n;
        }
        if (lane < 8) wsum[lane] = s;
    }
    __syncthreads();
    int base = (wid > 0) ? wsum[wid - 1] : 0;
    if (t < NN) g_part[t] = base + incl - v;
    if (tid == 255) g_bsum[blockIdx.x] = wsum[7];
}

// merged top-level scan: each block reduces g_bsum[0..blockIdx.x-1]
__global__ void k_scan_add() {
    __shared__ int wsum[8];
    __shared__ int sbase;
    int tid = threadIdx.x;
    int lane = tid & 31, wid = tid >> 5;
    int vb = (tid < blockIdx.x) ? g_bsum[tid] : 0;   // blockIdx.x <= 195 < 256
#pragma unroll
    for (int o = 16; o > 0; o >>= 1) vb += __shfl_xor_sync(0xffffffffu, vb, o);
    if (lane == 0) wsum[wid] = vb;
    __syncthreads();
    if (wid == 0) {
        int s = (lane < 8) ? wsum[lane] : 0;
#pragma unroll
        for (int o = 4; o > 0; o >>= 1) s += __shfl_xor_sync(0xffffffffu, s, o);
        if (lane == 0) sbase = s;
    }
    __syncthreads();
    int t = blockIdx.x * 256 + tid;
    if (t < NN) {
        int off = g_part[t] + sbase;
        g_off[t] = off;
        g_cur[t] = off;
    }
    if (blockIdx.x == 0 && tid == 0) g_off[NN] = ET;
}

// scatter: place edge src at sorted position; 4 edges per thread for MLP
__global__ void k_scatter(const int* __restrict__ ei) {
    int i = (blockIdx.x * blockDim.x + threadIdx.x) * 4;
    if (i >= ET) return;
    if (i < EE) {   // EE divisible by 4 -> quads never straddle the boundary
        int4 s4 = *(const int4*)(ei + i);
        int4 d4 = *(const int4*)(ei + EE + i);
        int p0 = atomicAdd(&g_cur[d4.x], 1);
        int p1 = atomicAdd(&g_cur[d4.y], 1);
        int p2 = atomicAdd(&g_cur[d4.z], 1);
        int p3 = atomicAdd(&g_cur[d4.w], 1);
        g_src[p0] = s4.x;
        g_src[p1] = s4.y;
        g_src[p2] = s4.z;
        g_src[p3] = s4.w;
    } else {
#pragma unroll
        for (int u = 0; u < 4; u++) {
            int n = i + u - EE;
            int pos = atomicAdd(&g_cur[n], 1);
            g_src[pos] = n;
        }
    }
}

// ---------------- GEMM1 (tf32 tensor-core) + fused logits1 ------------------
__global__ __launch_bounds__(128) void k_gemm1(const float* __restrict__ x,
                                               const float* __restrict__ W1,
                                               const float* __restrict__ as1,
                                               const float* __restrict__ ad1) {
    __shared__ unsigned As[64 * 68];
    __shared__ unsigned Bs[64 * 68];
    __shared__ __half   Cs[64 * 72];
    __shared__ float    sA[64], sD[64];

    int tid = threadIdx.x;
    int lane = tid & 31, w = tid >> 5;
    int n0 = blockIdx.x * 64;
    int hb = blockIdx.y;
    if (tid < 64) {
        sA[tid] = as1[hb * 64 + tid];
        sD[tid] = ad1[hb * 64 + tid];
    }

    float c[8][4];
#pragma unroll
    for (int j = 0; j < 8; j++)
#pragma unroll
        for (int q = 0; q < 4; q++) c[j][q] = 0.f;

    int m0 = w * 16;
    int r4 = lane >> 2, c4 = lane & 3;

    for (int kk = 0; kk < 128; kk += 64) {
        __syncthreads();
#pragma unroll
        for (int i = 0; i < 8; i++) {
            int q = tid + i * 128;
            int row = q >> 4, cq = (q & 15) * 4;
            int gn = n0 + row;
            float4 v = make_float4(0,0,0,0);
            if (gn < NN) v = *(const float4*)(x + (size_t)gn * 128 + kk + cq);
            unsigned* ap = &As[row * 68 + cq];
            ap[0] = f2tf32(v.x); ap[1] = f2tf32(v.y);
            ap[2] = f2tf32(v.z); ap[3] = f2tf32(v.w);
        }
#pragma unroll
        for (int i = 0; i < 8; i++) {
            int q = tid + i * 128;
            int row = q >> 4, cq = (q & 15) * 4;
            float4 v = *(const float4*)(W1 + (size_t)(kk + row) * 256 + hb * 64 + cq);
            unsigned* bp = &Bs[row * 68 + cq];
            bp[0] = f2tf32(v.x); bp[1] = f2tf32(v.y);
            bp[2] = f2tf32(v.z); bp[3] = f2tf32(v.w);
        }
        __syncthreads();

#pragma unroll
        for (int ks = 0; ks < 8; ks++) {
            int k0 = ks * 8;
            unsigned a0 = As[(m0 + r4) * 68 + k0 + c4];
            unsigned a1 = As[(m0 + r4 + 8) * 68 + k0 + c4];
            unsigned a2 = As[(m0 + r4) * 68 + k0 + c4 + 4];
            unsigned a3 = As[(m0 + r4 + 8) * 68 + k0 + c4 + 4];
#pragma unroll
            for (int j = 0; j < 8; j++) {
                unsigned b0 = Bs[(k0 + c4) * 68 + j * 8 + r4];
                unsigned b1 = Bs[(k0 + c4 + 4) * 68 + j * 8 + r4];
                mma_tf32(c[j][0], c[j][1], c[j][2], c[j][3], a0, a1, a2, a3, b0, b1);
            }
        }
    }

    __syncthreads();
#pragma unroll
    for (int j = 0; j < 8; j++) {
        int col = j * 8 + 2 * c4;
        *(__half2*)&Cs[(m0 + r4) * 72 + col]     = __floats2half2_rn(c[j][0], c[j][1]);
        *(__half2*)&Cs[(m0 + r4 + 8) * 72 + col] = __floats2half2_rn(c[j][2], c[j][3]);
    }
    __syncthreads();

#pragma unroll
    for (int i = 0; i < 4; i++) {
        int q = tid + i * 128;
        int row = q >> 3, cq = (q & 7) * 8;
        int gn = n0 + row;
        if (gn < NN)
            *(uint4*)(g_xl1h + (size_t)gn * 256 + hb * 64 + cq) =
                *(uint4*)&Cs[row * 72 + cq];
    }

    {
        int row = tid >> 1;
        int cbase = (tid & 1) * 32;
        float s = 0.f, d = 0.f;
#pragma unroll
        for (int cc = 0; cc < 32; cc++) {
            float v = __half2float(Cs[row * 72 + cbase + cc]);
            s += v * sA[cbase + cc];
            d += v * sD[cbase + cc];
        }
        s += __shfl_xor_sync(0xffffffffu, s, 1);
        d += __shfl_xor_sync(0xffffffffu, d, 1);
        int gn = n0 + row;
        if ((tid & 1) == 0 && gn < NN) {
            g_ls1[gn * 4 + hb] = s;
            g_ld1[gn * 4 + hb] = d;
        }
    }
}

// ------- aggregation layer1 (CSR; warp/dst; fp16 gather; unroll 4) ----------
__global__ __launch_bounds__(256) void k_agg1(const float* __restrict__ b1) {
    int wid = threadIdx.x >> 5, lane = threadIdx.x & 31;
    int dst = blockIdx.x * 8 + wid;
    if (dst >= NN) return;
    int beg = g_off[dst], end = g_off[dst + 1];
    int hh = lane >> 3;
    float ldv = g_ld1[dst * 4 + hh];
    float2 a0 = make_float2(0,0), a1 = make_float2(0,0);
    float2 a2 = make_float2(0,0), a3 = make_float2(0,0);
    float den = 0.f;
    int j = beg;
    for (; j + 4 <= end; j += 4) {
        int s[4];
#pragma unroll
        for (int u = 0; u < 4; u++) s[u] = __ldg(&g_src[j + u]);
        float wv[4];
#pragma unroll
        for (int u = 0; u < 4; u++) wv[u] = __expf(lrelu(__ldg(&g_ls1[s[u] * 4 + hh]) + ldv));
        uint4 hv[4];
#pragma unroll
        for (int u = 0; u < 4; u++) hv[u] = __ldg((const uint4*)(g_xl1h + (size_t)s[u] * 256 + lane * 8));
#pragma unroll
        for (int u = 0; u < 4; u++) {
            float wu = wv[u];
            den += wu;
            float2 v;
            v = __half22float2(*(__half2*)&hv[u].x); a0.x += wu * v.x; a0.y += wu * v.y;
            v = __half22float2(*(__half2*)&hv[u].y); a1.x += wu * v.x; a1.y += wu * v.y;
            v = __half22float2(*(__half2*)&hv[u].z); a2.x += wu * v.x; a2.y += wu * v.y;
            v = __half22float2(*(__half2*)&hv[u].w); a3.x += wu * v.x; a3.y += wu * v.y;
        }
    }
    for (; j < end; j++) {
        int s0 = __ldg(&g_src[j]);
        float w0 = __expf(lrelu(__ldg(&g_ls1[s0 * 4 + hh]) + ldv));
        uint4 hv0 = __ldg((const uint4*)(g_xl1h + (size_t)s0 * 256 + lane * 8));
        den += w0;
        float2 v;
        v = __half22float2(*(__half2*)&hv0.x); a0.x += w0 * v.x; a0.y += w0 * v.y;
        v = __half22float2(*(__half2*)&hv0.y); a1.x += w0 * v.x; a1.y += w0 * v.y;
        v = __half22float2(*(__half2*)&hv0.z); a2.x += w0 * v.x; a2.y += w0 * v.y;
        v = __half22float2(*(__half2*)&hv0.w); a3.x += w0 * v.x; a3.y += w0 * v.y;
    }
    float inv = 1.f / den;
    float4 bb0 = *(const float4*)(b1 + lane * 8);
    float4 bb1 = *(const float4*)(b1 + lane * 8 + 4);
    float o0 = fmaxf(a0.x * inv + bb0.x, 0.f);
    float o1 = fmaxf(a0.y * inv + bb0.y, 0.f);
    float o2 = fmaxf(a1.x * inv + bb0.z, 0.f);
    float o3 = fmaxf(a1.y * inv + bb0.w, 0.f);
    float o4 = fmaxf(a2.x * inv + bb1.x, 0.f);
    float o5 = fmaxf(a2.y * inv + bb1.y, 0.f);
    float o6 = fmaxf(a3.x * inv + bb1.z, 0.f);
    float o7 = fmaxf(a3.y * inv + bb1.w, 0.f);
    uint4 st;
    *(__half2*)&st.x = __floats2half2_rn(o0, o1);
    *(__half2*)&st.y = __floats2half2_rn(o2, o3);
    *(__half2*)&st.z = __floats2half2_rn(o4, o5);
    *(__half2*)&st.w = __floats2half2_rn(o6, o7);
    *(uint4*)(g_h1h + (size_t)dst * 256 + lane * 8) = st;
}

// ---------------- GEMM2 (fp16 mma) + fused logits2 --------------------------
__global__ __launch_bounds__(128) void k_gemm2(const float* __restrict__ W2,
                                               const float* __restrict__ as2,
                                               const float* __restrict__ ad2) {
    __shared__ __half As[64 * 136];   // [row][k-chunk 128], pad 136
    __shared__ __half Bs[32 * 266];   // [n][k 256], pad 266 (odd word stride)
    __shared__ __half Cs[64 * 40];    // [row][n 32], pad 40
    __shared__ float  sa[32], sd[32];
    int tid = threadIdx.x;
    int lane = tid & 31, w = tid >> 5;
    int n0 = blockIdx.x * 64;
    if (tid < 32) { sa[tid] = as2[tid]; sd[tid] = ad2[tid]; }
    // load W2 transposed -> Bs[n][k] fp16
#pragma unroll
    for (int i = 0; i < 64; i++) {
        int idx = tid + i * 128;          // 8192 elements
        int k = idx >> 5, n = idx & 31;
        Bs[n * 266 + k] = __float2half_rn(W2[idx]);
    }
    float c[4][4];
#pragma unroll
    for (int j = 0; j < 4; j++)
#pragma unroll
        for (int q = 0; q < 4; q++) c[j][q] = 0.f;
    int r4 = lane >> 2, c4 = lane & 3, m0 = w * 16;

    for (int ch = 0; ch < 2; ch++) {
        __syncthreads();
#pragma unroll
        for (int i = 0; i < 8; i++) {
            int q = tid + i * 128;             // 1024 uint4
            int row = q >> 4, cq = (q & 15) * 8;
            int gn = n0 + row;
            uint4 v = make_uint4(0,0,0,0);
            if (gn < NN) v = *(const uint4*)(g_h1h + (size_t)gn * 256 + ch * 128 + cq);
            *(uint4*)&As[row * 136 + cq] = v;
        }
        __syncthreads();
#pragma unroll
        for (int ks = 0; ks < 8; ks++) {
            int kb = ks * 16;
            unsigned a0 = *(unsigned*)&As[(m0 + r4) * 136 + kb + 2 * c4];
            unsigned a1 = *(unsigned*)&As[(m0 + r4 + 8) * 136 + kb + 2 * c4];
            unsigned a2 = *(unsigned*)&As[(m0 + r4) * 136 + kb + 2 * c4 + 8];
            unsigned a3 = *(unsigned*)&As[(m0 + r4 + 8) * 136 + kb + 2 * c4 + 8];
            int kg = ch * 128 + kb + 2 * c4;
#pragma unroll
            for (int j = 0; j < 4; j++) {
                int n = j * 8 + r4;
                unsigned b0 = *(unsigned*)&Bs[n * 266 + kg];
                unsigned b1 = *(unsigned*)&Bs[n * 266 + kg + 8];
                mma_f16(c[j][0], c[j][1], c[j][2], c[j][3], a0, a1, a2, a3, b0, b1);
            }
        }
    }
    __syncthreads();
#pragma unroll
    for (int j = 0; j < 4; j++) {
        int col = j * 8 + 2 * c4;
        *(__half2*)&Cs[(m0 + r4) * 40 + col]     = __floats2half2_rn(c[j][0], c[j][1]);
        *(__half2*)&Cs[(m0 + r4 + 8) * 40 + col] = __floats2half2_rn(c[j][2], c[j][3]);
    }
    __syncthreads();
    // write xl2h
#pragma unroll
    for (int i = 0; i < 2; i++) {
        int q = tid + i * 128;                 // 256 uint4
        int row = q >> 2, cq = (q & 3) * 8;
        int gn = n0 + row;
        if (gn < NN)
            *(uint4*)(g_xl2h + (size_t)gn * 32 + cq) = *(uint4*)&Cs[row * 40 + cq];
    }
    // logits2
    if (tid < 64) {
        int gn = n0 + tid;
        if (gn < NN) {
            float s = 0.f, d = 0.f;
#pragma unroll
            for (int cc = 0; cc < 32; cc++) {
                float v = __half2float(Cs[tid * 40 + cc]);
                s += v * sa[cc];
                d += v * sd[cc];
            }
            g_ls2[gn] = s;
            g_ld2[gn] = d;
        }
    }
}

// ---------------- aggregation layer2 (CSR; fp16 gather; unroll 4) ----------
__global__ __launch_bounds__(256) void k_agg2(const float* __restrict__ b2) {
    int wid = threadIdx.x >> 5, lane = threadIdx.x & 31;
    int dst = blockIdx.x * 8 + wid;
    if (dst >= NN) return;
    int beg = g_off[dst], end = g_off[dst + 1];
    float ld2d = g_ld2[dst];
    float acc = 0.f, den = 0.f;
    int j = beg;
    for (; j + 4 <= end; j += 4) {
        int s[4];
#pragma unroll
        for (int u = 0; u < 4; u++) s[u] = __ldg(&g_src[j + u]);
        float wv[4], vv[4];
#pragma unroll
        for (int u = 0; u < 4; u++) wv[u] = __expf(lrelu(__ldg(&g_ls2[s[u]]) + ld2d));
#pragma unroll
        for (int u = 0; u < 4; u++) vv[u] = __half2float(__ldg(&g_xl2h[(size_t)s[u] * 32 + lane]));
#pragma unroll
        for (int u = 0; u < 4; u++) { den += wv[u]; acc += wv[u] * vv[u]; }
    }
    for (; j < end; j++) {
        int s0 = __ldg(&g_src[j]);
        float w0 = __expf(lrelu(__ldg(&g_ls2[s0]) + ld2d));
        den += w0;
        acc += w0 * __half2float(__ldg(&g_xl2h[(size_t)s0 * 32 + lane]));
    }
    float h = fmaxf(acc / den + b2[lane], 0.f);
    g_h2h[(size_t)dst * 32 + lane] = __float2half_rn(h);
}

// ---------------- final (fp16 mma): out = h2 @ fc_W + fc_b ------------------
__global__ __launch_bounds__(128) void k_final(const float* __restrict__ fcW,
                                               const float* __restrict__ fcb,
                                               float* __restrict__ out) {
    __shared__ __half As[64 * 40];    // [row][k 32], pad 40
    __shared__ __half Bs[128 * 40];   // [n][k 32], pad 40
    __shared__ float  sb[128];
    int tid = threadIdx.x;
    int lane = tid & 31, w = tid >> 5;
    int n0 = blockIdx.x * 64;
    sb[tid] = fcb[tid];
    // fcW [32][128] -> Bs[n][k] fp16
#pragma unroll
    for (int i = 0; i < 32; i++) {
        int idx = tid + i * 128;           // 4096 elements
        int k = idx >> 7, n = idx & 127;
        Bs[n * 40 + k] = __float2half_rn(fcW[idx]);
    }
    // h2h tile -> As
#pragma unroll
    for (int i = 0; i < 2; i++) {
        int q = tid + i * 128;             // 256 uint4
        int row = q >> 2, cq = (q & 3) * 8;
        int gn = n0 + row;
        uint4 v = make_uint4(0,0,0,0);
        if (gn < NN) v = *(const uint4*)(g_h2h + (size_t)gn * 32 + cq);
        *(uint4*)&As[row * 40 + cq] = v;
    }
    __syncthreads();

    float c[16][4];
#pragma unroll
    for (int j = 0; j < 16; j++)
#pragma unroll
        for (int q = 0; q < 4; q++) c[j][q] = 0.f;
    int r4 = lane >> 2, c4 = lane & 3, m0 = w * 16;

#pragma unroll
    for (int ks = 0; ks < 2; ks++) {
        int kb = ks * 16;
        unsigned a0 = *(unsigned*)&As[(m0 + r4) * 40 + kb + 2 * c4];
        unsigned a1 = *(unsigned*)&As[(m0 + r4 + 8) * 40 + kb + 2 * c4];
        unsigned a2 = *(unsigned*)&As[(m0 + r4) * 40 + kb + 2 * c4 + 8];
        unsigned a3 = *(unsigned*)&As[(m0 + r4 + 8) * 40 + kb + 2 * c4 + 8];
#pragma unroll
        for (int j = 0; j < 16; j++) {
            int n = j * 8 + r4;
            unsigned b0 = *(unsigned*)&Bs[n * 40 + kb + 2 * c4];
            unsigned b1 = *(unsigned*)&Bs[n * 40 + kb + 2 * c4 + 8];
            mma_f16(c[j][0], c[j][1], c[j][2], c[j][3], a0, a1, a2, a3, b0, b1);
        }
    }
    int row0 = n0 + m0 + r4, row1 = row0 + 8;
#pragma unroll
    for (int j = 0; j < 16; j++) {
        int col = j * 8 + 2 * c4;
        float bx = sb[col], by = sb[col + 1];
        if (row0 < NN) {
            float2 v0 = make_float2(c[j][0] + bx, c[j][1] + by);
            *(float2*)(out + (size_t)row0 * 128 + col) = v0;
        }
        if (row1 < NN) {
            float2 v1 = make_float2(c[j][2] + bx, c[j][3] + by);
            *(float2*)(out + (size_t)row1 * 128 + col) = v1;
        }
    }
}

// ---------------- launch ----------------
extern "C" void kernel_launch(void* const* d_in, const int* in_sizes, int n_in,
                              void* d_out, int out_size) {
    const float* x   = (const float*)d_in[0];
    const int*   ei  = (const int*)d_in[1];
    const float* W1  = (const float*)d_in[2];
    const float* as1 = (const float*)d_in[3];
    const float* ad1 = (const float*)d_in[4];
    const float* b1  = (const float*)d_in[5];
    const float* W2  = (const float*)d_in[6];
    const float* as2 = (const float*)d_in[7];
    const float* ad2 = (const float*)d_in[8];
    const float* b2  = (const float*)d_in[9];
    const float* fcW = (const float*)d_in[10];
    const float* fcb = (const float*)d_in[11];
    float* out = (float*)d_out;

    dim3 g1((NN + 63) / 64, 4);

    if (g_ss.ok) {
        // fork: CSR chain on side stream, concurrent with gemm1 on main stream
        cudaEventRecord(g_ss.fork, 0);
        cudaStreamWaitEvent(g_ss.s, g_ss.fork, 0);
        k_hist<<<(EE / 4 + 255) / 256, 256, 0, g_ss.s>>>(ei);
        k_scan_blk<<<NB, 256, 0, g_ss.s>>>();
        k_scan_add<<<NB, 256, 0, g_ss.s>>>();
        k_scatter<<<(ET / 4 + 255) / 256, 256, 0, g_ss.s>>>(ei);
        cudaEventRecord(g_ss.join, g_ss.s);

        k_gemm1<<<g1, 128>>>(x, W1, as1, ad1);
        cudaStreamWaitEvent(0, g_ss.join, 0);
    } else {
        // serial fallback (identical work)
        k_hist<<<(EE / 4 + 255) / 256, 256>>>(ei);
        k_scan_blk<<<NB, 256>>>();
        k_scan_add<<<NB, 256>>>();
        k_scatter<<<(ET / 4 + 255) / 256, 256>>>(ei);
        k_gemm1<<<g1, 128>>>(x, W1, as1, ad1);
    }

    k_agg1<<<(NN + 7) / 8, 256>>>(b1);
    k_gemm2<<<(NN + 63) / 64, 128>>>(W2, as2, ad2);
    k_agg2<<<(NN + 7) / 8, 256>>>(b2);
    k_final<<<(NN + 63) / 64, 128>>>(fcW, fcb, out);
}

// round 9
// speedup vs baseline: 3.3835x; 1.0660x over previous
#include <cuda_runtime.h>
#include <cuda_fp16.h>

// Problem constants
#define NN 50000
#define DD 128
#define EE 800000
#define ET (EE + NN)     // edges + self loops
#define F1 256
#define F2 32
#define NB ((NN + 255) / 256)   // 196 scan blocks

// ---------------- scratch (device globals; no allocations) ----------------
__device__ __half g_xl1h[NN * F1];   // fp16 xl1 for aggregation gather
__device__ __half g_h1h[NN * F1];    // relu(agg1 + b1), fp16 for gemm2
__device__ float  g_ls1[NN * 4];
__device__ float  g_ld1[NN * 4];

__device__ __half g_xl2h[NN * F2];   // fp16 xl2 for agg2 gather
__device__ __half g_h2h[NN * F2];    // relu(agg2 + b2) fp16 (feeds final mma)
__device__ float  g_ls2[NN];
__device__ float  g_ld2[NN];

// CSR structures (g_cnt self-restores to 0; g_total reset in k_hist)
__device__ int  g_cnt[NN];
__device__ int2 g_offdeg[NN];        // (offset, degree) per dst
__device__ int  g_cur[NN];
__device__ int  g_total;
__device__ int  g_src[ET];           // src node per grouped edge

// ---------------- side stream for DAG capture (created once at load) -------
struct SideStream {
    cudaStream_t s = nullptr;
    cudaEvent_t fork = nullptr, join = nullptr;
    bool ok = false;
    SideStream() {
        if (cudaStreamCreateWithFlags(&s, cudaStreamNonBlocking) == cudaSuccess &&
            cudaEventCreateWithFlags(&fork, cudaEventDisableTiming) == cudaSuccess &&
            cudaEventCreateWithFlags(&join, cudaEventDisableTiming) == cudaSuccess)
            ok = true;
    }
};
static SideStream g_ss;

// ---------------- helpers ----------------
__device__ __forceinline__ float lrelu(float e) { return fmaxf(e, 0.2f * e); }

__device__ __forceinline__ unsigned f2tf32(float f) {
    unsigned u;
    asm("cvt.rna.tf32.f32 %0, %1;" : "=r"(u) : "f"(f));
    return u;
}
__device__ __forceinline__ void mma_tf32(float& c0, float& c1, float& c2, float& c3,
                                         unsigned a0, unsigned a1, unsigned a2, unsigned a3,
                                         unsigned b0, unsigned b1) {
    asm volatile("mma.sync.aligned.m16n8k8.row.col.f32.tf32.tf32.f32 "
                 "{%0,%1,%2,%3}, {%4,%5,%6,%7}, {%8,%9}, {%0,%1,%2,%3};"
                 : "+f"(c0), "+f"(c1), "+f"(c2), "+f"(c3)
                 : "r"(a0), "r"(a1), "r"(a2), "r"(a3), "r"(b0), "r"(b1));
}
__device__ __forceinline__ void mma_f16(float& c0, float& c1, float& c2, float& c3,
                                        unsigned a0, unsigned a1, unsigned a2, unsigned a3,
                                        unsigned b0, unsigned b1) {
    asm volatile("mma.sync.aligned.m16n8k16.row.col.f32.f16.f16.f32 "
                 "{%0,%1,%2,%3}, {%4,%5,%6,%7}, {%8,%9}, {%0,%1,%2,%3};"
                 : "+f"(c0), "+f"(c1), "+f"(c2), "+f"(c3)
                 : "r"(a0), "r"(a1), "r"(a2), "r"(a3), "r"(b0), "r"(b1));
}

// ---------------- CSR build ----------------
__global__ void k_hist(const int* __restrict__ ei) {
    int i = blockIdx.x * blockDim.x + threadIdx.x;
    if (i == 0) g_total = 0;              // reset scan base counter
    if (i * 4 >= EE) return;
    int4 d4 = *(const int4*)(ei + EE + i * 4);
    atomicAdd(&g_cnt[d4.x], 1);
    atomicAdd(&g_cnt[d4.y], 1);
    atomicAdd(&g_cnt[d4.z], 1);
    atomicAdd(&g_cnt[d4.w], 1);
}

// fused single-pass scan: block base via atomicAdd (offsets are block-grouped,
// NOT node-ordered — consumers only use (off,deg) pairs and g_cur).
__global__ void k_scan() {
    __shared__ int wsum[8];
    __shared__ int sbase;
    int tid = threadIdx.x;
    int t = blockIdx.x * 256 + tid;
    int v = 0;
    if (t < NN) { v = g_cnt[t] + 1; g_cnt[t] = 0; }   // +1 = self loop; restore 0
    int lane = tid & 31, wid = tid >> 5;
    int incl = v;
#pragma unroll
    for (int o = 1; o < 32; o <<= 1) {
        int n = __shfl_up_sync(0xffffffffu, incl, o);
        if (lane >= o) incl += n;
    }
    if (lane == 31) wsum[wid] = incl;
    __syncthreads();
    if (wid == 0) {
        int s = (lane < 8) ? wsum[lane] : 0;
#pragma unroll
        for (int o = 1; o < 8; o <<= 1) {
            int n = __shfl_up_sync(0xffffffffu, s, o);
            if (lane >= o) s += n;
        }
        if (lane < 8) wsum[lane] = s;
        if (lane == 7) sbase = atomicAdd(&g_total, s);  // s = block total
    }
    __syncthreads();
    int base = (wid > 0) ? wsum[wid - 1] : 0;
    if (t < NN) {
        int off = sbase + base + incl - v;
        g_offdeg[t] = make_int2(off, v);
        g_cur[t] = off;
    }
}

// scatter: place edge src at grouped position; 4 edges per thread for MLP
__global__ void k_scatter(const int* __restrict__ ei) {
    int i = (blockIdx.x * blockDim.x + threadIdx.x) * 4;
    if (i >= ET) return;
    if (i < EE) {   // EE divisible by 4 -> quads never straddle the boundary
        int4 s4 = *(const int4*)(ei + i);
        int4 d4 = *(const int4*)(ei + EE + i);
        int p0 = atomicAdd(&g_cur[d4.x], 1);
        int p1 = atomicAdd(&g_cur[d4.y], 1);
        int p2 = atomicAdd(&g_cur[d4.z], 1);
        int p3 = atomicAdd(&g_cur[d4.w], 1);
        g_src[p0] = s4.x;
        g_src[p1] = s4.y;
        g_src[p2] = s4.z;
        g_src[p3] = s4.w;
    } else {
#pragma unroll
        for (int u = 0; u < 4; u++) {
            int n = i + u - EE;
            int pos = atomicAdd(&g_cur[n], 1);
            g_src[pos] = n;
        }
    }
}

// ---------------- GEMM1 (tf32 tensor-core) + fused logits1 ------------------
__global__ __launch_bounds__(128) void k_gemm1(const float* __restrict__ x,
                                               const float* __restrict__ W1,
                                               const float* __restrict__ as1,
                                               const float* __restrict__ ad1) {
    __shared__ unsigned As[64 * 68];
    __shared__ unsigned Bs[64 * 68];
    __shared__ __half   Cs[64 * 72];
    __shared__ float    sA[64], sD[64];

    int tid = threadIdx.x;
    int lane = tid & 31, w = tid >> 5;
    int n0 = blockIdx.x * 64;
    int hb = blockIdx.y;
    if (tid < 64) {
        sA[tid] = as1[hb * 64 + tid];
        sD[tid] = ad1[hb * 64 + tid];
    }

    float c[8][4];
#pragma unroll
    for (int j = 0; j < 8; j++)
#pragma unroll
        for (int q = 0; q < 4; q++) c[j][q] = 0.f;

    int m0 = w * 16;
    int r4 = lane >> 2, c4 = lane & 3;

    for (int kk = 0; kk < 128; kk += 64) {
        __syncthreads();
#pragma unroll
        for (int i = 0; i < 8; i++) {
            int q = tid + i * 128;
            int row = q >> 4, cq = (q & 15) * 4;
            int gn = n0 + row;
            float4 v = make_float4(0,0,0,0);
            if (gn < NN) v = *(const float4*)(x + (size_t)gn * 128 + kk + cq);
            unsigned* ap = &As[row * 68 + cq];
            ap[0] = f2tf32(v.x); ap[1] = f2tf32(v.y);
            ap[2] = f2tf32(v.z); ap[3] = f2tf32(v.w);
        }
#pragma unroll
        for (int i = 0; i < 8; i++) {
            int q = tid + i * 128;
            int row = q >> 4, cq = (q & 15) * 4;
            float4 v = *(const float4*)(W1 + (size_t)(kk + row) * 256 + hb * 64 + cq);
            unsigned* bp = &Bs[row * 68 + cq];
            bp[0] = f2tf32(v.x); bp[1] = f2tf32(v.y);
            bp[2] = f2tf32(v.z); bp[3] = f2tf32(v.w);
        }
        __syncthreads();

#pragma unroll
        for (int ks = 0; ks < 8; ks++) {
            int k0 = ks * 8;
            unsigned a0 = As[(m0 + r4) * 68 + k0 + c4];
            unsigned a1 = As[(m0 + r4 + 8) * 68 + k0 + c4];
            unsigned a2 = As[(m0 + r4) * 68 + k0 + c4 + 4];
            unsigned a3 = As[(m0 + r4 + 8) * 68 + k0 + c4 + 4];
#pragma unroll
            for (int j = 0; j < 8; j++) {
                unsigned b0 = Bs[(k0 + c4) * 68 + j * 8 + r4];
                unsigned b1 = Bs[(k0 + c4 + 4) * 68 + j * 8 + r4];
                mma_tf32(c[j][0], c[j][1], c[j][2], c[j][3], a0, a1, a2, a3, b0, b1);
            }
        }
    }

    __syncthreads();
#pragma unroll
    for (int j = 0; j < 8; j++) {
        int col = j * 8 + 2 * c4;
        *(__half2*)&Cs[(m0 + r4) * 72 + col]     = __floats2half2_rn(c[j][0], c[j][1]);
        *(__half2*)&Cs[(m0 + r4 + 8) * 72 + col] = __floats2half2_rn(c[j][2], c[j][3]);
    }
    __syncthreads();

#pragma unroll
    for (int i = 0; i < 4; i++) {
        int q = tid + i * 128;
        int row = q >> 3, cq = (q & 7) * 8;
        int gn = n0 + row;
        if (gn < NN)
            *(uint4*)(g_xl1h + (size_t)gn * 256 + hb * 64 + cq) =
                *(uint4*)&Cs[row * 72 + cq];
    }

    {
        int row = tid >> 1;
        int cbase = (tid & 1) * 32;
        float s = 0.f, d = 0.f;
#pragma unroll
        for (int cc = 0; cc < 32; cc++) {
            float v = __half2float(Cs[row * 72 + cbase + cc]);
            s += v * sA[cbase + cc];
            d += v * sD[cbase + cc];
        }
        s += __shfl_xor_sync(0xffffffffu, s, 1);
        d += __shfl_xor_sync(0xffffffffu, d, 1);
        int gn = n0 + row;
        if ((tid & 1) == 0 && gn < NN) {
            g_ls1[gn * 4 + hb] = s;
            g_ld1[gn * 4 + hb] = d;
        }
    }
}

// ------- aggregation layer1 (CSR; warp/dst; fp16 gather; unroll 4) ----------
__global__ __launch_bounds__(256) void k_agg1(const float* __restrict__ b1) {
    int wid = threadIdx.x >> 5, lane = threadIdx.x & 31;
    int dst = blockIdx.x * 8 + wid;
    if (dst >= NN) return;
    int2 od = g_offdeg[dst];
    int beg = od.x, end = od.x + od.y;
    int hh = lane >> 3;
    float ldv = g_ld1[dst * 4 + hh];
    float2 a0 = make_float2(0,0), a1 = make_float2(0,0);
    float2 a2 = make_float2(0,0), a3 = make_float2(0,0);
    float den = 0.f;
    int j = beg;
    for (; j + 4 <= end; j += 4) {
        int s[4];
#pragma unroll
        for (int u = 0; u < 4; u++) s[u] = __ldg(&g_src[j + u]);
        float wv[4];
#pragma unroll
        for (int u = 0; u < 4; u++) wv[u] = __expf(lrelu(__ldg(&g_ls1[s[u] * 4 + hh]) + ldv));
        uint4 hv[4];
#pragma unroll
        for (int u = 0; u < 4; u++) hv[u] = __ldg((const uint4*)(g_xl1h + (size_t)s[u] * 256 + lane * 8));
#pragma unroll
        for (int u = 0; u < 4; u++) {
            float wu = wv[u];
            den += wu;
            float2 v;
            v = __half22float2(*(__half2*)&hv[u].x); a0.x += wu * v.x; a0.y += wu * v.y;
            v = __half22float2(*(__half2*)&hv[u].y); a1.x += wu * v.x; a1.y += wu * v.y;
            v = __half22float2(*(__half2*)&hv[u].z); a2.x += wu * v.x; a2.y += wu * v.y;
            v = __half22float2(*(__half2*)&hv[u].w); a3.x += wu * v.x; a3.y += wu * v.y;
        }
    }
    for (; j < end; j++) {
        int s0 = __ldg(&g_src[j]);
        float w0 = __expf(lrelu(__ldg(&g_ls1[s0 * 4 + hh]) + ldv));
        uint4 hv0 = __ldg((const uint4*)(g_xl1h + (size_t)s0 * 256 + lane * 8));
        den += w0;
        float2 v;
        v = __half22float2(*(__half2*)&hv0.x); a0.x += w0 * v.x; a0.y += w0 * v.y;
        v = __half22float2(*(__half2*)&hv0.y); a1.x += w0 * v.x; a1.y += w0 * v.y;
        v = __half22float2(*(__half2*)&hv0.z); a2.x += w0 * v.x; a2.y += w0 * v.y;
        v = __half22float2(*(__half2*)&hv0.w); a3.x += w0 * v.x; a3.y += w0 * v.y;
    }
    float inv = 1.f / den;
    float4 bb0 = *(const float4*)(b1 + lane * 8);
    float4 bb1 = *(const float4*)(b1 + lane * 8 + 4);
    float o0 = fmaxf(a0.x * inv + bb0.x, 0.f);
    float o1 = fmaxf(a0.y * inv + bb0.y, 0.f);
    float o2 = fmaxf(a1.x * inv + bb0.z, 0.f);
    float o3 = fmaxf(a1.y * inv + bb0.w, 0.f);
    float o4 = fmaxf(a2.x * inv + bb1.x, 0.f);
    float o5 = fmaxf(a2.y * inv + bb1.y, 0.f);
    float o6 = fmaxf(a3.x * inv + bb1.z, 0.f);
    float o7 = fmaxf(a3.y * inv + bb1.w, 0.f);
    uint4 st;
    *(__half2*)&st.x = __floats2half2_rn(o0, o1);
    *(__half2*)&st.y = __floats2half2_rn(o2, o3);
    *(__half2*)&st.z = __floats2half2_rn(o4, o5);
    *(__half2*)&st.w = __floats2half2_rn(o6, o7);
    *(uint4*)(g_h1h + (size_t)dst * 256 + lane * 8) = st;
}

// ---------------- GEMM2 (fp16 mma) + fused logits2 --------------------------
__global__ __launch_bounds__(128) void k_gemm2(const float* __restrict__ W2,
                                               const float* __restrict__ as2,
                                               const float* __restrict__ ad2) {
    __shared__ __half As[64 * 136];   // [row][k-chunk 128], pad 136
    __shared__ __half Bs[32 * 266];   // [n][k 256], pad 266 (odd word stride)
    __shared__ __half Cs[64 * 40];    // [row][n 32], pad 40
    __shared__ float  sa[32], sd[32];
    int tid = threadIdx.x;
    int lane = tid & 31, w = tid >> 5;
    int n0 = blockIdx.x * 64;
    if (tid < 32) { sa[tid] = as2[tid]; sd[tid] = ad2[tid]; }
    // load W2 transposed -> Bs[n][k] fp16
#pragma unroll
    for (int i = 0; i < 64; i++) {
        int idx = tid + i * 128;          // 8192 elements
        int k = idx >> 5, n = idx & 31;
        Bs[n * 266 + k] = __float2half_rn(W2[idx]);
    }
    float c[4][4];
#pragma unroll
    for (int j = 0; j < 4; j++)
#pragma unroll
        for (int q = 0; q < 4; q++) c[j][q] = 0.f;
    int r4 = lane >> 2, c4 = lane & 3, m0 = w * 16;

    for (int ch = 0; ch < 2; ch++) {
        __syncthreads();
#pragma unroll
        for (int i = 0; i < 8; i++) {
            int q = tid + i * 128;             // 1024 uint4
            int row = q >> 4, cq = (q & 15) * 8;
            int gn = n0 + row;
            uint4 v = make_uint4(0,0,0,0);
            if (gn < NN) v = *(const uint4*)(g_h1h + (size_t)gn * 256 + ch * 128 + cq);
            *(uint4*)&As[row * 136 + cq] = v;
        }
        __syncthreads();
#pragma unroll
        for (int ks = 0; ks < 8; ks++) {
            int kb = ks * 16;
            unsigned a0 = *(unsigned*)&As[(m0 + r4) * 136 + kb + 2 * c4];
            unsigned a1 = *(unsigned*)&As[(m0 + r4 + 8) * 136 + kb + 2 * c4];
            unsigned a2 = *(unsigned*)&As[(m0 + r4) * 136 + kb + 2 * c4 + 8];
            unsigned a3 = *(unsigned*)&As[(m0 + r4 + 8) * 136 + kb + 2 * c4 + 8];
            int kg = ch * 128 + kb + 2 * c4;
#pragma unroll
            for (int j = 0; j < 4; j++) {
                int n = j * 8 + r4;
                unsigned b0 = *(unsigned*)&Bs[n * 266 + kg];
                unsigned b1 = *(unsigned*)&Bs[n * 266 + kg + 8];
                mma_f16(c[j][0], c[j][1], c[j][2], c[j][3], a0, a1, a2, a3, b0, b1);
            }
        }
    }
    __syncthreads();
#pragma unroll
    for (int j = 0; j < 4; j++) {
        int col = j * 8 + 2 * c4;
        *(__half2*)&Cs[(m0 + r4) * 40 + col]     = __floats2half2_rn(c[j][0], c[j][1]);
        *(__half2*)&Cs[(m0 + r4 + 8) * 40 + col] = __floats2half2_rn(c[j][2], c[j][3]);
    }
    __syncthreads();
    // write xl2h
#pragma unroll
    for (int i = 0; i < 2; i++) {
        int q = tid + i * 128;                 // 256 uint4
        int row = q >> 2, cq = (q & 3) * 8;
        int gn = n0 + row;
        if (gn < NN)
            *(uint4*)(g_xl2h + (size_t)gn * 32 + cq) = *(uint4*)&Cs[row * 40 + cq];
    }
    // logits2
    if (tid < 64) {
        int gn = n0 + tid;
        if (gn < NN) {
            float s = 0.f, d = 0.f;
#pragma unroll
            for (int cc = 0; cc < 32; cc++) {
                float v = __half2float(Cs[tid * 40 + cc]);
                s += v * sa[cc];
                d += v * sd[cc];
            }
            g_ls2[gn] = s;
            g_ld2[gn] = d;
        }
    }
}

// ------- aggregation layer2 (CSR; 2 dst per warp; half2 channels) ----------
__global__ __launch_bounds__(256) void k_agg2(const float* __restrict__ b2) {
    int wid = threadIdx.x >> 5, lane = threadIdx.x & 31;
    int half = lane >> 4, hl = lane & 15;
    int dst = blockIdx.x * 16 + wid * 2 + half;
    if (dst >= NN) return;
    int2 od = g_offdeg[dst];
    int beg = od.x, end = od.x + od.y;
    float ld2d = g_ld2[dst];
    int ch = hl * 2;
    float2 acc = make_float2(0.f, 0.f);
    float den = 0.f;
    int j = beg;
    for (; j + 2 <= end; j += 2) {
        int s0 = __ldg(&g_src[j]);
        int s1 = __ldg(&g_src[j + 1]);
        float w0 = __expf(lrelu(__ldg(&g_ls2[s0]) + ld2d));
        float w1 = __expf(lrelu(__ldg(&g_ls2[s1]) + ld2d));
        float2 v0 = __half22float2(__ldg((const __half2*)(g_xl2h + (size_t)s0 * 32 + ch)));
        float2 v1 = __half22float2(__ldg((const __half2*)(g_xl2h + (size_t)s1 * 32 + ch)));
        den += w0 + w1;
        acc.x += w0 * v0.x + w1 * v1.x;
        acc.y += w0 * v0.y + w1 * v1.y;
    }
    if (j < end) {
        int s0 = __ldg(&g_src[j]);
        float w0 = __expf(lrelu(__ldg(&g_ls2[s0]) + ld2d));
        float2 v0 = __half22float2(__ldg((const __half2*)(g_xl2h + (size_t)s0 * 32 + ch)));
        den += w0;
        acc.x += w0 * v0.x;
        acc.y += w0 * v0.y;
    }
    float inv = 1.f / den;
    float hx = fmaxf(acc.x * inv + b2[ch], 0.f);
    float hy = fmaxf(acc.y * inv + b2[ch + 1], 0.f);
    *(__half2*)(g_h2h + (size_t)dst * 32 + ch) = __floats2half2_rn(hx, hy);
}

// ---------------- final (fp16 mma): out = h2 @ fc_W + fc_b ------------------
__global__ __launch_bounds__(128) void k_final(const float* __restrict__ fcW,
                                               const float* __restrict__ fcb,
                                               float* __restrict__ out) {
    __shared__ __half As[64 * 40];    // [row][k 32], pad 40
    __shared__ __half Bs[128 * 40];   // [n][k 32], pad 40
    __shared__ float  sb[128];
    int tid = threadIdx.x;
    int lane = tid & 31, w = tid >> 5;
    int n0 = blockIdx.x * 64;
    sb[tid] = fcb[tid];
    // fcW [32][128] -> Bs[n][k] fp16
#pragma unroll
    for (int i = 0; i < 32; i++) {
        int idx = tid + i * 128;           // 4096 elements
        int k = idx >> 7, n = idx & 127;
        Bs[n * 40 + k] = __float2half_rn(fcW[idx]);
    }
    // h2h tile -> As
#pragma unroll
    for (int i = 0; i < 2; i++) {
        int q = tid + i * 128;             // 256 uint4
        int row = q >> 2, cq = (q & 3) * 8;
        int gn = n0 + row;
        uint4 v = make_uint4(0,0,0,0);
        if (gn < NN) v = *(const uint4*)(g_h2h + (size_t)gn * 32 + cq);
        *(uint4*)&As[row * 40 + cq] = v;
    }
    __syncthreads();

    float c[16][4];
#pragma unroll
    for (int j = 0; j < 16; j++)
#pragma unroll
        for (int q = 0; q < 4; q++) c[j][q] = 0.f;
    int r4 = lane >> 2, c4 = lane & 3, m0 = w * 16;

#pragma unroll
    for (int ks = 0; ks < 2; ks++) {
        int kb = ks * 16;
        unsigned a0 = *(unsigned*)&As[(m0 + r4) * 40 + kb + 2 * c4];
        unsigned a1 = *(unsigned*)&As[(m0 + r4 + 8) * 40 + kb + 2 * c4];
        unsigned a2 = *(unsigned*)&As[(m0 + r4) * 40 + kb + 2 * c4 + 8];
        unsigned a3 = *(unsigned*)&As[(m0 + r4 + 8) * 40 + kb + 2 * c4 + 8];
#pragma unroll
        for (int j = 0; j < 16; j++) {
            int n = j * 8 + r4;
            unsigned b0 = *(unsigned*)&Bs[n * 40 + kb + 2 * c4];
            unsigned b1 = *(unsigned*)&Bs[n * 40 + kb + 2 * c4 + 8];
            mma_f16(c[j][0], c[j][1], c[j][2], c[j][3], a0, a1, a2, a3, b0, b1);
        }
    }
    int row0 = n0 + m0 + r4, row1 = row0 + 8;
#pragma unroll
    for (int j = 0; j < 16; j++) {
        int col = j * 8 + 2 * c4;
        float bx = sb[col], by = sb[col + 1];
        if (row0 < NN) {
            float2 v0 = make_float2(c[j][0] + bx, c[j][1] + by);
            *(float2*)(out + (size_t)row0 * 128 + col) = v0;
        }
        if (row1 < NN) {
            float2 v1 = make_float2(c[j][2] + bx, c[j][3] + by);
            *(float2*)(out + (size_t)row1 * 128 + col) = v1;
        }
    }
}

// ---------------- launch ----------------
extern "C" void kernel_launch(void* const* d_in, const int* in_sizes, int n_in,
                              void* d_out, int out_size) {
    const float* x   = (const float*)d_in[0];
    const int*   ei  = (const int*)d_in[1];
    const float* W1  = (const float*)d_in[2];
    const float* as1 = (const float*)d_in[3];
    const float* ad1 = (const float*)d_in[4];
    const float* b1  = (const float*)d_in[5];
    const float* W2  = (const float*)d_in[6];
    const float* as2 = (const float*)d_in[7];
    const float* ad2 = (const float*)d_in[8];
    const float* b2  = (const float*)d_in[9];
    const float* fcW = (const float*)d_in[10];
    const float* fcb = (const float*)d_in[11];
    float* out = (float*)d_out;

    dim3 g1((NN + 63) / 64, 4);

    if (g_ss.ok) {
        // fork: CSR chain on side stream, concurrent with gemm1 on main stream
        cudaEventRecord(g_ss.fork, 0);
        cudaStreamWaitEvent(g_ss.s, g_ss.fork, 0);
        k_hist<<<(EE / 4 + 255) / 256, 256, 0, g_ss.s>>>(ei);
        k_scan<<<NB, 256, 0, g_ss.s>>>();
        k_scatter<<<(ET / 4 + 255) / 256, 256, 0, g_ss.s>>>(ei);
        cudaEventRecord(g_ss.join, g_ss.s);

        k_gemm1<<<g1, 128>>>(x, W1, as1, ad1);
        cudaStreamWaitEvent(0, g_ss.join, 0);
    } else {
        // serial fallback (identical work)
        k_hist<<<(EE / 4 + 255) / 256, 256>>>(ei);
        k_scan<<<NB, 256>>>();
        k_scatter<<<(ET / 4 + 255) / 256, 256>>>(ei);
        k_gemm1<<<g1, 128>>>(x, W1, as1, ad1);
    }

    k_agg1<<<(NN + 7) / 8, 256>>>(b1);
    k_gemm2<<<(NN + 63) / 64, 128>>>(W2, as2, ad2);
    k_agg2<<<(NN + 15) / 16, 256>>>(b2);
    k_final<<<(NN + 63) / 64, 128>>>(fcW, fcb, out);
}

// round 10
// speedup vs baseline: 3.8040x; 1.1243x over previous
#include <cuda_runtime.h>
#include <cuda_fp16.h>

// Problem constants
#define NN 50000
#define DD 128
#define EE 800000
#define ET (EE + NN)     // edges + self loops
#define F1 256
#define F2 32
#define NB ((NN + 255) / 256)   // 196 scan blocks

// ---------------- scratch (device globals; no allocations) ----------------
__device__ __half g_xl1h[NN * F1];   // fp16 xl1 for aggregation gather
__device__ __half g_h1h[NN * F1];    // relu(agg1 + b1), fp16 for gemm2
__device__ float  g_ls1[NN * 4];
__device__ float  g_ld1[NN * 4];

__device__ __half g_xl2h[NN * F2];   // fp16 xl2 for agg2 gather
__device__ __half g_h2h[NN * F2];    // relu(agg2 + b2) fp16 (feeds final mma)
__device__ float  g_ls2[NN];
__device__ float  g_ld2[NN];

// CSR structures (g_cnt self-restores to 0; g_total reset in k_hist)
__device__ int  g_cnt[NN];
__device__ int2 g_offdeg[NN];        // (offset, degree) per dst
__device__ int  g_cur[NN];
__device__ int  g_total;
__device__ int  g_src[ET];           // src node per grouped edge

// ---------------- side stream for DAG capture (created once at load) -------
struct SideStream {
    cudaStream_t s = nullptr;
    cudaEvent_t fork = nullptr, join = nullptr;
    bool ok = false;
    SideStream() {
        if (cudaStreamCreateWithFlags(&s, cudaStreamNonBlocking) == cudaSuccess &&
            cudaEventCreateWithFlags(&fork, cudaEventDisableTiming) == cudaSuccess &&
            cudaEventCreateWithFlags(&join, cudaEventDisableTiming) == cudaSuccess)
            ok = true;
    }
};
static SideStream g_ss;

// ---------------- helpers ----------------
__device__ __forceinline__ float lrelu(float e) { return fmaxf(e, 0.2f * e); }

__device__ __forceinline__ void mma_f16(float& c0, float& c1, float& c2, float& c3,
                                        unsigned a0, unsigned a1, unsigned a2, unsigned a3,
                                        unsigned b0, unsigned b1) {
    asm volatile("mma.sync.aligned.m16n8k16.row.col.f32.f16.f16.f32 "
                 "{%0,%1,%2,%3}, {%4,%5,%6,%7}, {%8,%9}, {%0,%1,%2,%3};"
                 : "+f"(c0), "+f"(c1), "+f"(c2), "+f"(c3)
                 : "r"(a0), "r"(a1), "r"(a2), "r"(a3), "r"(b0), "r"(b1));
}

// ---------------- CSR build ----------------
__global__ void k_hist(const int* __restrict__ ei) {
    int i = blockIdx.x * blockDim.x + threadIdx.x;
    if (i == 0) g_total = 0;              // reset scan base counter
    if (i * 4 >= EE) return;
    int4 d4 = *(const int4*)(ei + EE + i * 4);
    atomicAdd(&g_cnt[d4.x], 1);
    atomicAdd(&g_cnt[d4.y], 1);
    atomicAdd(&g_cnt[d4.z], 1);
    atomicAdd(&g_cnt[d4.w], 1);
}

// fused single-pass scan: block base via atomicAdd (offsets are block-grouped,
// NOT node-ordered — consumers only use (off,deg) pairs and g_cur).
__global__ void k_scan() {
    __shared__ int wsum[8];
    __shared__ int sbase;
    int tid = threadIdx.x;
    int t = blockIdx.x * 256 + tid;
    int v = 0;
    if (t < NN) { v = g_cnt[t] + 1; g_cnt[t] = 0; }   // +1 = self loop; restore 0
    int lane = tid & 31, wid = tid >> 5;
    int incl = v;
#pragma unroll
    for (int o = 1; o < 32; o <<= 1) {
        int n = __shfl_up_sync(0xffffffffu, incl, o);
        if (lane >= o) incl += n;
    }
    if (lane == 31) wsum[wid] = incl;
    __syncthreads();
    if (wid == 0) {
        int s = (lane < 8) ? wsum[lane] : 0;
#pragma unroll
        for (int o = 1; o < 8; o <<= 1) {
            int n = __shfl_up_sync(0xffffffffu, s, o);
            if (lane >= o) s += n;
        }
        if (lane < 8) wsum[lane] = s;
        if (lane == 7) sbase = atomicAdd(&g_total, s);  // s = block total
    }
    __syncthreads();
    int base = (wid > 0) ? wsum[wid - 1] : 0;
    if (t < NN) {
        int off = sbase + base + incl - v;
        g_offdeg[t] = make_int2(off, v);
        g_cur[t] = off;
    }
}

// scatter: place edge src at grouped position; 4 edges per thread for MLP
__global__ void k_scatter(const int* __restrict__ ei) {
    int i = (blockIdx.x * blockDim.x + threadIdx.x) * 4;
    if (i >= ET) return;
    if (i < EE) {   // EE divisible by 4 -> quads never straddle the boundary
        int4 s4 = *(const int4*)(ei + i);
        int4 d4 = *(const int4*)(ei + EE + i);
        int p0 = atomicAdd(&g_cur[d4.x], 1);
        int p1 = atomicAdd(&g_cur[d4.y], 1);
        int p2 = atomicAdd(&g_cur[d4.z], 1);
        int p3 = atomicAdd(&g_cur[d4.w], 1);
        g_src[p0] = s4.x;
        g_src[p1] = s4.y;
        g_src[p2] = s4.z;
        g_src[p3] = s4.w;
    } else {
#pragma unroll
        for (int u = 0; u < 4; u++) {
            int n = i + u - EE;
            int pos = atomicAdd(&g_cur[n], 1);
            g_src[pos] = n;
        }
    }
}

// ---------------- GEMM1 (fp16 mma m16n8k16) + fused logits1 -----------------
// Block: 64 nodes x 64 cols (head blockIdx.y), K=128 in one smem residency.
// fp16 == tf32 mantissa width (10 bits) -> same accuracy, half the LDS/mma.
__global__ __launch_bounds__(128) void k_gemm1(const float* __restrict__ x,
                                               const float* __restrict__ W1,
                                               const float* __restrict__ as1,
                                               const float* __restrict__ ad1) {
    __shared__ __half As[64 * 136];   // [m][k=128], pad 136 (conflict-free frags)
    __shared__ __half Bs[64 * 138];   // [n][k=128], pad 138 (odd word stride 69)
    __shared__ __half Cs[64 * 72];    // [m][n] fp16 staging
    __shared__ float  sA[64], sD[64];

    int tid = threadIdx.x;
    int lane = tid & 31, w = tid >> 5;
    int n0 = blockIdx.x * 64;
    int hb = blockIdx.y;
    if (tid < 64) {
        sA[tid] = as1[hb * 64 + tid];
        sD[tid] = ad1[hb * 64 + tid];
    }

    // load x tile -> As fp16: 2048 float4 over 128 threads
#pragma unroll
    for (int i = 0; i < 16; i++) {
        int q = tid + i * 128;
        int row = q >> 5, cq = (q & 31) * 4;
        int gn = n0 + row;
        float4 v = make_float4(0,0,0,0);
        if (gn < NN) v = *(const float4*)(x + (size_t)gn * 128 + cq);
        *(__half2*)&As[row * 136 + cq]     = __floats2half2_rn(v.x, v.y);
        *(__half2*)&As[row * 136 + cq + 2] = __floats2half2_rn(v.z, v.w);
    }
    // load W1 slice transposed -> Bs[n][k] fp16: 2048 float4
#pragma unroll
    for (int i = 0; i < 16; i++) {
        int q = tid + i * 128;
        int k = q >> 4, nq = (q & 15) * 4;
        float4 v = *(const float4*)(W1 + (size_t)k * 256 + hb * 64 + nq);
        Bs[(nq + 0) * 138 + k] = __float2half_rn(v.x);
        Bs[(nq + 1) * 138 + k] = __float2half_rn(v.y);
        Bs[(nq + 2) * 138 + k] = __float2half_rn(v.z);
        Bs[(nq + 3) * 138 + k] = __float2half_rn(v.w);
    }
    __syncthreads();

    float c[8][4];
#pragma unroll
    for (int j = 0; j < 8; j++)
#pragma unroll
        for (int q = 0; q < 4; q++) c[j][q] = 0.f;

    int m0 = w * 16;
    int r4 = lane >> 2, c4 = lane & 3;

#pragma unroll
    for (int ks = 0; ks < 8; ks++) {
        int kb = ks * 16;
        unsigned a0 = *(unsigned*)&As[(m0 + r4) * 136 + kb + 2 * c4];
        unsigned a1 = *(unsigned*)&As[(m0 + r4 + 8) * 136 + kb + 2 * c4];
        unsigned a2 = *(unsigned*)&As[(m0 + r4) * 136 + kb + 2 * c4 + 8];
        unsigned a3 = *(unsigned*)&As[(m0 + r4 + 8) * 136 + kb + 2 * c4 + 8];
#pragma unroll
        for (int j = 0; j < 8; j++) {
            int n = j * 8 + r4;
            unsigned b0 = *(unsigned*)&Bs[n * 138 + kb + 2 * c4];
            unsigned b1 = *(unsigned*)&Bs[n * 138 + kb + 2 * c4 + 8];
            mma_f16(c[j][0], c[j][1], c[j][2], c[j][3], a0, a1, a2, a3, b0, b1);
        }
    }

    __syncthreads();
#pragma unroll
    for (int j = 0; j < 8; j++) {
        int col = j * 8 + 2 * c4;
        *(__half2*)&Cs[(m0 + r4) * 72 + col]     = __floats2half2_rn(c[j][0], c[j][1]);
        *(__half2*)&Cs[(m0 + r4 + 8) * 72 + col] = __floats2half2_rn(c[j][2], c[j][3]);
    }
    __syncthreads();

#pragma unroll
    for (int i = 0; i < 4; i++) {
        int q = tid + i * 128;
        int row = q >> 3, cq = (q & 7) * 8;
        int gn = n0 + row;
        if (gn < NN)
            *(uint4*)(g_xl1h + (size_t)gn * 256 + hb * 64 + cq) =
                *(uint4*)&Cs[row * 72 + cq];
    }

    {
        int row = tid >> 1;
        int cbase = (tid & 1) * 32;
        float s = 0.f, d = 0.f;
#pragma unroll
        for (int cc = 0; cc < 32; cc++) {
            float v = __half2float(Cs[row * 72 + cbase + cc]);
            s += v * sA[cbase + cc];
            d += v * sD[cbase + cc];
        }
        s += __shfl_xor_sync(0xffffffffu, s, 1);
        d += __shfl_xor_sync(0xffffffffu, d, 1);
        int gn = n0 + row;
        if ((tid & 1) == 0 && gn < NN) {
            g_ls1[gn * 4 + hb] = s;
            g_ld1[gn * 4 + hb] = d;
        }
    }
}

// ------- aggregation layer1 (CSR; warp/dst; fp16 gather; unroll 4) ----------
__global__ __launch_bounds__(256) void k_agg1(const float* __restrict__ b1) {
    int wid = threadIdx.x >> 5, lane = threadIdx.x & 31;
    int dst = blockIdx.x * 8 + wid;
    if (dst >= NN) return;
    int2 od = g_offdeg[dst];
    int beg = od.x, end = od.x + od.y;
    int hh = lane >> 3;
    float ldv = g_ld1[dst * 4 + hh];
    float2 a0 = make_float2(0,0), a1 = make_float2(0,0);
    float2 a2 = make_float2(0,0), a3 = make_float2(0,0);
    float den = 0.f;
    int j = beg;
    for (; j + 4 <= end; j += 4) {
        int s[4];
#pragma unroll
        for (int u = 0; u < 4; u++) s[u] = __ldg(&g_src[j + u]);
        float wv[4];
#pragma unroll
        for (int u = 0; u < 4; u++) wv[u] = __expf(lrelu(__ldg(&g_ls1[s[u] * 4 + hh]) + ldv));
        uint4 hv[4];
#pragma unroll
        for (int u = 0; u < 4; u++) hv[u] = __ldg((const uint4*)(g_xl1h + (size_t)s[u] * 256 + lane * 8));
#pragma unroll
        for (int u = 0; u < 4; u++) {
            float wu = wv[u];
            den += wu;
            float2 v;
            v = __half22float2(*(__half2*)&hv[u].x); a0.x += wu * v.x; a0.y += wu * v.y;
            v = __half22float2(*(__half2*)&hv[u].y); a1.x += wu * v.x; a1.y += wu * v.y;
            v = __half22float2(*(__half2*)&hv[u].z); a2.x += wu * v.x; a2.y += wu * v.y;
            v = __half22float2(*(__half2*)&hv[u].w); a3.x += wu * v.x; a3.y += wu * v.y;
        }
    }
    for (; j < end; j++) {
        int s0 = __ldg(&g_src[j]);
        float w0 = __expf(lrelu(__ldg(&g_ls1[s0 * 4 + hh]) + ldv));
        uint4 hv0 = __ldg((const uint4*)(g_xl1h + (size_t)s0 * 256 + lane * 8));
        den += w0;
        float2 v;
        v = __half22float2(*(__half2*)&hv0.x); a0.x += w0 * v.x; a0.y += w0 * v.y;
        v = __half22float2(*(__half2*)&hv0.y); a1.x += w0 * v.x; a1.y += w0 * v.y;
        v = __half22float2(*(__half2*)&hv0.z); a2.x += w0 * v.x; a2.y += w0 * v.y;
        v = __half22float2(*(__half2*)&hv0.w); a3.x += w0 * v.x; a3.y += w0 * v.y;
    }
    float inv = 1.f / den;
    float4 bb0 = *(const float4*)(b1 + lane * 8);
    float4 bb1 = *(const float4*)(b1 + lane * 8 + 4);
    float o0 = fmaxf(a0.x * inv + bb0.x, 0.f);
    float o1 = fmaxf(a0.y * inv + bb0.y, 0.f);
    float o2 = fmaxf(a1.x * inv + bb0.z, 0.f);
    float o3 = fmaxf(a1.y * inv + bb0.w, 0.f);
    float o4 = fmaxf(a2.x * inv + bb1.x, 0.f);
    float o5 = fmaxf(a2.y * inv + bb1.y, 0.f);
    float o6 = fmaxf(a3.x * inv + bb1.z, 0.f);
    float o7 = fmaxf(a3.y * inv + bb1.w, 0.f);
    uint4 st;
    *(__half2*)&st.x = __floats2half2_rn(o0, o1);
    *(__half2*)&st.y = __floats2half2_rn(o2, o3);
    *(__half2*)&st.z = __floats2half2_rn(o4, o5);
    *(__half2*)&st.w = __floats2half2_rn(o6, o7);
    *(uint4*)(g_h1h + (size_t)dst * 256 + lane * 8) = st;
}

// ---------------- GEMM2 (fp16 mma) + fused logits2 --------------------------
__global__ __launch_bounds__(128) void k_gemm2(const float* __restrict__ W2,
                                               const float* __restrict__ as2,
                                               const float* __restrict__ ad2) {
    __shared__ __half As[64 * 136];   // [row][k-chunk 128], pad 136
    __shared__ __half Bs[32 * 266];   // [n][k 256], pad 266 (odd word stride)
    __shared__ __half Cs[64 * 40];    // [row][n 32], pad 40
    __shared__ float  sa[32], sd[32];
    int tid = threadIdx.x;
    int lane = tid & 31, w = tid >> 5;
    int n0 = blockIdx.x * 64;
    if (tid < 32) { sa[tid] = as2[tid]; sd[tid] = ad2[tid]; }
    // load W2 transposed -> Bs[n][k] fp16
#pragma unroll
    for (int i = 0; i < 64; i++) {
        int idx = tid + i * 128;          // 8192 elements
        int k = idx >> 5, n = idx & 31;
        Bs[n * 266 + k] = __float2half_rn(W2[idx]);
    }
    float c[4][4];
#pragma unroll
    for (int j = 0; j < 4; j++)
#pragma unroll
        for (int q = 0; q < 4; q++) c[j][q] = 0.f;
    int r4 = lane >> 2, c4 = lane & 3, m0 = w * 16;

    for (int ch = 0; ch < 2; ch++) {
        __syncthreads();
#pragma unroll
        for (int i = 0; i < 8; i++) {
            int q = tid + i * 128;             // 1024 uint4
            int row = q >> 4, cq = (q & 15) * 8;
            int gn = n0 + row;
            uint4 v = make_uint4(0,0,0,0);
            if (gn < NN) v = *(const uint4*)(g_h1h + (size_t)gn * 256 + ch * 128 + cq);
            *(uint4*)&As[row * 136 + cq] = v;
        }
        __syncthreads();
#pragma unroll
        for (int ks = 0; ks < 8; ks++) {
            int kb = ks * 16;
            unsigned a0 = *(unsigned*)&As[(m0 + r4) * 136 + kb + 2 * c4];
            unsigned a1 = *(unsigned*)&As[(m0 + r4 + 8) * 136 + kb + 2 * c4];
            unsigned a2 = *(unsigned*)&As[(m0 + r4) * 136 + kb + 2 * c4 + 8];
            unsigned a3 = *(unsigned*)&As[(m0 + r4 + 8) * 136 + kb + 2 * c4 + 8];
            int kg = ch * 128 + kb + 2 * c4;
#pragma unroll
            for (int j = 0; j < 4; j++) {
                int n = j * 8 + r4;
                unsigned b0 = *(unsigned*)&Bs[n * 266 + kg];
                unsigned b1 = *(unsigned*)&Bs[n * 266 + kg + 8];
                mma_f16(c[j][0], c[j][1], c[j][2], c[j][3], a0, a1, a2, a3, b0, b1);
            }
        }
    }
    __syncthreads();
#pragma unroll
    for (int j = 0; j < 4; j++) {
        int col = j * 8 + 2 * c4;
        *(__half2*)&Cs[(m0 + r4) * 40 + col]     = __floats2half2_rn(c[j][0], c[j][1]);
        *(__half2*)&Cs[(m0 + r4 + 8) * 40 + col] = __floats2half2_rn(c[j][2], c[j][3]);
    }
    __syncthreads();
    // write xl2h
#pragma unroll
    for (int i = 0; i < 2; i++) {
        int q = tid + i * 128;                 // 256 uint4
        int row = q >> 2, cq = (q & 3) * 8;
        int gn = n0 + row;
        if (gn < NN)
            *(uint4*)(g_xl2h + (size_t)gn * 32 + cq) = *(uint4*)&Cs[row * 40 + cq];
    }
    // logits2
    if (tid < 64) {
        int gn = n0 + tid;
        if (gn < NN) {
            float s = 0.f, d = 0.f;
#pragma unroll
            for (int cc = 0; cc < 32; cc++) {
                float v = __half2float(Cs[tid * 40 + cc]);
                s += v * sa[cc];
                d += v * sd[cc];
            }
            g_ls2[gn] = s;
            g_ld2[gn] = d;
        }
    }
}

// ------- aggregation layer2 (CSR; 2 dst per warp; half2 channels) ----------
__global__ __launch_bounds__(256) void k_agg2(const float* __restrict__ b2) {
    int wid = threadIdx.x >> 5, lane = threadIdx.x & 31;
    int half = lane >> 4, hl = lane & 15;
    int dst = blockIdx.x * 16 + wid * 2 + half;
    if (dst >= NN) return;
    int2 od = g_offdeg[dst];
    int beg = od.x, end = od.x + od.y;
    float ld2d = g_ld2[dst];
    int ch = hl * 2;
    float2 acc = make_float2(0.f, 0.f);
    float den = 0.f;
    int j = beg;
    for (; j + 2 <= end; j += 2) {
        int s0 = __ldg(&g_src[j]);
        int s1 = __ldg(&g_src[j + 1]);
        float w0 = __expf(lrelu(__ldg(&g_ls2[s0]) + ld2d));
        float w1 = __expf(lrelu(__ldg(&g_ls2[s1]) + ld2d));
        float2 v0 = __half22float2(__ldg((const __half2*)(g_xl2h + (size_t)s0 * 32 + ch)));
        float2 v1 = __half22float2(__ldg((const __half2*)(g_xl2h + (size_t)s1 * 32 + ch)));
        den += w0 + w1;
        acc.x += w0 * v0.x + w1 * v1.x;
        acc.y += w0 * v0.y + w1 * v1.y;
    }
    if (j < end) {
        int s0 = __ldg(&g_src[j]);
        float w0 = __expf(lrelu(__ldg(&g_ls2[s0]) + ld2d));
        float2 v0 = __half22float2(__ldg((const __half2*)(g_xl2h + (size_t)s0 * 32 + ch)));
        den += w0;
        acc.x += w0 * v0.x;
        acc.y += w0 * v0.y;
    }
    float inv = 1.f / den;
    float hx = fmaxf(acc.x * inv + b2[ch], 0.f);
    float hy = fmaxf(acc.y * inv + b2[ch + 1], 0.f);
    *(__half2*)(g_h2h + (size_t)dst * 32 + ch) = __floats2half2_rn(hx, hy);
}

// ---------------- final (fp16 mma): out = h2 @ fc_W + fc_b ------------------
__global__ __launch_bounds__(128) void k_final(const float* __restrict__ fcW,
                                               const float* __restrict__ fcb,
                                               float* __restrict__ out) {
    __shared__ __half As[64 * 40];    // [row][k 32], pad 40
    __shared__ __half Bs[128 * 40];   // [n][k 32], pad 40
    __shared__ float  sb[128];
    int tid = threadIdx.x;
    int lane = tid & 31, w = tid >> 5;
    int n0 = blockIdx.x * 64;
    sb[tid] = fcb[tid];
    // fcW [32][128] -> Bs[n][k] fp16
#pragma unroll
    for (int i = 0; i < 32; i++) {
        int idx = tid + i * 128;           // 4096 elements
        int k = idx >> 7, n = idx & 127;
        Bs[n * 40 + k] = __float2half_rn(fcW[idx]);
    }
    // h2h tile -> As
#pragma unroll
    for (int i = 0; i < 2; i++) {
        int q = tid + i * 128;             // 256 uint4
        int row = q >> 2, cq = (q & 3) * 8;
        int gn = n0 + row;
        uint4 v = make_uint4(0,0,0,0);
        if (gn < NN) v = *(const uint4*)(g_h2h + (size_t)gn * 32 + cq);
        *(uint4*)&As[row * 40 + cq] = v;
    }
    __syncthreads();

    float c[16][4];
#pragma unroll
    for (int j = 0; j < 16; j++)
#pragma unroll
        for (int q = 0; q < 4; q++) c[j][q] = 0.f;
    int r4 = lane >> 2, c4 = lane & 3, m0 = w * 16;

#pragma unroll
    for (int ks = 0; ks < 2; ks++) {
        int kb = ks * 16;
        unsigned a0 = *(unsigned*)&As[(m0 + r4) * 40 + kb + 2 * c4];
        unsigned a1 = *(unsigned*)&As[(m0 + r4 + 8) * 40 + kb + 2 * c4];
        unsigned a2 = *(unsigned*)&As[(m0 + r4) * 40 + kb + 2 * c4 + 8];
        unsigned a3 = *(unsigned*)&As[(m0 + r4 + 8) * 40 + kb + 2 * c4 + 8];
#pragma unroll
        for (int j = 0; j < 16; j++) {
            int n = j * 8 + r4;
            unsigned b0 = *(unsigned*)&Bs[n * 40 + kb + 2 * c4];
            unsigned b1 = *(unsigned*)&Bs[n * 40 + kb + 2 * c4 + 8];
            mma_f16(c[j][0], c[j][1], c[j][2], c[j][3], a0, a1, a2, a3, b0, b1);
        }
    }
    int row0 = n0 + m0 + r4, row1 = row0 + 8;
#pragma unroll
    for (int j = 0; j < 16; j++) {
        int col = j * 8 + 2 * c4;
        float bx = sb[col], by = sb[col + 1];
        if (row0 < NN) {
            float2 v0 = make_float2(c[j][0] + bx, c[j][1] + by);
            *(float2*)(out + (size_t)row0 * 128 + col) = v0;
        }
        if (row1 < NN) {
            float2 v1 = make_float2(c[j][2] + bx, c[j][3] + by);
            *(float2*)(out + (size_t)row1 * 128 + col) = v1;
        }
    }
}

// ---------------- launch ----------------
extern "C" void kernel_launch(void* const* d_in, const int* in_sizes, int n_in,
                              void* d_out, int out_size) {
    const float* x   = (const float*)d_in[0];
    const int*   ei  = (const int*)d_in[1];
    const float* W1  = (const float*)d_in[2];
    const float* as1 = (const float*)d_in[3];
    const float* ad1 = (const float*)d_in[4];
    const float* b1  = (const float*)d_in[5];
    const float* W2  = (const float*)d_in[6];
    const float* as2 = (const float*)d_in[7];
    const float* ad2 = (const float*)d_in[8];
    const float* b2  = (const float*)d_in[9];
    const float* fcW = (const float*)d_in[10];
    const float* fcb = (const float*)d_in[11];
    float* out = (float*)d_out;

    dim3 g1((NN + 63) / 64, 4);

    if (g_ss.ok) {
        // fork: CSR chain on side stream, concurrent with gemm1 on main stream
        cudaEventRecord(g_ss.fork, 0);
        cudaStreamWaitEvent(g_ss.s, g_ss.fork, 0);
        k_hist<<<(EE / 4 + 255) / 256, 256, 0, g_ss.s>>>(ei);
        k_scan<<<NB, 256, 0, g_ss.s>>>();
        k_scatter<<<(ET / 4 + 255) / 256, 256, 0, g_ss.s>>>(ei);
        cudaEventRecord(g_ss.join, g_ss.s);

        k_gemm1<<<g1, 128>>>(x, W1, as1, ad1);
        cudaStreamWaitEvent(0, g_ss.join, 0);
    } else {
        // serial fallback (identical work)
        k_hist<<<(EE / 4 + 255) / 256, 256>>>(ei);
        k_scan<<<NB, 256>>>();
        k_scatter<<<(ET / 4 + 255) / 256, 256>>>(ei);
        k_gemm1<<<g1, 128>>>(x, W1, as1, ad1);
    }

    k_agg1<<<(NN + 7) / 8, 256>>>(b1);
    k_gemm2<<<(NN + 63) / 64, 128>>>(W2, as2, ad2);
    k_agg2<<<(NN + 15) / 16, 256>>>(b2);
    k_final<<<(NN + 63) / 64, 128>>>(fcW, fcb, out);
}

// round 11
// speedup vs baseline: 3.9496x; 1.0383x over previous
#include <cuda_runtime.h>
#include <cuda_fp16.h>

// Problem constants
#define NN 50000
#define DD 128
#define EE 800000
#define ET (EE + NN)     // edges + self loops
#define F1 256
#define F2 32
#define NB ((NN + 255) / 256)   // 196 scan blocks

// ---------------- scratch (device globals; no allocations) ----------------
__device__ __half g_xl1h[NN * F1];   // fp16 xl1 for aggregation gather
__device__ __half g_h1h[NN * F1];    // relu(agg1 + b1), fp16 for gemm2
__device__ float  g_ls1[NN * 4];
__device__ float  g_ld1[NN * 4];

__device__ __half g_xl2h[NN * F2];   // fp16 xl2 for agg2 gather
__device__ __half g_h2h[NN * F2];    // relu(agg2 + b2) fp16 (feeds final mma)
__device__ float  g_ls2[NN];
__device__ float  g_ld2[NN];

// CSR structures (g_cnt self-restores to 0; g_total reset in k_hist)
__device__ int  g_cnt[NN];
__device__ int2 g_offdeg[NN];        // (offset, degree) per dst
__device__ int  g_cur[NN];
__device__ int  g_total;
__device__ int  g_src[ET];           // src node per grouped edge

// ---------------- side stream for DAG capture (created once at load) -------
struct SideStream {
    cudaStream_t s = nullptr;
    cudaEvent_t fork = nullptr, join = nullptr;
    bool ok = false;
    SideStream() {
        if (cudaStreamCreateWithFlags(&s, cudaStreamNonBlocking) == cudaSuccess &&
            cudaEventCreateWithFlags(&fork, cudaEventDisableTiming) == cudaSuccess &&
            cudaEventCreateWithFlags(&join, cudaEventDisableTiming) == cudaSuccess)
            ok = true;
    }
};
static SideStream g_ss;

// ---------------- helpers ----------------
__device__ __forceinline__ float lrelu(float e) { return fmaxf(e, 0.2f * e); }

__device__ __forceinline__ void mma_f16(float& c0, float& c1, float& c2, float& c3,
                                        unsigned a0, unsigned a1, unsigned a2, unsigned a3,
                                        unsigned b0, unsigned b1) {
    asm volatile("mma.sync.aligned.m16n8k16.row.col.f32.f16.f16.f32 "
                 "{%0,%1,%2,%3}, {%4,%5,%6,%7}, {%8,%9}, {%0,%1,%2,%3};"
                 : "+f"(c0), "+f"(c1), "+f"(c2), "+f"(c3)
                 : "r"(a0), "r"(a1), "r"(a2), "r"(a3), "r"(b0), "r"(b1));
}

// ---------------- CSR build ----------------
__global__ void k_hist(const int* __restrict__ ei) {
    int i = blockIdx.x * blockDim.x + threadIdx.x;
    if (i == 0) g_total = 0;              // reset scan base counter
    if (i * 4 >= EE) return;
    int4 d4 = *(const int4*)(ei + EE + i * 4);
    atomicAdd(&g_cnt[d4.x], 1);
    atomicAdd(&g_cnt[d4.y], 1);
    atomicAdd(&g_cnt[d4.z], 1);
    atomicAdd(&g_cnt[d4.w], 1);
}

// fused single-pass scan: block base via atomicAdd (offsets are block-grouped,
// NOT node-ordered — consumers only use (off,deg) pairs and g_cur).
__global__ void k_scan() {
    __shared__ int wsum[8];
    __shared__ int sbase;
    int tid = threadIdx.x;
    int t = blockIdx.x * 256 + tid;
    int v = 0;
    if (t < NN) { v = g_cnt[t] + 1; g_cnt[t] = 0; }   // +1 = self loop; restore 0
    int lane = tid & 31, wid = tid >> 5;
    int incl = v;
#pragma unroll
    for (int o = 1; o < 32; o <<= 1) {
        int n = __shfl_up_sync(0xffffffffu, incl, o);
        if (lane >= o) incl += n;
    }
    if (lane == 31) wsum[wid] = incl;
    __syncthreads();
    if (wid == 0) {
        int s = (lane < 8) ? wsum[lane] : 0;
#pragma unroll
        for (int o = 1; o < 8; o <<= 1) {
            int n = __shfl_up_sync(0xffffffffu, s, o);
            if (lane >= o) s += n;
        }
        if (lane < 8) wsum[lane] = s;
        if (lane == 7) sbase = atomicAdd(&g_total, s);  // s = block total
    }
    __syncthreads();
    int base = (wid > 0) ? wsum[wid - 1] : 0;
    if (t < NN) {
        int off = sbase + base + incl - v;
        g_offdeg[t] = make_int2(off, v);
        g_cur[t] = off;
    }
}

// scatter: place edge src at grouped position; 4 edges per thread for MLP
__global__ void k_scatter(const int* __restrict__ ei) {
    int i = (blockIdx.x * blockDim.x + threadIdx.x) * 4;
    if (i >= ET) return;
    if (i < EE) {   // EE divisible by 4 -> quads never straddle the boundary
        int4 s4 = *(const int4*)(ei + i);
        int4 d4 = *(const int4*)(ei + EE + i);
        int p0 = atomicAdd(&g_cur[d4.x], 1);
        int p1 = atomicAdd(&g_cur[d4.y], 1);
        int p2 = atomicAdd(&g_cur[d4.z], 1);
        int p3 = atomicAdd(&g_cur[d4.w], 1);
        g_src[p0] = s4.x;
        g_src[p1] = s4.y;
        g_src[p2] = s4.z;
        g_src[p3] = s4.w;
    } else {
#pragma unroll
        for (int u = 0; u < 4; u++) {
            int n = i + u - EE;
            int pos = atomicAdd(&g_cur[n], 1);
            g_src[pos] = n;
        }
    }
}

// ---------------- GEMM1 (fp16 mma) + fused logits1; heads looped in-block ---
// Block: 64 nodes; A tile (x -> fp16) loaded ONCE, then loop over 4 heads
// (B tile + mainloop + epilogue each). Logits computed from mma registers.
__global__ __launch_bounds__(128) void k_gemm1(const float* __restrict__ x,
                                               const float* __restrict__ W1,
                                               const float* __restrict__ as1,
                                               const float* __restrict__ ad1) {
    __shared__ __half As[64 * 136];   // [m][k=128], pad 136 (conflict-free frags)
    __shared__ __half Bs[64 * 138];   // [n][k=128], pad 138 (odd word stride 69)
    __shared__ __half Cs[64 * 72];    // [m][n] fp16 staging
    __shared__ float  sA[64], sD[64];

    int tid = threadIdx.x;
    int lane = tid & 31, w = tid >> 5;
    int n0 = blockIdx.x * 64;
    int m0 = w * 16;
    int r4 = lane >> 2, c4 = lane & 3;

    // load x tile -> As fp16 ONCE: 2048 float4 over 128 threads
#pragma unroll
    for (int i = 0; i < 16; i++) {
        int q = tid + i * 128;
        int row = q >> 5, cq = (q & 31) * 4;
        int gn = n0 + row;
        float4 v = make_float4(0,0,0,0);
        if (gn < NN) v = *(const float4*)(x + (size_t)gn * 128 + cq);
        *(__half2*)&As[row * 136 + cq]     = __floats2half2_rn(v.x, v.y);
        *(__half2*)&As[row * 136 + cq + 2] = __floats2half2_rn(v.z, v.w);
    }

    for (int hb = 0; hb < 4; hb++) {
        __syncthreads();   // previous iteration's Bs/Cs/sA reads complete
        if (tid < 64) {
            sA[tid] = as1[hb * 64 + tid];
            sD[tid] = ad1[hb * 64 + tid];
        }
        // load W1 head slice transposed -> Bs[n][k] fp16: 2048 float4
#pragma unroll
        for (int i = 0; i < 16; i++) {
            int q = tid + i * 128;
            int k = q >> 4, nq = (q & 15) * 4;
            float4 v = *(const float4*)(W1 + (size_t)k * 256 + hb * 64 + nq);
            Bs[(nq + 0) * 138 + k] = __float2half_rn(v.x);
            Bs[(nq + 1) * 138 + k] = __float2half_rn(v.y);
            Bs[(nq + 2) * 138 + k] = __float2half_rn(v.z);
            Bs[(nq + 3) * 138 + k] = __float2half_rn(v.w);
        }
        __syncthreads();

        float c[8][4];
#pragma unroll
        for (int j = 0; j < 8; j++)
#pragma unroll
            for (int q = 0; q < 4; q++) c[j][q] = 0.f;

#pragma unroll
        for (int ks = 0; ks < 8; ks++) {
            int kb = ks * 16;
            unsigned a0 = *(unsigned*)&As[(m0 + r4) * 136 + kb + 2 * c4];
            unsigned a1 = *(unsigned*)&As[(m0 + r4 + 8) * 136 + kb + 2 * c4];
            unsigned a2 = *(unsigned*)&As[(m0 + r4) * 136 + kb + 2 * c4 + 8];
            unsigned a3 = *(unsigned*)&As[(m0 + r4 + 8) * 136 + kb + 2 * c4 + 8];
#pragma unroll
            for (int j = 0; j < 8; j++) {
                int n = j * 8 + r4;
                unsigned b0 = *(unsigned*)&Bs[n * 138 + kb + 2 * c4];
                unsigned b1 = *(unsigned*)&Bs[n * 138 + kb + 2 * c4 + 8];
                mma_f16(c[j][0], c[j][1], c[j][2], c[j][3], a0, a1, a2, a3, b0, b1);
            }
        }

        // logits straight from registers: quad-reduce over c4 (lanes 4q+c4)
        {
            float s0 = 0.f, d0 = 0.f, s1 = 0.f, d1 = 0.f;
#pragma unroll
            for (int j = 0; j < 8; j++) {
                int col = j * 8 + 2 * c4;
                float2 av = *(const float2*)&sA[col];
                float2 dv = *(const float2*)&sD[col];
                s0 += c[j][0] * av.x + c[j][1] * av.y;
                d0 += c[j][0] * dv.x + c[j][1] * dv.y;
                s1 += c[j][2] * av.x + c[j][3] * av.y;
                d1 += c[j][2] * dv.x + c[j][3] * dv.y;
            }
#pragma unroll
            for (int o = 1; o < 4; o <<= 1) {
                s0 += __shfl_xor_sync(0xffffffffu, s0, o);
                d0 += __shfl_xor_sync(0xffffffffu, d0, o);
                s1 += __shfl_xor_sync(0xffffffffu, s1, o);
                d1 += __shfl_xor_sync(0xffffffffu, d1, o);
            }
            if (c4 == 0) {
                int gn0 = n0 + m0 + r4, gn1 = gn0 + 8;
                if (gn0 < NN) { g_ls1[gn0 * 4 + hb] = s0; g_ld1[gn0 * 4 + hb] = d0; }
                if (gn1 < NN) { g_ls1[gn1 * 4 + hb] = s1; g_ld1[gn1 * 4 + hb] = d1; }
            }
        }

        // stage C as fp16, then coalesced store of the head slice
#pragma unroll
        for (int j = 0; j < 8; j++) {
            int col = j * 8 + 2 * c4;
            *(__half2*)&Cs[(m0 + r4) * 72 + col]     = __floats2half2_rn(c[j][0], c[j][1]);
            *(__half2*)&Cs[(m0 + r4 + 8) * 72 + col] = __floats2half2_rn(c[j][2], c[j][3]);
        }
        __syncthreads();
#pragma unroll
        for (int i = 0; i < 4; i++) {
            int q = tid + i * 128;
            int row = q >> 3, cq = (q & 7) * 8;
            int gn = n0 + row;
            if (gn < NN)
                *(uint4*)(g_xl1h + (size_t)gn * 256 + hb * 64 + cq) =
                    *(uint4*)&Cs[row * 72 + cq];
        }
    }
}

// ------- aggregation layer1 (CSR; warp/dst; fp16 gather; unroll 4) ----------
__global__ __launch_bounds__(256) void k_agg1(const float* __restrict__ b1) {
    int wid = threadIdx.x >> 5, lane = threadIdx.x & 31;
    int dst = blockIdx.x * 8 + wid;
    if (dst >= NN) return;
    int2 od = g_offdeg[dst];
    int beg = od.x, end = od.x + od.y;
    int hh = lane >> 3;
    float ldv = g_ld1[dst * 4 + hh];
    float2 a0 = make_float2(0,0), a1 = make_float2(0,0);
    float2 a2 = make_float2(0,0), a3 = make_float2(0,0);
    float den = 0.f;
    int j = beg;
    for (; j + 4 <= end; j += 4) {
        int s[4];
#pragma unroll
        for (int u = 0; u < 4; u++) s[u] = __ldg(&g_src[j + u]);
        float wv[4];
#pragma unroll
        for (int u = 0; u < 4; u++) wv[u] = __expf(lrelu(__ldg(&g_ls1[s[u] * 4 + hh]) + ldv));
        uint4 hv[4];
#pragma unroll
        for (int u = 0; u < 4; u++) hv[u] = __ldg((const uint4*)(g_xl1h + (size_t)s[u] * 256 + lane * 8));
#pragma unroll
        for (int u = 0; u < 4; u++) {
            float wu = wv[u];
            den += wu;
            float2 v;
            v = __half22float2(*(__half2*)&hv[u].x); a0.x += wu * v.x; a0.y += wu * v.y;
            v = __half22float2(*(__half2*)&hv[u].y); a1.x += wu * v.x; a1.y += wu * v.y;
            v = __half22float2(*(__half2*)&hv[u].z); a2.x += wu * v.x; a2.y += wu * v.y;
            v = __half22float2(*(__half2*)&hv[u].w); a3.x += wu * v.x; a3.y += wu * v.y;
        }
    }
    for (; j < end; j++) {
        int s0 = __ldg(&g_src[j]);
        float w0 = __expf(lrelu(__ldg(&g_ls1[s0 * 4 + hh]) + ldv));
        uint4 hv0 = __ldg((const uint4*)(g_xl1h + (size_t)s0 * 256 + lane * 8));
        den += w0;
        float2 v;
        v = __half22float2(*(__half2*)&hv0.x); a0.x += w0 * v.x; a0.y += w0 * v.y;
        v = __half22float2(*(__half2*)&hv0.y); a1.x += w0 * v.x; a1.y += w0 * v.y;
        v = __half22float2(*(__half2*)&hv0.z); a2.x += w0 * v.x; a2.y += w0 * v.y;
        v = __half22float2(*(__half2*)&hv0.w); a3.x += w0 * v.x; a3.y += w0 * v.y;
    }
    float inv = 1.f / den;
    float4 bb0 = *(const float4*)(b1 + lane * 8);
    float4 bb1 = *(const float4*)(b1 + lane * 8 + 4);
    float o0 = fmaxf(a0.x * inv + bb0.x, 0.f);
    float o1 = fmaxf(a0.y * inv + bb0.y, 0.f);
    float o2 = fmaxf(a1.x * inv + bb0.z, 0.f);
    float o3 = fmaxf(a1.y * inv + bb0.w, 0.f);
    float o4 = fmaxf(a2.x * inv + bb1.x, 0.f);
    float o5 = fmaxf(a2.y * inv + bb1.y, 0.f);
    float o6 = fmaxf(a3.x * inv + bb1.z, 0.f);
    float o7 = fmaxf(a3.y * inv + bb1.w, 0.f);
    uint4 st;
    *(__half2*)&st.x = __floats2half2_rn(o0, o1);
    *(__half2*)&st.y = __floats2half2_rn(o2, o3);
    *(__half2*)&st.z = __floats2half2_rn(o4, o5);
    *(__half2*)&st.w = __floats2half2_rn(o6, o7);
    *(uint4*)(g_h1h + (size_t)dst * 256 + lane * 8) = st;
}

// ---------------- GEMM2 (fp16 mma) + fused logits2 --------------------------
__global__ __launch_bounds__(128) void k_gemm2(const float* __restrict__ W2,
                                               const float* __restrict__ as2,
                                               const float* __restrict__ ad2) {
    __shared__ __half As[64 * 136];   // [row][k-chunk 128], pad 136
    __shared__ __half Bs[32 * 266];   // [n][k 256], pad 266 (odd word stride)
    __shared__ __half Cs[64 * 40];    // [row][n 32], pad 40
    __shared__ float  sa[32], sd[32];
    int tid = threadIdx.x;
    int lane = tid & 31, w = tid >> 5;
    int n0 = blockIdx.x * 64;
    if (tid < 32) { sa[tid] = as2[tid]; sd[tid] = ad2[tid]; }
    // load W2 transposed -> Bs[n][k] fp16
#pragma unroll
    for (int i = 0; i < 64; i++) {
        int idx = tid + i * 128;          // 8192 elements
        int k = idx >> 5, n = idx & 31;
        Bs[n * 266 + k] = __float2half_rn(W2[idx]);
    }
    float c[4][4];
#pragma unroll
    for (int j = 0; j < 4; j++)
#pragma unroll
        for (int q = 0; q < 4; q++) c[j][q] = 0.f;
    int r4 = lane >> 2, c4 = lane & 3, m0 = w * 16;

    for (int ch = 0; ch < 2; ch++) {
        __syncthreads();
#pragma unroll
        for (int i = 0; i < 8; i++) {
            int q = tid + i * 128;             // 1024 uint4
            int row = q >> 4, cq = (q & 15) * 8;
            int gn = n0 + row;
            uint4 v = make_uint4(0,0,0,0);
            if (gn < NN) v = *(const uint4*)(g_h1h + (size_t)gn * 256 + ch * 128 + cq);
            *(uint4*)&As[row * 136 + cq] = v;
        }
        __syncthreads();
#pragma unroll
        for (int ks = 0; ks < 8; ks++) {
            int kb = ks * 16;
            unsigned a0 = *(unsigned*)&As[(m0 + r4) * 136 + kb + 2 * c4];
            unsigned a1 = *(unsigned*)&As[(m0 + r4 + 8) * 136 + kb + 2 * c4];
            unsigned a2 = *(unsigned*)&As[(m0 + r4) * 136 + kb + 2 * c4 + 8];
            unsigned a3 = *(unsigned*)&As[(m0 + r4 + 8) * 136 + kb + 2 * c4 + 8];
            int kg = ch * 128 + kb + 2 * c4;
#pragma unroll
            for (int j = 0; j < 4; j++) {
                int n = j * 8 + r4;
                unsigned b0 = *(unsigned*)&Bs[n * 266 + kg];
                unsigned b1 = *(unsigned*)&Bs[n * 266 + kg + 8];
                mma_f16(c[j][0], c[j][1], c[j][2], c[j][3], a0, a1, a2, a3, b0, b1);
            }
        }
    }
    __syncthreads();
#pragma unroll
    for (int j = 0; j < 4; j++) {
        int col = j * 8 + 2 * c4;
        *(__half2*)&Cs[(m0 + r4) * 40 + col]     = __floats2half2_rn(c[j][0], c[j][1]);
        *(__half2*)&Cs[(m0 + r4 + 8) * 40 + col] = __floats2half2_rn(c[j][2], c[j][3]);
    }
    __syncthreads();
    // write xl2h
#pragma unroll
    for (int i = 0; i < 2; i++) {
        int q = tid + i * 128;                 // 256 uint4
        int row = q >> 2, cq = (q & 3) * 8;
        int gn = n0 + row;
        if (gn < NN)
            *(uint4*)(g_xl2h + (size_t)gn * 32 + cq) = *(uint4*)&Cs[row * 40 + cq];
    }
    // logits2
    if (tid < 64) {
        int gn = n0 + tid;
        if (gn < NN) {
            float s = 0.f, d = 0.f;
#pragma unroll
            for (int cc = 0; cc < 32; cc++) {
                float v = __half2float(Cs[tid * 40 + cc]);
                s += v * sa[cc];
                d += v * sd[cc];
            }
            g_ls2[gn] = s;
            g_ld2[gn] = d;
        }
    }
}

// ------- aggregation layer2 (CSR; 2 dst per warp; half2 channels) ----------
__global__ __launch_bounds__(256) void k_agg2(const float* __restrict__ b2) {
    int wid = threadIdx.x >> 5, lane = threadIdx.x & 31;
    int half = lane >> 4, hl = lane & 15;
    int dst = blockIdx.x * 16 + wid * 2 + half;
    if (dst >= NN) return;
    int2 od = g_offdeg[dst];
    int beg = od.x, end = od.x + od.y;
    float ld2d = g_ld2[dst];
    int ch = hl * 2;
    float2 acc = make_float2(0.f, 0.f);
    float den = 0.f;
    int j = beg;
    for (; j + 2 <= end; j += 2) {
        int s0 = __ldg(&g_src[j]);
        int s1 = __ldg(&g_src[j + 1]);
        float w0 = __expf(lrelu(__ldg(&g_ls2[s0]) + ld2d));
        float w1 = __expf(lrelu(__ldg(&g_ls2[s1]) + ld2d));
        float2 v0 = __half22float2(__ldg((const __half2*)(g_xl2h + (size_t)s0 * 32 + ch)));
        float2 v1 = __half22float2(__ldg((const __half2*)(g_xl2h + (size_t)s1 * 32 + ch)));
        den += w0 + w1;
        acc.x += w0 * v0.x + w1 * v1.x;
        acc.y += w0 * v0.y + w1 * v1.y;
    }
    if (j < end) {
        int s0 = __ldg(&g_src[j]);
        float w0 = __expf(lrelu(__ldg(&g_ls2[s0]) + ld2d));
        float2 v0 = __half22float2(__ldg((const __half2*)(g_xl2h + (size_t)s0 * 32 + ch)));
        den += w0;
        acc.x += w0 * v0.x;
        acc.y += w0 * v0.y;
    }
    float inv = 1.f / den;
    float hx = fmaxf(acc.x * inv + b2[ch], 0.f);
    float hy = fmaxf(acc.y * inv + b2[ch + 1], 0.f);
    *(__half2*)(g_h2h + (size_t)dst * 32 + ch) = __floats2half2_rn(hx, hy);
}

// ---------------- final (fp16 mma): out = h2 @ fc_W + fc_b ------------------
__global__ __launch_bounds__(128) void k_final(const float* __restrict__ fcW,
                                               const float* __restrict__ fcb,
                                               float* __restrict__ out) {
    __shared__ __half As[64 * 40];    // [row][k 32], pad 40
    __shared__ __half Bs[128 * 40];   // [n][k 32], pad 40
    __shared__ float  sb[128];
    int tid = threadIdx.x;
    int lane = tid & 31, w = tid >> 5;
    int n0 = blockIdx.x * 64;
    sb[tid] = fcb[tid];
    // fcW [32][128] -> Bs[n][k] fp16
#pragma unroll
    for (int i = 0; i < 32; i++) {
        int idx = tid + i * 128;           // 4096 elements
        int k = idx >> 7, n = idx & 127;
        Bs[n * 40 + k] = __float2half_rn(fcW[idx]);
    }
    // h2h tile -> As
#pragma unroll
    for (int i = 0; i < 2; i++) {
        int q = tid + i * 128;             // 256 uint4
        int row = q >> 2, cq = (q & 3) * 8;
        int gn = n0 + row;
        uint4 v = make_uint4(0,0,0,0);
        if (gn < NN) v = *(const uint4*)(g_h2h + (size_t)gn * 32 + cq);
        *(uint4*)&As[row * 40 + cq] = v;
    }
    __syncthreads();

    float c[16][4];
#pragma unroll
    for (int j = 0; j < 16; j++)
#pragma unroll
        for (int q = 0; q < 4; q++) c[j][q] = 0.f;
    int r4 = lane >> 2, c4 = lane & 3, m0 = w * 16;

#pragma unroll
    for (int ks = 0; ks < 2; ks++) {
        int kb = ks * 16;
        unsigned a0 = *(unsigned*)&As[(m0 + r4) * 40 + kb + 2 * c4];
        unsigned a1 = *(unsigned*)&As[(m0 + r4 + 8) * 40 + kb + 2 * c4];
        unsigned a2 = *(unsigned*)&As[(m0 + r4) * 40 + kb + 2 * c4 + 8];
        unsigned a3 = *(unsigned*)&As[(m0 + r4 + 8) * 40 + kb + 2 * c4 + 8];
#pragma unroll
        for (int j = 0; j < 16; j++) {
            int n = j * 8 + r4;
            unsigned b0 = *(unsigned*)&Bs[n * 40 + kb + 2 * c4];
            unsigned b1 = *(unsigned*)&Bs[n * 40 + kb + 2 * c4 + 8];
            mma_f16(c[j][0], c[j][1], c[j][2], c[j][3], a0, a1, a2, a3, b0, b1);
        }
    }
    int row0 = n0 + m0 + r4, row1 = row0 + 8;
#pragma unroll
    for (int j = 0; j < 16; j++) {
        int col = j * 8 + 2 * c4;
        float bx = sb[col], by = sb[col + 1];
        if (row0 < NN) {
            float2 v0 = make_float2(c[j][0] + bx, c[j][1] + by);
            *(float2*)(out + (size_t)row0 * 128 + col) = v0;
        }
        if (row1 < NN) {
            float2 v1 = make_float2(c[j][2] + bx, c[j][3] + by);
            *(float2*)(out + (size_t)row1 * 128 + col) = v1;
        }
    }
}

// ---------------- launch ----------------
extern "C" void kernel_launch(void* const* d_in, const int* in_sizes, int n_in,
                              void* d_out, int out_size) {
    const float* x   = (const float*)d_in[0];
    const int*   ei  = (const int*)d_in[1];
    const float* W1  = (const float*)d_in[2];
    const float* as1 = (const float*)d_in[3];
    const float* ad1 = (const float*)d_in[4];
    const float* b1  = (const float*)d_in[5];
    const float* W2  = (const float*)d_in[6];
    const float* as2 = (const float*)d_in[7];
    const float* ad2 = (const float*)d_in[8];
    const float* b2  = (const float*)d_in[9];
    const float* fcW = (const float*)d_in[10];
    const float* fcb = (const float*)d_in[11];
    float* out = (float*)d_out;

    int g1 = (NN + 63) / 64;

    if (g_ss.ok) {
        // fork: CSR chain on side stream, concurrent with gemm1 on main stream
        cudaEventRecord(g_ss.fork, 0);
        cudaStreamWaitEvent(g_ss.s, g_ss.fork, 0);
        k_hist<<<(EE / 4 + 255) / 256, 256, 0, g_ss.s>>>(ei);
        k_scan<<<NB, 256, 0, g_ss.s>>>();
        k_scatter<<<(ET / 4 + 255) / 256, 256, 0, g_ss.s>>>(ei);
        cudaEventRecord(g_ss.join, g_ss.s);

        k_gemm1<<<g1, 128>>>(x, W1, as1, ad1);
        cudaStreamWaitEvent(0, g_ss.join, 0);
    } else {
        // serial fallback (identical work)
        k_hist<<<(EE / 4 + 255) / 256, 256>>>(ei);
        k_scan<<<NB, 256>>>();
        k_scatter<<<(ET / 4 + 255) / 256, 256>>>(ei);
        k_gemm1<<<g1, 128>>>(x, W1, as1, ad1);
    }

    k_agg1<<<(NN + 7) / 8, 256>>>(b1);
    k_gemm2<<<(NN + 63) / 64, 128>>>(W2, as2, ad2);
    k_agg2<<<(NN + 15) / 16, 256>>>(b2);
    k_final<<<(NN + 63) / 64, 128>>>(fcW, fcb, out);
}

// round 12
// speedup vs baseline: 4.0252x; 1.0192x over previous
#include <cuda_runtime.h>
#include <cuda_fp16.h>

// Problem constants
#define NN 50000
#define DD 128
#define EE 800000
#define ET (EE + NN)     // edges + self loops
#define F1 256
#define F2 32
#define NB ((NN + 255) / 256)   // 196 scan blocks

// ---------------- scratch (device globals; no allocations) ----------------
__device__ __half g_W1h[F1 * DD];    // W1 transposed [n=256][k=128] fp16
__device__ __half g_xl1h[NN * F1];   // fp16 xl1 for aggregation gather
__device__ __half g_h1h[NN * F1];    // relu(agg1 + b1), fp16 for gemm2
__device__ float  g_ls1[NN * 4];
__device__ float  g_ld1[NN * 4];

__device__ __half g_xl2h[NN * F2];   // fp16 xl2 for agg2 gather
__device__ __half g_h2h[NN * F2];    // relu(agg2 + b2) fp16 (feeds final mma)
__device__ float  g_ls2[NN];
__device__ float  g_ld2[NN];

// CSR structures (g_cnt self-restores to 0; g_total reset in k_hist)
__device__ int  g_cnt[NN];
__device__ int2 g_offdeg[NN];        // (offset, degree) per dst
__device__ int  g_cur[NN];
__device__ int  g_total;
__device__ int  g_src[ET];           // src node per grouped edge

// ---------------- side stream for DAG capture (created once at load) -------
struct SideStream {
    cudaStream_t s = nullptr;
    cudaEvent_t fork = nullptr, join = nullptr;
    bool ok = false;
    SideStream() {
        if (cudaStreamCreateWithFlags(&s, cudaStreamNonBlocking) == cudaSuccess &&
            cudaEventCreateWithFlags(&fork, cudaEventDisableTiming) == cudaSuccess &&
            cudaEventCreateWithFlags(&join, cudaEventDisableTiming) == cudaSuccess)
            ok = true;
    }
};
static SideStream g_ss;

// ---------------- helpers ----------------
__device__ __forceinline__ float lrelu(float e) { return fmaxf(e, 0.2f * e); }

__device__ __forceinline__ void mma_f16(float& c0, float& c1, float& c2, float& c3,
                                        unsigned a0, unsigned a1, unsigned a2, unsigned a3,
                                        unsigned b0, unsigned b1) {
    asm volatile("mma.sync.aligned.m16n8k16.row.col.f32.f16.f16.f32 "
                 "{%0,%1,%2,%3}, {%4,%5,%6,%7}, {%8,%9}, {%0,%1,%2,%3};"
                 : "+f"(c0), "+f"(c1), "+f"(c2), "+f"(c3)
                 : "r"(a0), "r"(a1), "r"(a2), "r"(a3), "r"(b0), "r"(b1));
}

// ---------------- weight prep: W1 -> fp16 transposed ------------------------
__global__ void k_prep(const float* __restrict__ W1) {
    int i = blockIdx.x * 256 + threadIdx.x;   // 32768 elements
    int k = i >> 8, n = i & 255;              // coalesced read of W1[k][n]
    g_W1h[n * 128 + k] = __float2half_rn(W1[i]);
}

// ---------------- CSR build ----------------
__global__ void k_hist(const int* __restrict__ ei) {
    int i = blockIdx.x * blockDim.x + threadIdx.x;
    if (i == 0) g_total = 0;              // reset scan base counter
    if (i * 4 >= EE) return;
    int4 d4 = *(const int4*)(ei + EE + i * 4);
    atomicAdd(&g_cnt[d4.x], 1);
    atomicAdd(&g_cnt[d4.y], 1);
    atomicAdd(&g_cnt[d4.z], 1);
    atomicAdd(&g_cnt[d4.w], 1);
}

// fused single-pass scan: block base via atomicAdd (offsets are block-grouped,
// NOT node-ordered — consumers only use (off,deg) pairs and g_cur).
__global__ void k_scan() {
    __shared__ int wsum[8];
    __shared__ int sbase;
    int tid = threadIdx.x;
    int t = blockIdx.x * 256 + tid;
    int v = 0;
    if (t < NN) { v = g_cnt[t] + 1; g_cnt[t] = 0; }   // +1 = self loop; restore 0
    int lane = tid & 31, wid = tid >> 5;
    int incl = v;
#pragma unroll
    for (int o = 1; o < 32; o <<= 1) {
        int n = __shfl_up_sync(0xffffffffu, incl, o);
        if (lane >= o) incl += n;
    }
    if (lane == 31) wsum[wid] = incl;
    __syncthreads();
    if (wid == 0) {
        int s = (lane < 8) ? wsum[lane] : 0;
#pragma unroll
        for (int o = 1; o < 8; o <<= 1) {
            int n = __shfl_up_sync(0xffffffffu, s, o);
            if (lane >= o) s += n;
        }
        if (lane < 8) wsum[lane] = s;
        if (lane == 7) sbase = atomicAdd(&g_total, s);  // s = block total
    }
    __syncthreads();
    int base = (wid > 0) ? wsum[wid - 1] : 0;
    if (t < NN) {
        int off = sbase + base + incl - v;
        g_offdeg[t] = make_int2(off, v);
        g_cur[t] = off;
    }
}

// scatter: place edge src at grouped position; 4 edges per thread for MLP
__global__ void k_scatter(const int* __restrict__ ei) {
    int i = (blockIdx.x * blockDim.x + threadIdx.x) * 4;
    if (i >= ET) return;
    if (i < EE) {   // EE divisible by 4 -> quads never straddle the boundary
        int4 s4 = *(const int4*)(ei + i);
        int4 d4 = *(const int4*)(ei + EE + i);
        int p0 = atomicAdd(&g_cur[d4.x], 1);
        int p1 = atomicAdd(&g_cur[d4.y], 1);
        int p2 = atomicAdd(&g_cur[d4.z], 1);
        int p3 = atomicAdd(&g_cur[d4.w], 1);
        g_src[p0] = s4.x;
        g_src[p1] = s4.y;
        g_src[p2] = s4.z;
        g_src[p3] = s4.w;
    } else {
#pragma unroll
        for (int u = 0; u < 4; u++) {
            int n = i + u - EE;
            int pos = atomicAdd(&g_cur[n], 1);
            g_src[pos] = n;
        }
    }
}

// ---------------- GEMM1 (fp16 mma) + fused logits1; heads looped in-block ---
// A tile (x -> fp16) loaded once; per head: B tile is a straight uint4 copy
// from pre-transposed g_W1h (no convert, no scalar stores).
__global__ __launch_bounds__(128) void k_gemm1(const float* __restrict__ x,
                                               const float* __restrict__ as1,
                                               const float* __restrict__ ad1) {
    __shared__ __half As[64 * 136];   // [m][k=128], pad 136 (conflict-free)
    __shared__ __half Bs[64 * 136];   // [n][k=128], pad 136 (uint4-aligned, CF)
    __shared__ __half Cs[64 * 72];    // [m][n] fp16 staging
    __shared__ float  sA[64], sD[64];

    int tid = threadIdx.x;
    int lane = tid & 31, w = tid >> 5;
    int n0 = blockIdx.x * 64;
    int m0 = w * 16;
    int r4 = lane >> 2, c4 = lane & 3;

    // load x tile -> As fp16 ONCE: 2048 float4 over 128 threads
#pragma unroll
    for (int i = 0; i < 16; i++) {
        int q = tid + i * 128;
        int row = q >> 5, cq = (q & 31) * 4;
        int gn = n0 + row;
        float4 v = make_float4(0,0,0,0);
        if (gn < NN) v = *(const float4*)(x + (size_t)gn * 128 + cq);
        *(__half2*)&As[row * 136 + cq]     = __floats2half2_rn(v.x, v.y);
        *(__half2*)&As[row * 136 + cq + 2] = __floats2half2_rn(v.z, v.w);
    }

    for (int hb = 0; hb < 4; hb++) {
        __syncthreads();   // previous iteration's Bs/Cs/sA reads complete
        if (tid < 64) {
            sA[tid] = as1[hb * 64 + tid];
            sD[tid] = ad1[hb * 64 + tid];
        }
        // B tile: straight uint4 copy from pre-transposed fp16 weights
#pragma unroll
        for (int i = 0; i < 8; i++) {
            int q = tid + i * 128;             // 1024 uint4
            int nq = q >> 4, kq = (q & 15) * 8;
            *(uint4*)&Bs[nq * 136 + kq] =
                *(const uint4*)(g_W1h + (size_t)(hb * 64 + nq) * 128 + kq);
        }
        __syncthreads();

        float c[8][4];
#pragma unroll
        for (int j = 0; j < 8; j++)
#pragma unroll
            for (int q = 0; q < 4; q++) c[j][q] = 0.f;

#pragma unroll
        for (int ks = 0; ks < 8; ks++) {
            int kb = ks * 16;
            unsigned a0 = *(unsigned*)&As[(m0 + r4) * 136 + kb + 2 * c4];
            unsigned a1 = *(unsigned*)&As[(m0 + r4 + 8) * 136 + kb + 2 * c4];
            unsigned a2 = *(unsigned*)&As[(m0 + r4) * 136 + kb + 2 * c4 + 8];
            unsigned a3 = *(unsigned*)&As[(m0 + r4 + 8) * 136 + kb + 2 * c4 + 8];
#pragma unroll
            for (int j = 0; j < 8; j++) {
                int n = j * 8 + r4;
                unsigned b0 = *(unsigned*)&Bs[n * 136 + kb + 2 * c4];
                unsigned b1 = *(unsigned*)&Bs[n * 136 + kb + 2 * c4 + 8];
                mma_f16(c[j][0], c[j][1], c[j][2], c[j][3], a0, a1, a2, a3, b0, b1);
            }
        }

        // logits straight from registers: quad-reduce over c4 (lanes 4q+c4)
        {
            float s0 = 0.f, d0 = 0.f, s1 = 0.f, d1 = 0.f;
#pragma unroll
            for (int j = 0; j < 8; j++) {
                int col = j * 8 + 2 * c4;
                float2 av = *(const float2*)&sA[col];
                float2 dv = *(const float2*)&sD[col];
                s0 += c[j][0] * av.x + c[j][1] * av.y;
                d0 += c[j][0] * dv.x + c[j][1] * dv.y;
                s1 += c[j][2] * av.x + c[j][3] * av.y;
                d1 += c[j][2] * dv.x + c[j][3] * dv.y;
            }
#pragma unroll
            for (int o = 1; o < 4; o <<= 1) {
                s0 += __shfl_xor_sync(0xffffffffu, s0, o);
                d0 += __shfl_xor_sync(0xffffffffu, d0, o);
                s1 += __shfl_xor_sync(0xffffffffu, s1, o);
                d1 += __shfl_xor_sync(0xffffffffu, d1, o);
            }
            if (c4 == 0) {
                int gn0 = n0 + m0 + r4, gn1 = gn0 + 8;
                if (gn0 < NN) { g_ls1[gn0 * 4 + hb] = s0; g_ld1[gn0 * 4 + hb] = d0; }
                if (gn1 < NN) { g_ls1[gn1 * 4 + hb] = s1; g_ld1[gn1 * 4 + hb] = d1; }
            }
        }

        // stage C as fp16, then coalesced store of the head slice
#pragma unroll
        for (int j = 0; j < 8; j++) {
            int col = j * 8 + 2 * c4;
            *(__half2*)&Cs[(m0 + r4) * 72 + col]     = __floats2half2_rn(c[j][0], c[j][1]);
            *(__half2*)&Cs[(m0 + r4 + 8) * 72 + col] = __floats2half2_rn(c[j][2], c[j][3]);
        }
        __syncthreads();
#pragma unroll
        for (int i = 0; i < 4; i++) {
            int q = tid + i * 128;
            int row = q >> 3, cq = (q & 7) * 8;
            int gn = n0 + row;
            if (gn < NN)
                *(uint4*)(g_xl1h + (size_t)gn * 256 + hb * 64 + cq) =
                    *(uint4*)&Cs[row * 72 + cq];
        }
    }
}

// ------- aggregation layer1 (CSR; warp/dst; fp16 gather; unroll 4) ----------
__global__ __launch_bounds__(256) void k_agg1(const float* __restrict__ b1) {
    int wid = threadIdx.x >> 5, lane = threadIdx.x & 31;
    int dst = blockIdx.x * 8 + wid;
    if (dst >= NN) return;
    int2 od = g_offdeg[dst];
    int beg = od.x, end = od.x + od.y;
    int hh = lane >> 3;
    float ldv = g_ld1[dst * 4 + hh];
    float2 a0 = make_float2(0,0), a1 = make_float2(0,0);
    float2 a2 = make_float2(0,0), a3 = make_float2(0,0);
    float den = 0.f;
    int j = beg;
    for (; j + 4 <= end; j += 4) {
        int s[4];
#pragma unroll
        for (int u = 0; u < 4; u++) s[u] = __ldg(&g_src[j + u]);
        float wv[4];
#pragma unroll
        for (int u = 0; u < 4; u++) wv[u] = __expf(lrelu(__ldg(&g_ls1[s[u] * 4 + hh]) + ldv));
        uint4 hv[4];
#pragma unroll
        for (int u = 0; u < 4; u++) hv[u] = __ldg((const uint4*)(g_xl1h + (size_t)s[u] * 256 + lane * 8));
#pragma unroll
        for (int u = 0; u < 4; u++) {
            float wu = wv[u];
            den += wu;
            float2 v;
            v = __half22float2(*(__half2*)&hv[u].x); a0.x += wu * v.x; a0.y += wu * v.y;
            v = __half22float2(*(__half2*)&hv[u].y); a1.x += wu * v.x; a1.y += wu * v.y;
            v = __half22float2(*(__half2*)&hv[u].z); a2.x += wu * v.x; a2.y += wu * v.y;
            v = __half22float2(*(__half2*)&hv[u].w); a3.x += wu * v.x; a3.y += wu * v.y;
        }
    }
    for (; j < end; j++) {
        int s0 = __ldg(&g_src[j]);
        float w0 = __expf(lrelu(__ldg(&g_ls1[s0 * 4 + hh]) + ldv));
        uint4 hv0 = __ldg((const uint4*)(g_xl1h + (size_t)s0 * 256 + lane * 8));
        den += w0;
        float2 v;
        v = __half22float2(*(__half2*)&hv0.x); a0.x += w0 * v.x; a0.y += w0 * v.y;
        v = __half22float2(*(__half2*)&hv0.y); a1.x += w0 * v.x; a1.y += w0 * v.y;
        v = __half22float2(*(__half2*)&hv0.z); a2.x += w0 * v.x; a2.y += w0 * v.y;
        v = __half22float2(*(__half2*)&hv0.w); a3.x += w0 * v.x; a3.y += w0 * v.y;
    }
    float inv = 1.f / den;
    float4 bb0 = *(const float4*)(b1 + lane * 8);
    float4 bb1 = *(const float4*)(b1 + lane * 8 + 4);
    float o0 = fmaxf(a0.x * inv + bb0.x, 0.f);
    float o1 = fmaxf(a0.y * inv + bb0.y, 0.f);
    float o2 = fmaxf(a1.x * inv + bb0.z, 0.f);
    float o3 = fmaxf(a1.y * inv + bb0.w, 0.f);
    float o4 = fmaxf(a2.x * inv + bb1.x, 0.f);
    float o5 = fmaxf(a2.y * inv + bb1.y, 0.f);
    float o6 = fmaxf(a3.x * inv + bb1.z, 0.f);
    float o7 = fmaxf(a3.y * inv + bb1.w, 0.f);
    uint4 st;
    *(__half2*)&st.x = __floats2half2_rn(o0, o1);
    *(__half2*)&st.y = __floats2half2_rn(o2, o3);
    *(__half2*)&st.z = __floats2half2_rn(o4, o5);
    *(__half2*)&st.w = __floats2half2_rn(o6, o7);
    *(uint4*)(g_h1h + (size_t)dst * 256 + lane * 8) = st;
}

// ---------------- GEMM2 (fp16 mma) + fused logits2 --------------------------
__global__ __launch_bounds__(128) void k_gemm2(const float* __restrict__ W2,
                                               const float* __restrict__ as2,
                                               const float* __restrict__ ad2) {
    __shared__ __half As[64 * 136];   // [row][k-chunk 128], pad 136
    __shared__ __half Bs[32 * 266];   // [n][k 256], pad 266 (odd word stride)
    __shared__ __half Cs[64 * 40];    // [row][n 32], pad 40
    __shared__ float  sa[32], sd[32];
    int tid = threadIdx.x;
    int lane = tid & 31, w = tid >> 5;
    int n0 = blockIdx.x * 64;
    if (tid < 32) { sa[tid] = as2[tid]; sd[tid] = ad2[tid]; }
    // load W2 transposed -> Bs[n][k] fp16
#pragma unroll
    for (int i = 0; i < 64; i++) {
        int idx = tid + i * 128;          // 8192 elements
        int k = idx >> 5, n = idx & 31;
        Bs[n * 266 + k] = __float2half_rn(W2[idx]);
    }
    float c[4][4];
#pragma unroll
    for (int j = 0; j < 4; j++)
#pragma unroll
        for (int q = 0; q < 4; q++) c[j][q] = 0.f;
    int r4 = lane >> 2, c4 = lane & 3, m0 = w * 16;

    for (int ch = 0; ch < 2; ch++) {
        __syncthreads();
#pragma unroll
        for (int i = 0; i < 8; i++) {
            int q = tid + i * 128;             // 1024 uint4
            int row = q >> 4, cq = (q & 15) * 8;
            int gn = n0 + row;
            uint4 v = make_uint4(0,0,0,0);
            if (gn < NN) v = *(const uint4*)(g_h1h + (size_t)gn * 256 + ch * 128 + cq);
            *(uint4*)&As[row * 136 + cq] = v;
        }
        __syncthreads();
#pragma unroll
        for (int ks = 0; ks < 8; ks++) {
            int kb = ks * 16;
            unsigned a0 = *(unsigned*)&As[(m0 + r4) * 136 + kb + 2 * c4];
            unsigned a1 = *(unsigned*)&As[(m0 + r4 + 8) * 136 + kb + 2 * c4];
            unsigned a2 = *(unsigned*)&As[(m0 + r4) * 136 + kb + 2 * c4 + 8];
            unsigned a3 = *(unsigned*)&As[(m0 + r4 + 8) * 136 + kb + 2 * c4 + 8];
            int kg = ch * 128 + kb + 2 * c4;
#pragma unroll
            for (int j = 0; j < 4; j++) {
                int n = j * 8 + r4;
                unsigned b0 = *(unsigned*)&Bs[n * 266 + kg];
                unsigned b1 = *(unsigned*)&Bs[n * 266 + kg + 8];
                mma_f16(c[j][0], c[j][1], c[j][2], c[j][3], a0, a1, a2, a3, b0, b1);
            }
        }
    }
    __syncthreads();
#pragma unroll
    for (int j = 0; j < 4; j++) {
        int col = j * 8 + 2 * c4;
        *(__half2*)&Cs[(m0 + r4) * 40 + col]     = __floats2half2_rn(c[j][0], c[j][1]);
        *(__half2*)&Cs[(m0 + r4 + 8) * 40 + col] = __floats2half2_rn(c[j][2], c[j][3]);
    }
    __syncthreads();
    // write xl2h
#pragma unroll
    for (int i = 0; i < 2; i++) {
        int q = tid + i * 128;                 // 256 uint4
        int row = q >> 2, cq = (q & 3) * 8;
        int gn = n0 + row;
        if (gn < NN)
            *(uint4*)(g_xl2h + (size_t)gn * 32 + cq) = *(uint4*)&Cs[row * 40 + cq];
    }
    // logits2
    if (tid < 64) {
        int gn = n0 + tid;
        if (gn < NN) {
            float s = 0.f, d = 0.f;
#pragma unroll
            for (int cc = 0; cc < 32; cc++) {
                float v = __half2float(Cs[tid * 40 + cc]);
                s += v * sa[cc];
                d += v * sd[cc];
            }
            g_ls2[gn] = s;
            g_ld2[gn] = d;
        }
    }
}

// ------- aggregation layer2 (CSR; 2 dst per warp; half2 channels) ----------
__global__ __launch_bounds__(256) void k_agg2(const float* __restrict__ b2) {
    int wid = threadIdx.x >> 5, lane = threadIdx.x & 31;
    int half = lane >> 4, hl = lane & 15;
    int dst = blockIdx.x * 16 + wid * 2 + half;
    if (dst >= NN) return;
    int2 od = g_offdeg[dst];
    int beg = od.x, end = od.x + od.y;
    float ld2d = g_ld2[dst];
    int ch = hl * 2;
    float2 acc = make_float2(0.f, 0.f);
    float den = 0.f;
    int j = beg;
    for (; j + 2 <= end; j += 2) {
        int s0 = __ldg(&g_src[j]);
        int s1 = __ldg(&g_src[j + 1]);
        float w0 = __expf(lrelu(__ldg(&g_ls2[s0]) + ld2d));
        float w1 = __expf(lrelu(__ldg(&g_ls2[s1]) + ld2d));
        float2 v0 = __half22float2(__ldg((const __half2*)(g_xl2h + (size_t)s0 * 32 + ch)));
        float2 v1 = __half22float2(__ldg((const __half2*)(g_xl2h + (size_t)s1 * 32 + ch)));
        den += w0 + w1;
        acc.x += w0 * v0.x + w1 * v1.x;
        acc.y += w0 * v0.y + w1 * v1.y;
    }
    if (j < end) {
        int s0 = __ldg(&g_src[j]);
        float w0 = __expf(lrelu(__ldg(&g_ls2[s0]) + ld2d));
        float2 v0 = __half22float2(__ldg((const __half2*)(g_xl2h + (size_t)s0 * 32 + ch)));
        den += w0;
        acc.x += w0 * v0.x;
        acc.y += w0 * v0.y;
    }
    float inv = 1.f / den;
    float hx = fmaxf(acc.x * inv + b2[ch], 0.f);
    float hy = fmaxf(acc.y * inv + b2[ch + 1], 0.f);
    *(__half2*)(g_h2h + (size_t)dst * 32 + ch) = __floats2half2_rn(hx, hy);
}

// ---------------- final (fp16 mma): out = h2 @ fc_W + fc_b ------------------
__global__ __launch_bounds__(128) void k_final(const float* __restrict__ fcW,
                                               const float* __restrict__ fcb,
                                               float* __restrict__ out) {
    __shared__ __half As[64 * 40];    // [row][k 32], pad 40
    __shared__ __half Bs[128 * 40];   // [n][k 32], pad 40
    __shared__ float  sb[128];
    int tid = threadIdx.x;
    int lane = tid & 31, w = tid >> 5;
    int n0 = blockIdx.x * 64;
    sb[tid] = fcb[tid];
    // fcW [32][128] -> Bs[n][k] fp16
#pragma unroll
    for (int i = 0; i < 32; i++) {
        int idx = tid + i * 128;           // 4096 elements
        int k = idx >> 7, n = idx & 127;
        Bs[n * 40 + k] = __float2half_rn(fcW[idx]);
    }
    // h2h tile -> As
#pragma unroll
    for (int i = 0; i < 2; i++) {
        int q = tid + i * 128;             // 256 uint4
        int row = q >> 2, cq = (q & 3) * 8;
        int gn = n0 + row;
        uint4 v = make_uint4(0,0,0,0);
        if (gn < NN) v = *(const uint4*)(g_h2h + (size_t)gn * 32 + cq);
        *(uint4*)&As[row * 40 + cq] = v;
    }
    __syncthreads();

    float c[16][4];
#pragma unroll
    for (int j = 0; j < 16; j++)
#pragma unroll
        for (int q = 0; q < 4; q++) c[j][q] = 0.f;
    int r4 = lane >> 2, c4 = lane & 3, m0 = w * 16;

#pragma unroll
    for (int ks = 0; ks < 2; ks++) {
        int kb = ks * 16;
        unsigned a0 = *(unsigned*)&As[(m0 + r4) * 40 + kb + 2 * c4];
        unsigned a1 = *(unsigned*)&As[(m0 + r4 + 8) * 40 + kb + 2 * c4];
        unsigned a2 = *(unsigned*)&As[(m0 + r4) * 40 + kb + 2 * c4 + 8];
        unsigned a3 = *(unsigned*)&As[(m0 + r4 + 8) * 40 + kb + 2 * c4 + 8];
#pragma unroll
        for (int j = 0; j < 16; j++) {
            int n = j * 8 + r4;
            unsigned b0 = *(unsigned*)&Bs[n * 40 + kb + 2 * c4];
            unsigned b1 = *(unsigned*)&Bs[n * 40 + kb + 2 * c4 + 8];
            mma_f16(c[j][0], c[j][1], c[j][2], c[j][3], a0, a1, a2, a3, b0, b1);
        }
    }
    int row0 = n0 + m0 + r4, row1 = row0 + 8;
#pragma unroll
    for (int j = 0; j < 16; j++) {
        int col = j * 8 + 2 * c4;
        float bx = sb[col], by = sb[col + 1];
        if (row0 < NN) {
            float2 v0 = make_float2(c[j][0] + bx, c[j][1] + by);
            *(float2*)(out + (size_t)row0 * 128 + col) = v0;
        }
        if (row1 < NN) {
            float2 v1 = make_float2(c[j][2] + bx, c[j][3] + by);
            *(float2*)(out + (size_t)row1 * 128 + col) = v1;
        }
    }
}

// ---------------- launch ----------------
extern "C" void kernel_launch(void* const* d_in, const int* in_sizes, int n_in,
                              void* d_out, int out_size) {
    const float* x   = (const float*)d_in[0];
    const int*   ei  = (const int*)d_in[1];
    const float* W1  = (const float*)d_in[2];
    const float* as1 = (const float*)d_in[3];
    const float* ad1 = (const float*)d_in[4];
    const float* b1  = (const float*)d_in[5];
    const float* W2  = (const float*)d_in[6];
    const float* as2 = (const float*)d_in[7];
    const float* ad2 = (const float*)d_in[8];
    const float* b2  = (const float*)d_in[9];
    const float* fcW = (const float*)d_in[10];
    const float* fcb = (const float*)d_in[11];
    float* out = (float*)d_out;

    int g1 = (NN + 63) / 64;

    if (g_ss.ok) {
        // fork: CSR chain on side stream, concurrent with prep+gemm1 on main
        cudaEventRecord(g_ss.fork, 0);
        cudaStreamWaitEvent(g_ss.s, g_ss.fork, 0);
        k_hist<<<(EE / 4 + 255) / 256, 256, 0, g_ss.s>>>(ei);
        k_scan<<<NB, 256, 0, g_ss.s>>>();
        k_scatter<<<(ET / 4 + 255) / 256, 256, 0, g_ss.s>>>(ei);
        cudaEventRecord(g_ss.join, g_ss.s);

        k_prep<<<128, 256>>>(W1);
        k_gemm1<<<g1, 128>>>(x, as1, ad1);
        cudaStreamWaitEvent(0, g_ss.join, 0);
    } else {
        // serial fallback (identical work)
        k_hist<<<(EE / 4 + 255) / 256, 256>>>(ei);
        k_scan<<<NB, 256>>>();
        k_scatter<<<(ET / 4 + 255) / 256, 256>>>(ei);
        k_prep<<<128, 256>>>(W1);
        k_gemm1<<<g1, 128>>>(x, as1, ad1);
    }

    k_agg1<<<(NN + 7) / 8, 256>>>(b1);
    k_gemm2<<<(NN + 63) / 64, 128>>>(W2, as2, ad2);
    k_agg2<<<(NN + 15) / 16, 256>>>(b2);
    k_final<<<(NN + 63) / 64, 128>>>(fcW, fcb, out);
}

// round 13
// speedup vs baseline: 4.0999x; 1.0186x over previous
#include <cuda_runtime.h>
#include <cuda_fp16.h>

// Problem constants
#define NN 50000
#define DD 128
#define EE 800000
#define ET (EE + NN)     // edges + self loops
#define F1 256
#define F2 32
#define NB ((NN + 255) / 256)   // 196 scan blocks

// ---------------- scratch (device globals; no allocations) ----------------
__device__ __half g_W1h[F1 * DD];    // W1 transposed [n=256][k=128] fp16
__device__ __half g_xl1h[NN * F1];   // fp16 xl1 for aggregation gather
__device__ __half g_h1h[NN * F1];    // relu(agg1 + b1), fp16 for gemm2
__device__ float  g_ls1[NN * 4];
__device__ float  g_ld1[NN * 4];

__device__ __half g_xl2h[NN * F2];   // fp16 xl2 for agg2 gather
__device__ __half g_h2h[NN * F2];    // relu(agg2 + b2) fp16 (feeds final mma)
__device__ float  g_ls2[NN];
__device__ float  g_ld2[NN];

// CSR structures (g_cnt self-restores to 0; g_total reset in k_hist)
__device__ int  g_cnt[NN];
__device__ int2 g_offdeg[NN];        // (offset, degree) per dst
__device__ int  g_cur[NN];
__device__ int  g_total;
__device__ int  g_src[ET];           // src node per grouped edge

// ---------------- side stream for DAG capture (created once at load) -------
struct SideStream {
    cudaStream_t s = nullptr;
    cudaEvent_t fork = nullptr, join = nullptr;
    bool ok = false;
    SideStream() {
        if (cudaStreamCreateWithFlags(&s, cudaStreamNonBlocking) == cudaSuccess &&
            cudaEventCreateWithFlags(&fork, cudaEventDisableTiming) == cudaSuccess &&
            cudaEventCreateWithFlags(&join, cudaEventDisableTiming) == cudaSuccess)
            ok = true;
    }
};
static SideStream g_ss;

// ---------------- helpers ----------------
__device__ __forceinline__ float lrelu(float e) { return fmaxf(e, 0.2f * e); }

__device__ __forceinline__ void mma_f16(float& c0, float& c1, float& c2, float& c3,
                                        unsigned a0, unsigned a1, unsigned a2, unsigned a3,
                                        unsigned b0, unsigned b1) {
    asm volatile("mma.sync.aligned.m16n8k16.row.col.f32.f16.f16.f32 "
                 "{%0,%1,%2,%3}, {%4,%5,%6,%7}, {%8,%9}, {%0,%1,%2,%3};"
                 : "+f"(c0), "+f"(c1), "+f"(c2), "+f"(c3)
                 : "r"(a0), "r"(a1), "r"(a2), "r"(a3), "r"(b0), "r"(b1));
}
__device__ __forceinline__ void ldsm_x4(unsigned& r0, unsigned& r1, unsigned& r2, unsigned& r3,
                                        unsigned addr) {
    asm volatile("ldmatrix.sync.aligned.m8n8.x4.shared.b16 {%0,%1,%2,%3}, [%4];"
                 : "=r"(r0), "=r"(r1), "=r"(r2), "=r"(r3) : "r"(addr));
}

// ---------------- weight prep: W1 -> fp16 transposed ------------------------
__global__ void k_prep(const float* __restrict__ W1) {
    int i = blockIdx.x * 256 + threadIdx.x;   // 32768 elements
    int k = i >> 8, n = i & 255;              // coalesced read of W1[k][n]
    g_W1h[n * 128 + k] = __float2half_rn(W1[i]);
}

// ---------------- CSR build ----------------
__global__ void k_hist(const int* __restrict__ ei) {
    int i = blockIdx.x * blockDim.x + threadIdx.x;
    if (i == 0) g_total = 0;              // reset scan base counter
    if (i * 4 >= EE) return;
    int4 d4 = *(const int4*)(ei + EE + i * 4);
    atomicAdd(&g_cnt[d4.x], 1);
    atomicAdd(&g_cnt[d4.y], 1);
    atomicAdd(&g_cnt[d4.z], 1);
    atomicAdd(&g_cnt[d4.w], 1);
}

// fused single-pass scan: block base via atomicAdd (offsets are block-grouped,
// NOT node-ordered — consumers only use (off,deg) pairs and g_cur).
__global__ void k_scan() {
    __shared__ int wsum[8];
    __shared__ int sbase;
    int tid = threadIdx.x;
    int t = blockIdx.x * 256 + tid;
    int v = 0;
    if (t < NN) { v = g_cnt[t] + 1; g_cnt[t] = 0; }   // +1 = self loop; restore 0
    int lane = tid & 31, wid = tid >> 5;
    int incl = v;
#pragma unroll
    for (int o = 1; o < 32; o <<= 1) {
        int n = __shfl_up_sync(0xffffffffu, incl, o);
        if (lane >= o) incl += n;
    }
    if (lane == 31) wsum[wid] = incl;
    __syncthreads();
    if (wid == 0) {
        int s = (lane < 8) ? wsum[lane] : 0;
#pragma unroll
        for (int o = 1; o < 8; o <<= 1) {
            int n = __shfl_up_sync(0xffffffffu, s, o);
            if (lane >= o) s += n;
        }
        if (lane < 8) wsum[lane] = s;
        if (lane == 7) sbase = atomicAdd(&g_total, s);  // s = block total
    }
    __syncthreads();
    int base = (wid > 0) ? wsum[wid - 1] : 0;
    if (t < NN) {
        int off = sbase + base + incl - v;
        g_offdeg[t] = make_int2(off, v);
        g_cur[t] = off;
    }
}

// scatter: place edge src at grouped position; 4 edges per thread for MLP
__global__ void k_scatter(const int* __restrict__ ei) {
    int i = (blockIdx.x * blockDim.x + threadIdx.x) * 4;
    if (i >= ET) return;
    if (i < EE) {   // EE divisible by 4 -> quads never straddle the boundary
        int4 s4 = *(const int4*)(ei + i);
        int4 d4 = *(const int4*)(ei + EE + i);
        int p0 = atomicAdd(&g_cur[d4.x], 1);
        int p1 = atomicAdd(&g_cur[d4.y], 1);
        int p2 = atomicAdd(&g_cur[d4.z], 1);
        int p3 = atomicAdd(&g_cur[d4.w], 1);
        g_src[p0] = s4.x;
        g_src[p1] = s4.y;
        g_src[p2] = s4.z;
        g_src[p3] = s4.w;
    } else {
#pragma unroll
        for (int u = 0; u < 4; u++) {
            int n = i + u - EE;
            int pos = atomicAdd(&g_cur[n], 1);
            g_src[pos] = n;
        }
    }
}

// ---------------- GEMM1 (fp16 mma + ldmatrix) + fused logits1 ---------------
// A tile (x -> fp16) loaded once; per head: B tile uint4 copy from g_W1h,
// mainloop fragments via ldmatrix.x4 (1 A + 4 B per k-step).
__global__ __launch_bounds__(128) void k_gemm1(const float* __restrict__ x,
                                               const float* __restrict__ as1,
                                               const float* __restrict__ ad1) {
    __shared__ __half As[64 * 136];   // [m][k=128], pad 136
    __shared__ __half Bs[64 * 136];   // [n][k=128], pad 136
    __shared__ __half Cs[64 * 72];    // [m][n] fp16 staging
    __shared__ float  sA[64], sD[64];

    int tid = threadIdx.x;
    int lane = tid & 31, w = tid >> 5;
    int n0 = blockIdx.x * 64;
    int m0 = w * 16;
    int r4 = lane >> 2, c4 = lane & 3;
    int g8 = lane >> 3, r8 = lane & 7;

    // load x tile -> As fp16 ONCE: 2048 float4 over 128 threads
#pragma unroll
    for (int i = 0; i < 16; i++) {
        int q = tid + i * 128;
        int row = q >> 5, cq = (q & 31) * 4;
        int gn = n0 + row;
        float4 v = make_float4(0,0,0,0);
        if (gn < NN) v = *(const float4*)(x + (size_t)gn * 128 + cq);
        *(__half2*)&As[row * 136 + cq]     = __floats2half2_rn(v.x, v.y);
        *(__half2*)&As[row * 136 + cq + 2] = __floats2half2_rn(v.z, v.w);
    }

    // ldmatrix base addresses (lane-dependent, kb added per step)
    unsigned asBase = (unsigned)__cvta_generic_to_shared(As);
    unsigned bsBase = (unsigned)__cvta_generic_to_shared(Bs);
    // A x4: mats = {m0..7/k0..7, m8..15/k0..7, m0..7/k8..15, m8..15/k8..15}
    unsigned aAddr = asBase + (((m0 + r8 + (g8 & 1) * 8) * 136 + (g8 >> 1) * 8) << 1);
    // B x4 (pair p): mats = {n0p..7/k0..7, n0p..7/k8..15, n0p+8../k0..7, n0p+8../k8..15}
    unsigned bAddr0 = bsBase + (((r8 + (g8 >> 1) * 8) * 136 + (g8 & 1) * 8) << 1);

    for (int hb = 0; hb < 4; hb++) {
        __syncthreads();   // previous iteration's Bs/Cs/sA reads complete
        if (tid < 64) {
            sA[tid] = as1[hb * 64 + tid];
            sD[tid] = ad1[hb * 64 + tid];
        }
        // B tile: straight uint4 copy from pre-transposed fp16 weights
#pragma unroll
        for (int i = 0; i < 8; i++) {
            int q = tid + i * 128;             // 1024 uint4
            int nq = q >> 4, kq = (q & 15) * 8;
            *(uint4*)&Bs[nq * 136 + kq] =
                *(const uint4*)(g_W1h + (size_t)(hb * 64 + nq) * 128 + kq);
        }
        __syncthreads();

        float c[8][4];
#pragma unroll
        for (int j = 0; j < 8; j++)
#pragma unroll
            for (int q = 0; q < 4; q++) c[j][q] = 0.f;

#pragma unroll
        for (int ks = 0; ks < 8; ks++) {
            unsigned koff = (unsigned)(ks * 16 * 2);
            unsigned a0, a1, a2, a3;
            ldsm_x4(a0, a1, a2, a3, aAddr + koff);
#pragma unroll
            for (int p = 0; p < 4; p++) {
                unsigned b0, b1, b2, b3;
                ldsm_x4(b0, b1, b2, b3, bAddr0 + (unsigned)(p * 16 * 136 * 2) + koff);
                mma_f16(c[2*p][0],   c[2*p][1],   c[2*p][2],   c[2*p][3],
                        a0, a1, a2, a3, b0, b1);
                mma_f16(c[2*p+1][0], c[2*p+1][1], c[2*p+1][2], c[2*p+1][3],
                        a0, a1, a2, a3, b2, b3);
            }
        }

        // logits straight from registers: quad-reduce over c4 (lanes 4q+c4)
        {
            float s0 = 0.f, d0 = 0.f, s1 = 0.f, d1 = 0.f;
#pragma unroll
            for (int j = 0; j < 8; j++) {
                int col = j * 8 + 2 * c4;
                float2 av = *(const float2*)&sA[col];
                float2 dv = *(const float2*)&sD[col];
                s0 += c[j][0] * av.x + c[j][1] * av.y;
                d0 += c[j][0] * dv.x + c[j][1] * dv.y;
                s1 += c[j][2] * av.x + c[j][3] * av.y;
                d1 += c[j][2] * dv.x + c[j][3] * dv.y;
            }
#pragma unroll
            for (int o = 1; o < 4; o <<= 1) {
                s0 += __shfl_xor_sync(0xffffffffu, s0, o);
                d0 += __shfl_xor_sync(0xffffffffu, d0, o);
                s1 += __shfl_xor_sync(0xffffffffu, s1, o);
                d1 += __shfl_xor_sync(0xffffffffu, d1, o);
            }
            if (c4 == 0) {
                int gn0 = n0 + m0 + r4, gn1 = gn0 + 8;
                if (gn0 < NN) { g_ls1[gn0 * 4 + hb] = s0; g_ld1[gn0 * 4 + hb] = d0; }
                if (gn1 < NN) { g_ls1[gn1 * 4 + hb] = s1; g_ld1[gn1 * 4 + hb] = d1; }
            }
        }

        // stage C as fp16, then coalesced store of the head slice
#pragma unroll
        for (int j = 0; j < 8; j++) {
            int col = j * 8 + 2 * c4;
            *(__half2*)&Cs[(m0 + r4) * 72 + col]     = __floats2half2_rn(c[j][0], c[j][1]);
            *(__half2*)&Cs[(m0 + r4 + 8) * 72 + col] = __floats2half2_rn(c[j][2], c[j][3]);
        }
        __syncthreads();
#pragma unroll
        for (int i = 0; i < 4; i++) {
            int q = tid + i * 128;
            int row = q >> 3, cq = (q & 7) * 8;
            int gn = n0 + row;
            if (gn < NN)
                *(uint4*)(g_xl1h + (size_t)gn * 256 + hb * 64 + cq) =
                    *(uint4*)&Cs[row * 72 + cq];
        }
    }
}

// ------- aggregation layer1 (CSR; warp/dst; fp16 gather; unroll 4) ----------
__global__ __launch_bounds__(256) void k_agg1(const float* __restrict__ b1) {
    int wid = threadIdx.x >> 5, lane = threadIdx.x & 31;
    int dst = blockIdx.x * 8 + wid;
    if (dst >= NN) return;
    int2 od = g_offdeg[dst];
    int beg = od.x, end = od.x + od.y;
    int hh = lane >> 3;
    float ldv = g_ld1[dst * 4 + hh];
    float2 a0 = make_float2(0,0), a1 = make_float2(0,0);
    float2 a2 = make_float2(0,0), a3 = make_float2(0,0);
    float den = 0.f;
    int j = beg;
    for (; j + 4 <= end; j += 4) {
        int s[4];
#pragma unroll
        for (int u = 0; u < 4; u++) s[u] = __ldg(&g_src[j + u]);
        float wv[4];
#pragma unroll
        for (int u = 0; u < 4; u++) wv[u] = __expf(lrelu(__ldg(&g_ls1[s[u] * 4 + hh]) + ldv));
        uint4 hv[4];
#pragma unroll
        for (int u = 0; u < 4; u++) hv[u] = __ldg((const uint4*)(g_xl1h + (size_t)s[u] * 256 + lane * 8));
#pragma unroll
        for (int u = 0; u < 4; u++) {
            float wu = wv[u];
            den += wu;
            float2 v;
            v = __half22float2(*(__half2*)&hv[u].x); a0.x += wu * v.x; a0.y += wu * v.y;
            v = __half22float2(*(__half2*)&hv[u].y); a1.x += wu * v.x; a1.y += wu * v.y;
            v = __half22float2(*(__half2*)&hv[u].z); a2.x += wu * v.x; a2.y += wu * v.y;
            v = __half22float2(*(__half2*)&hv[u].w); a3.x += wu * v.x; a3.y += wu * v.y;
        }
    }
    for (; j < end; j++) {
        int s0 = __ldg(&g_src[j]);
        float w0 = __expf(lrelu(__ldg(&g_ls1[s0 * 4 + hh]) + ldv));
        uint4 hv0 = __ldg((const uint4*)(g_xl1h + (size_t)s0 * 256 + lane * 8));
        den += w0;
        float2 v;
        v = __half22float2(*(__half2*)&hv0.x); a0.x += w0 * v.x; a0.y += w0 * v.y;
        v = __half22float2(*(__half2*)&hv0.y); a1.x += w0 * v.x; a1.y += w0 * v.y;
        v = __half22float2(*(__half2*)&hv0.z); a2.x += w0 * v.x; a2.y += w0 * v.y;
        v = __half22float2(*(__half2*)&hv0.w); a3.x += w0 * v.x; a3.y += w0 * v.y;
    }
    float inv = 1.f / den;
    float4 bb0 = *(const float4*)(b1 + lane * 8);
    float4 bb1 = *(const float4*)(b1 + lane * 8 + 4);
    float o0 = fmaxf(a0.x * inv + bb0.x, 0.f);
    float o1 = fmaxf(a0.y * inv + bb0.y, 0.f);
    float o2 = fmaxf(a1.x * inv + bb0.z, 0.f);
    float o3 = fmaxf(a1.y * inv + bb0.w, 0.f);
    float o4 = fmaxf(a2.x * inv + bb1.x, 0.f);
    float o5 = fmaxf(a2.y * inv + bb1.y, 0.f);
    float o6 = fmaxf(a3.x * inv + bb1.z, 0.f);
    float o7 = fmaxf(a3.y * inv + bb1.w, 0.f);
    uint4 st;
    *(__half2*)&st.x = __floats2half2_rn(o0, o1);
    *(__half2*)&st.y = __floats2half2_rn(o2, o3);
    *(__half2*)&st.z = __floats2half2_rn(o4, o5);
    *(__half2*)&st.w = __floats2half2_rn(o6, o7);
    *(uint4*)(g_h1h + (size_t)dst * 256 + lane * 8) = st;
}

// ---------------- GEMM2 (fp16 mma) + fused logits2 --------------------------
__global__ __launch_bounds__(128) void k_gemm2(const float* __restrict__ W2,
                                               const float* __restrict__ as2,
                                               const float* __restrict__ ad2) {
    __shared__ __half As[64 * 136];   // [row][k-chunk 128], pad 136
    __shared__ __half Bs[32 * 266];   // [n][k 256], pad 266 (odd word stride)
    __shared__ __half Cs[64 * 40];    // [row][n 32], pad 40
    __shared__ float  sa[32], sd[32];
    int tid = threadIdx.x;
    int lane = tid & 31, w = tid >> 5;
    int n0 = blockIdx.x * 64;
    if (tid < 32) { sa[tid] = as2[tid]; sd[tid] = ad2[tid]; }
    // load W2 transposed -> Bs[n][k] fp16
#pragma unroll
    for (int i = 0; i < 64; i++) {
        int idx = tid + i * 128;          // 8192 elements
        int k = idx >> 5, n = idx & 31;
        Bs[n * 266 + k] = __float2half_rn(W2[idx]);
    }
    float c[4][4];
#pragma unroll
    for (int j = 0; j < 4; j++)
#pragma unroll
        for (int q = 0; q < 4; q++) c[j][q] = 0.f;
    int r4 = lane >> 2, c4 = lane & 3, m0 = w * 16;

    for (int ch = 0; ch < 2; ch++) {
        __syncthreads();
#pragma unroll
        for (int i = 0; i < 8; i++) {
            int q = tid + i * 128;             // 1024 uint4
            int row = q >> 4, cq = (q & 15) * 8;
            int gn = n0 + row;
            uint4 v = make_uint4(0,0,0,0);
            if (gn < NN) v = *(const uint4*)(g_h1h + (size_t)gn * 256 + ch * 128 + cq);
            *(uint4*)&As[row * 136 + cq] = v;
        }
        __syncthreads();
#pragma unroll
        for (int ks = 0; ks < 8; ks++) {
            int kb = ks * 16;
            unsigned a0 = *(unsigned*)&As[(m0 + r4) * 136 + kb + 2 * c4];
            unsigned a1 = *(unsigned*)&As[(m0 + r4 + 8) * 136 + kb + 2 * c4];
            unsigned a2 = *(unsigned*)&As[(m0 + r4) * 136 + kb + 2 * c4 + 8];
            unsigned a3 = *(unsigned*)&As[(m0 + r4 + 8) * 136 + kb + 2 * c4 + 8];
            int kg = ch * 128 + kb + 2 * c4;
#pragma unroll
            for (int j = 0; j < 4; j++) {
                int n = j * 8 + r4;
                unsigned b0 = *(unsigned*)&Bs[n * 266 + kg];
                unsigned b1 = *(unsigned*)&Bs[n * 266 + kg + 8];
                mma_f16(c[j][0], c[j][1], c[j][2], c[j][3], a0, a1, a2, a3, b0, b1);
            }
        }
    }
    __syncthreads();
#pragma unroll
    for (int j = 0; j < 4; j++) {
        int col = j * 8 + 2 * c4;
        *(__half2*)&Cs[(m0 + r4) * 40 + col]     = __floats2half2_rn(c[j][0], c[j][1]);
        *(__half2*)&Cs[(m0 + r4 + 8) * 40 + col] = __floats2half2_rn(c[j][2], c[j][3]);
    }
    __syncthreads();
    // write xl2h
#pragma unroll
    for (int i = 0; i < 2; i++) {
        int q = tid + i * 128;                 // 256 uint4
        int row = q >> 2, cq = (q & 3) * 8;
        int gn = n0 + row;
        if (gn < NN)
            *(uint4*)(g_xl2h + (size_t)gn * 32 + cq) = *(uint4*)&Cs[row * 40 + cq];
    }
    // logits2
    if (tid < 64) {
        int gn = n0 + tid;
        if (gn < NN) {
            float s = 0.f, d = 0.f;
#pragma unroll
            for (int cc = 0; cc < 32; cc++) {
                float v = __half2float(Cs[tid * 40 + cc]);
                s += v * sa[cc];
                d += v * sd[cc];
            }
            g_ls2[gn] = s;
            g_ld2[gn] = d;
        }
    }
}

// ------- aggregation layer2 (CSR; 2 dst per warp; half2 channels) ----------
__global__ __launch_bounds__(256) void k_agg2(const float* __restrict__ b2) {
    int wid = threadIdx.x >> 5, lane = threadIdx.x & 31;
    int half = lane >> 4, hl = lane & 15;
    int dst = blockIdx.x * 16 + wid * 2 + half;
    if (dst >= NN) return;
    int2 od = g_offdeg[dst];
    int beg = od.x, end = od.x + od.y;
    float ld2d = g_ld2[dst];
    int ch = hl * 2;
    float2 acc = make_float2(0.f, 0.f);
    float den = 0.f;
    int j = beg;
    for (; j + 2 <= end; j += 2) {
        int s0 = __ldg(&g_src[j]);
        int s1 = __ldg(&g_src[j + 1]);
        float w0 = __expf(lrelu(__ldg(&g_ls2[s0]) + ld2d));
        float w1 = __expf(lrelu(__ldg(&g_ls2[s1]) + ld2d));
        float2 v0 = __half22float2(__ldg((const __half2*)(g_xl2h + (size_t)s0 * 32 + ch)));
        float2 v1 = __half22float2(__ldg((const __half2*)(g_xl2h + (size_t)s1 * 32 + ch)));
        den += w0 + w1;
        acc.x += w0 * v0.x + w1 * v1.x;
        acc.y += w0 * v0.y + w1 * v1.y;
    }
    if (j < end) {
        int s0 = __ldg(&g_src[j]);
        float w0 = __expf(lrelu(__ldg(&g_ls2[s0]) + ld2d));
        float2 v0 = __half22float2(__ldg((const __half2*)(g_xl2h + (size_t)s0 * 32 + ch)));
        den += w0;
        acc.x += w0 * v0.x;
        acc.y += w0 * v0.y;
    }
    float inv = 1.f / den;
    float hx = fmaxf(acc.x * inv + b2[ch], 0.f);
    float hy = fmaxf(acc.y * inv + b2[ch + 1], 0.f);
    *(__half2*)(g_h2h + (size_t)dst * 32 + ch) = __floats2half2_rn(hx, hy);
}

// ---------------- final (fp16 mma): out = h2 @ fc_W + fc_b ------------------
__global__ __launch_bounds__(128) void k_final(const float* __restrict__ fcW,
                                               const float* __restrict__ fcb,
                                               float* __restrict__ out) {
    __shared__ __half As[64 * 40];    // [row][k 32], pad 40
    __shared__ __half Bs[128 * 40];   // [n][k 32], pad 40
    __shared__ float  sb[128];
    int tid = threadIdx.x;
    int lane = tid & 31, w = tid >> 5;
    int n0 = blockIdx.x * 64;
    sb[tid] = fcb[tid];
    // fcW [32][128] -> Bs[n][k] fp16
#pragma unroll
    for (int i = 0; i < 32; i++) {
        int idx = tid + i * 128;           // 4096 elements
        int k = idx >> 7, n = idx & 127;
        Bs[n * 40 + k] = __float2half_rn(fcW[idx]);
    }
    // h2h tile -> As
#pragma unroll
    for (int i = 0; i < 2; i++) {
        int q = tid + i * 128;             // 256 uint4
        int row = q >> 2, cq = (q & 3) * 8;
        int gn = n0 + row;
        uint4 v = make_uint4(0,0,0,0);
        if (gn < NN) v = *(const uint4*)(g_h2h + (size_t)gn * 32 + cq);
        *(uint4*)&As[row * 40 + cq] = v;
    }
    __syncthreads();

    float c[16][4];
#pragma unroll
    for (int j = 0; j < 16; j++)
#pragma unroll
        for (int q = 0; q < 4; q++) c[j][q] = 0.f;
    int r4 = lane >> 2, c4 = lane & 3, m0 = w * 16;

#pragma unroll
    for (int ks = 0; ks < 2; ks++) {
        int kb = ks * 16;
        unsigned a0 = *(unsigned*)&As[(m0 + r4) * 40 + kb + 2 * c4];
        unsigned a1 = *(unsigned*)&As[(m0 + r4 + 8) * 40 + kb + 2 * c4];
        unsigned a2 = *(unsigned*)&As[(m0 + r4) * 40 + kb + 2 * c4 + 8];
        unsigned a3 = *(unsigned*)&As[(m0 + r4 + 8) * 40 + kb + 2 * c4 + 8];
#pragma unroll
        for (int j = 0; j < 16; j++) {
            int n = j * 8 + r4;
            unsigned b0 = *(unsigned*)&Bs[n * 40 + kb + 2 * c4];
            unsigned b1 = *(unsigned*)&Bs[n * 40 + kb + 2 * c4 + 8];
            mma_f16(c[j][0], c[j][1], c[j][2], c[j][3], a0, a1, a2, a3, b0, b1);
        }
    }
    int row0 = n0 + m0 + r4, row1 = row0 + 8;
#pragma unroll
    for (int j = 0; j < 16; j++) {
        int col = j * 8 + 2 * c4;
        float bx = sb[col], by = sb[col + 1];
        if (row0 < NN) {
            float2 v0 = make_float2(c[j][0] + bx, c[j][1] + by);
            *(float2*)(out + (size_t)row0 * 128 + col) = v0;
        }
        if (row1 < NN) {
            float2 v1 = make_float2(c[j][2] + bx, c[j][3] + by);
            *(float2*)(out + (size_t)row1 * 128 + col) = v1;
        }
    }
}

// ---------------- launch ----------------
extern "C" void kernel_launch(void* const* d_in, const int* in_sizes, int n_in,
                              void* d_out, int out_size) {
    const float* x   = (const float*)d_in[0];
    const int*   ei  = (const int*)d_in[1];
    const float* W1  = (const float*)d_in[2];
    const float* as1 = (const float*)d_in[3];
    const float* ad1 = (const float*)d_in[4];
    const float* b1  = (const float*)d_in[5];
    const float* W2  = (const float*)d_in[6];
    const float* as2 = (const float*)d_in[7];
    const float* ad2 = (const float*)d_in[8];
    const float* b2  = (const float*)d_in[9];
    const float* fcW = (const float*)d_in[10];
    const float* fcb = (const float*)d_in[11];
    float* out = (float*)d_out;

    int g1 = (NN + 63) / 64;

    if (g_ss.ok) {
        // fork: CSR chain on side stream, concurrent with prep+gemm1 on main
        cudaEventRecord(g_ss.fork, 0);
        cudaStreamWaitEvent(g_ss.s, g_ss.fork, 0);
        k_hist<<<(EE / 4 + 255) / 256, 256, 0, g_ss.s>>>(ei);
        k_scan<<<NB, 256, 0, g_ss.s>>>();
        k_scatter<<<(ET / 4 + 255) / 256, 256, 0, g_ss.s>>>(ei);
        cudaEventRecord(g_ss.join, g_ss.s);

        k_prep<<<128, 256>>>(W1);
        k_gemm1<<<g1, 128>>>(x, as1, ad1);
        cudaStreamWaitEvent(0, g_ss.join, 0);
    } else {
        // serial fallback (identical work)
        k_hist<<<(EE / 4 + 255) / 256, 256>>>(ei);
        k_scan<<<NB, 256>>>();
        k_scatter<<<(ET / 4 + 255) / 256, 256>>>(ei);
        k_prep<<<128, 256>>>(W1);
        k_gemm1<<<g1, 128>>>(x, as1, ad1);
    }

    k_agg1<<<(NN + 7) / 8, 256>>>(b1);
    k_gemm2<<<(NN + 63) / 64, 128>>>(W2, as2, ad2);
    k_agg2<<<(NN + 15) / 16, 256>>>(b2);
    k_final<<<(NN + 63) / 64, 128>>>(fcW, fcb, out);
}